// round 1
// baseline (speedup 1.0000x reference)
#include <cuda_runtime.h>

// ----------------------------------------------------------------------------
// DeformableConvBlock: 4x conv3x3 (implicit GEMM) + bilinear sampling + GEMM
// All fp32. Shapes: B=1, H=W=64 (HW=4096), C=768.
//
// Pipeline:
//   h1  = relu(conv3x3(concat(x, ref)[1536], w1))   -> [192, 64, 64]
//   h2  = relu(conv3x3(h1, w2))                     -> [192, 64, 64]
//   est = conv3x3(h2, w3)                           -> [1536, 64, 64]
//   off = conv3x3(est, offset_w)                    -> [18, 64, 64]
//   S   = bilinear_sample(ref, off)                 -> [768*9, 4096]
//   out = deform_w[768][768*9] @ S                  -> [768, 64, 64]
// ----------------------------------------------------------------------------

#define HH 64
#define WW 64
#define HW 4096

// Scratch (device globals — no runtime allocation allowed)
__device__ float g_h1 [192  * HW];
__device__ float g_h2 [192  * HW];
__device__ float g_est[1536 * HW];
__device__ float g_off[18   * HW];
__device__ float g_S  [6912 * HW];   // 768*9 x 4096 sampled tensor (113 MB)

// ----------------------------------------------------------------------------
// Generic SGEMM / implicit-GEMM-conv kernel.
//   C[M][4096] = A[M][K] * B[K][4096]   (+ optional ReLU)
// MODE 0: B = im2col(X1), X1 has K/9 channels of [64][64], pad=1
// MODE 1: B = im2col(concat(X1, X2)), each 768 channels
// MODE 2: B = plain row-major matrix B1[K][4096]
// ----------------------------------------------------------------------------
template<int MODE, bool RELU>
__global__ __launch_bounds__(256)
void gemm_kernel(const float* __restrict__ A,
                 const float* __restrict__ B1,
                 const float* __restrict__ B2,
                 float* __restrict__ C,
                 int M, int Kdim)
{
    constexpr int BM = 64, BN = 64, BK = 16, TM = 4, TN = 4;
    __shared__ float As[BK][BM + 4];
    __shared__ float Bs[BK][BN + 4];

    const int tid = threadIdx.x;             // 0..255
    const int n0  = blockIdx.x * BN;
    const int m0  = blockIdx.y * BM;
    const int row = tid >> 4;                // 0..15
    const int col = tid & 15;                // 0..15

    float acc[TM][TN];
    #pragma unroll
    for (int i = 0; i < TM; i++)
        #pragma unroll
        for (int j = 0; j < TN; j++) acc[i][j] = 0.f;

    for (int k0 = 0; k0 < Kdim; k0 += BK) {
        // ---- load A tile: 64 x 16 ----
        #pragma unroll
        for (int i = 0; i < 4; i++) {
            int idx = tid + i * 256;
            int m = idx >> 4;                // 0..63
            int k = idx & 15;
            int gm = m0 + m;
            float v = 0.f;
            if (gm < M) v = A[(long long)gm * Kdim + (k0 + k)];
            As[k][m] = v;
        }
        // ---- load B tile: 16 x 64 ----
        #pragma unroll
        for (int i = 0; i < 4; i++) {
            int idx = tid + i * 256;
            int k = idx >> 6;                // 0..15
            int n = idx & 63;
            int gk = k0 + k;
            int gn = n0 + n;
            float v;
            if (MODE == 2) {
                v = B1[(long long)gk * HW + gn];
            } else {
                int c  = gk / 9;
                int t  = gk - c * 9;
                int ti = t / 3;
                int tj = t - ti * 3;
                int y  = gn >> 6;
                int x  = gn & 63;
                int py = y + ti - 1;
                int px = x + tj - 1;
                v = 0.f;
                if (py >= 0 && py < HH && px >= 0 && px < WW) {
                    const float* src;
                    if (MODE == 1) {
                        src = (c < 768) ? (B1 + (long long)c * HW)
                                        : (B2 + (long long)(c - 768) * HW);
                    } else {
                        src = B1 + (long long)c * HW;
                    }
                    v = src[py * WW + px];
                }
            }
            Bs[k][n] = v;
        }
        __syncthreads();

        // ---- inner product ----
        #pragma unroll
        for (int kk = 0; kk < BK; kk++) {
            float4 av = *reinterpret_cast<const float4*>(&As[kk][row * TM]);
            float4 bv = *reinterpret_cast<const float4*>(&Bs[kk][col * TN]);
            float a[TM] = {av.x, av.y, av.z, av.w};
            float b[TN] = {bv.x, bv.y, bv.z, bv.w};
            #pragma unroll
            for (int i = 0; i < TM; i++)
                #pragma unroll
                for (int j = 0; j < TN; j++)
                    acc[i][j] += a[i] * b[j];
        }
        __syncthreads();
    }

    // ---- store ----
    #pragma unroll
    for (int i = 0; i < TM; i++) {
        int gm = m0 + row * TM + i;
        if (gm >= M) continue;
        #pragma unroll
        for (int j = 0; j < TN; j++) {
            float v = acc[i][j];
            if (RELU) v = fmaxf(v, 0.f);
            C[(long long)gm * HW + n0 + col * TN + j] = v;
        }
    }
}

// ----------------------------------------------------------------------------
// Bilinear sampling (torchvision deform_conv2d semantics, zero padding).
// grid: (4096/256, 6912); block 256.  S[kk][p], kk = c*9 + tap
// offset layout: [18][64][64] with channel (tap*2 + {0:dy, 1:dx})
// ----------------------------------------------------------------------------
__device__ __forceinline__ float corner_val(const float* __restrict__ r,
                                            int yi, int xi, float w)
{
    bool valid = (yi >= 0) && (yi < HH) && (xi >= 0) && (xi < WW);
    int yc = min(max(yi, 0), HH - 1);
    int xc = min(max(xi, 0), WW - 1);
    return valid ? w * r[yc * WW + xc] : 0.f;
}

__global__ __launch_bounds__(256)
void sample_kernel(const float* __restrict__ ref,
                   const float* __restrict__ off,
                   float* __restrict__ S)
{
    int kk = blockIdx.y;                       // 0..6911
    int p  = blockIdx.x * blockDim.x + threadIdx.x;  // 0..4095
    int c  = kk / 9;
    int t  = kk - c * 9;
    int ti = t / 3;
    int tj = t - ti * 3;
    int y  = p >> 6;
    int x  = p & 63;

    float dy = off[(2 * t)     * HW + p];
    float dx = off[(2 * t + 1) * HW + p];
    float py = (float)(y - 1 + ti) + dy;
    float px = (float)(x - 1 + tj) + dx;

    float y0f = floorf(py), x0f = floorf(px);
    float wy1 = py - y0f,  wx1 = px - x0f;
    float wy0 = 1.f - wy1, wx0 = 1.f - wx1;
    int y0 = (int)y0f, x0 = (int)x0f;

    const float* r = ref + (long long)c * HW;
    float v = corner_val(r, y0,     x0,     wy0 * wx0)
            + corner_val(r, y0,     x0 + 1, wy0 * wx1)
            + corner_val(r, y0 + 1, x0,     wy1 * wx0)
            + corner_val(r, y0 + 1, x0 + 1, wy1 * wx1);

    S[(long long)kk * HW + p] = v;
}

// ----------------------------------------------------------------------------
extern "C" void kernel_launch(void* const* d_in, const int* in_sizes, int n_in,
                              void* d_out, int out_size)
{
    const float* x_in  = (const float*)d_in[0];   // input_features   [768,64,64]
    const float* x_ref = (const float*)d_in[1];   // reference_features
    const float* w1    = (const float*)d_in[2];   // [192,1536,3,3]
    const float* w2    = (const float*)d_in[3];   // [192,192,3,3]
    const float* w3    = (const float*)d_in[4];   // [1536,192,3,3]
    const float* wo    = (const float*)d_in[5];   // [18,1536,3,3]
    const float* wd    = (const float*)d_in[6];   // [768,768,3,3]
    float* out = (float*)d_out;                   // [768,64,64]

    float *h1, *h2, *est, *off, *S;
    cudaGetSymbolAddress((void**)&h1,  g_h1);
    cudaGetSymbolAddress((void**)&h2,  g_h2);
    cudaGetSymbolAddress((void**)&est, g_est);
    cudaGetSymbolAddress((void**)&off, g_off);
    cudaGetSymbolAddress((void**)&S,   g_S);

    // conv1: concat(x, ref)[1536] -> 192, relu
    gemm_kernel<1, true ><<<dim3(64, 3),  256>>>(w1, x_in, x_ref, h1, 192, 1536 * 9);
    // conv2: 192 -> 192, relu
    gemm_kernel<0, true ><<<dim3(64, 3),  256>>>(w2, h1, nullptr, h2, 192, 192 * 9);
    // conv3: 192 -> 1536
    gemm_kernel<0, false><<<dim3(64, 24), 256>>>(w3, h2, nullptr, est, 1536, 192 * 9);
    // conv4: 1536 -> 18 (offsets)
    gemm_kernel<0, false><<<dim3(64, 1),  256>>>(wo, est, nullptr, off, 18, 1536 * 9);
    // bilinear sampling: S[768*9][4096]
    sample_kernel<<<dim3(HW / 256, 6912), 256>>>(x_ref, off, S);
    // deform GEMM: out[768][4096] = wd[768][6912] @ S
    gemm_kernel<2, false><<<dim3(64, 12), 256>>>(wd, S, nullptr, out, 768, 768 * 9);
}

// round 5
// speedup vs baseline: 2.0775x; 2.0775x over previous
#include <cuda_runtime.h>
#include <cuda_bf16.h>

// ============================================================================
// DeformableConvBlock via mma.sync (m16n8k16 bf16) split-precision GEMMs.
// tcgen05 is unavailable (harness ptxas targets sm_103, not sm_103a), so we
// use baseline-PTX tensor-core ops: ldmatrix + mma.sync, valid on sm_80+.
//
// All stages are C[M][4096] = A[M][K] * B[K][4096]:
//   conv1: A=w1 [192][13824],  B=im2col(cat)        (ReLU)
//   conv2: A=w2 [192][1728],   B=im2col(h1)         (ReLU)
//   conv3: A=w3 [1536][1728],  B=im2col(h2)
//   conv4: A=wo [18][13824],   B=im2col(est)         (BM=32 layout)
//   deform:A=wd [768][6912],   B=S (bilinear, pre-split bf16 hi/lo, k-major)
// Precision: fp32 -> bf16 hi+lo; acc += Ah*Bh + Ah*Bl + Al*Bh  (f32 acc).
// ============================================================================

#define HW 4096

// ---------------- device scratch (no runtime allocation allowed) -----------
__device__ float g_cat[1536 * HW];
__device__ float g_h1 [192  * HW];
__device__ float g_h2 [192  * HW];
__device__ float g_est[1536 * HW];
__device__ float g_off[18   * HW];
__device__ __nv_bfloat16 g_shi[(size_t)6912 * HW];
__device__ __nv_bfloat16 g_slo[(size_t)6912 * HW];

// ---------------- smem layout (bytes) ---------------------------------------
// A tile: 128 rows x 40 bf16 (stride 80B -> conflict-free ldmatrix)
// B tile: 32 rows  x 136 bf16 (stride 272B -> conflict-free ldmatrix.trans)
#define A_STRIDE 40
#define B_STRIDE 136
#define ASZ (128 * A_STRIDE * 2)          // 10240
#define BSZ (32  * B_STRIDE * 2)          // 8704
#define OFF_AH(b) ((b) * ASZ)
#define OFF_AL(b) (2 * ASZ + (b) * ASZ)
#define OFF_BH(b) (4 * ASZ + (b) * BSZ)
#define OFF_BL(b) (4 * ASZ + 2 * BSZ + (b) * BSZ)
#define SMEM_BYTES (4 * ASZ + 4 * BSZ)    // 75776

// ---------------- PTX helpers ------------------------------------------------
__device__ __forceinline__ unsigned smem_to_u32(const void* p) {
    unsigned a;
    asm("{ .reg .u64 t; cvta.to.shared.u64 t, %1; cvt.u32.u64 %0, t; }"
        : "=r"(a) : "l"(p));
    return a;
}

__device__ __forceinline__ void ldsm_x4(unsigned* r, unsigned addr) {
    asm volatile("ldmatrix.sync.aligned.m8n8.x4.shared.b16 {%0,%1,%2,%3}, [%4];"
                 : "=r"(r[0]), "=r"(r[1]), "=r"(r[2]), "=r"(r[3]) : "r"(addr));
}
__device__ __forceinline__ void ldsm_x4_t(unsigned* r, unsigned addr) {
    asm volatile("ldmatrix.sync.aligned.m8n8.x4.trans.shared.b16 {%0,%1,%2,%3}, [%4];"
                 : "=r"(r[0]), "=r"(r[1]), "=r"(r[2]), "=r"(r[3]) : "r"(addr));
}
__device__ __forceinline__ void mma_bf16(float* c, const unsigned* a, const unsigned* b) {
    asm volatile(
        "mma.sync.aligned.m16n8k16.row.col.f32.bf16.bf16.f32 "
        "{%0,%1,%2,%3}, {%4,%5,%6,%7}, {%8,%9}, {%0,%1,%2,%3};"
        : "+f"(c[0]), "+f"(c[1]), "+f"(c[2]), "+f"(c[3])
        : "r"(a[0]), "r"(a[1]), "r"(a[2]), "r"(a[3]), "r"(b[0]), "r"(b[1]));
}

#define STS128A(addr, r0, r1, r2, r3) \
    asm volatile("st.shared.v4.b32 [%0], {%1, %2, %3, %4};" \
                 :: "r"((unsigned)(addr)), "r"(r0), "r"(r1), "r"(r2), "r"(r3) : "memory")
#define STS64A(addr, r0, r1) \
    asm volatile("st.shared.v2.b32 [%0], {%1, %2};" \
                 :: "r"((unsigned)(addr)), "r"(r0), "r"(r1) : "memory")

// split fp32 pair -> packed bf16x2 hi/lo
__device__ __forceinline__ void split2(float a, float b, unsigned& h, unsigned& l) {
    __nv_bfloat16 ha = __float2bfloat16(a);
    __nv_bfloat16 hb = __float2bfloat16(b);
    __nv_bfloat16 la = __float2bfloat16(a - __bfloat162float(ha));
    __nv_bfloat16 lb = __float2bfloat16(b - __bfloat162float(hb));
    __nv_bfloat162 hp = __halves2bfloat162(ha, hb);
    __nv_bfloat162 lp = __halves2bfloat162(la, lb);
    h = *reinterpret_cast<unsigned*>(&hp);
    l = *reinterpret_cast<unsigned*>(&lp);
}

// ============================================================================
// GEMM kernel. 256 threads (8 warps = WARP_M x WARP_N). BN=128, BK=32.
// MODE 0: B = im2col(srcF fp32, K/9 channels, pad=1)
// MODE 1: B = pre-split bf16 hi/lo matrices [K][4096] (k-major)
// grid (4096/128, ceil(M/BM)), dyn smem SMEM_BYTES.
// ============================================================================
template<int MODE, bool RELU, int WARP_M, int WARP_N, int BM>
__global__ __launch_bounds__(256, 1)
void gemm_mma(const float* __restrict__ A,
              const float* __restrict__ srcF,
              const __nv_bfloat16* __restrict__ bhi,
              const __nv_bfloat16* __restrict__ blo,
              float* __restrict__ C, int M, int K)
{
    constexpr int BN = 128, BK = 32;
    constexpr int MFRAG = BM / (WARP_M * 16);
    constexpr int NFRAG = BN / (WARP_N * 8);
    constexpr int A_ELEMS = BM / 8;   // staged floats per thread

    extern __shared__ char smem[];
    const unsigned sb = smem_to_u32(smem);
    const int tid  = threadIdx.x;
    const int wid  = tid >> 5;
    const int lane = tid & 31;
    const int n0 = blockIdx.x * BN;
    const int m0 = blockIdx.y * BM;

    // B-loader mapping: this thread fills tile row kloc, cols nbb..nbb+15
    const int kloc = tid >> 3;
    const int nbb  = (tid & 7) * 16;

    float a_st[A_ELEMS];
    float b_st[16];

    float acc[MFRAG][NFRAG][4];
    #pragma unroll
    for (int f = 0; f < MFRAG; f++)
        #pragma unroll
        for (int g = 0; g < NFRAG; g++)
            #pragma unroll
            for (int q = 0; q < 4; q++) acc[f][g][q] = 0.f;

    const int iters = K / BK;

    // -------------------- tile load (global -> regs) ------------------------
    auto LOAD = [&](int k0) {
        // ---- A ----
        if (BM == 128) {
            int m  = tid >> 1;
            int kh = (tid & 1) * 16;
            int gm = m0 + m;
            const float4* p =
                reinterpret_cast<const float4*>(A + (size_t)gm * K + k0 + kh);
            #pragma unroll
            for (int q = 0; q < 4; q++) {
                float4 v = (gm < M) ? p[q] : make_float4(0.f, 0.f, 0.f, 0.f);
                a_st[q * 4 + 0] = v.x; a_st[q * 4 + 1] = v.y;
                a_st[q * 4 + 2] = v.z; a_st[q * 4 + 3] = v.w;
            }
        } else {  // BM == 32
            int m  = tid >> 3;
            int kq = (tid & 7) * 4;
            int gm = m0 + m;
            float4 v = (gm < M)
                ? *reinterpret_cast<const float4*>(A + (size_t)gm * K + k0 + kq)
                : make_float4(0.f, 0.f, 0.f, 0.f);
            a_st[0] = v.x; a_st[1] = v.y; a_st[2] = v.z; a_st[3] = v.w;
        }
        // ---- B ----
        if (MODE == 0) {
            int gk = k0 + kloc;
            int c  = gk / 9;
            int tap = gk - c * 9;
            int ti = tap / 3;
            int tj = tap - ti * 3;
            int n  = n0 + nbb;
            int y  = n >> 6;
            int xb = n & 63;
            int py = y + ti - 1;
            bool yok = (unsigned)py < 64u;
            const float* src = srcF + (size_t)c * HW + py * 64 + (xb + tj - 1);
            #pragma unroll
            for (int j = 0; j < 16; j++) {
                int px = xb + tj - 1 + j;
                b_st[j] = (yok && (unsigned)px < 64u) ? __ldg(src + j) : 0.f;
            }
        } else {
            size_t gix = (size_t)(k0 + kloc) * HW + n0 + nbb;
            uint4 h0 = *reinterpret_cast<const uint4*>(bhi + gix);
            uint4 h1 = *reinterpret_cast<const uint4*>(bhi + gix + 8);
            uint4 l0 = *reinterpret_cast<const uint4*>(blo + gix);
            uint4 l1 = *reinterpret_cast<const uint4*>(blo + gix + 8);
            b_st[0]  = __uint_as_float(h0.x); b_st[1]  = __uint_as_float(h0.y);
            b_st[2]  = __uint_as_float(h0.z); b_st[3]  = __uint_as_float(h0.w);
            b_st[4]  = __uint_as_float(h1.x); b_st[5]  = __uint_as_float(h1.y);
            b_st[6]  = __uint_as_float(h1.z); b_st[7]  = __uint_as_float(h1.w);
            b_st[8]  = __uint_as_float(l0.x); b_st[9]  = __uint_as_float(l0.y);
            b_st[10] = __uint_as_float(l0.z); b_st[11] = __uint_as_float(l0.w);
            b_st[12] = __uint_as_float(l1.x); b_st[13] = __uint_as_float(l1.y);
            b_st[14] = __uint_as_float(l1.z); b_st[15] = __uint_as_float(l1.w);
        }
    };

    // -------------------- tile store (regs -> smem, with bf16 split) --------
    auto STORE = [&](int buf) {
        // ---- A ----
        if (BM == 128) {
            int m  = tid >> 1;
            int kh = (tid & 1) * 16;
            unsigned h[8], l[8];
            #pragma unroll
            for (int q = 0; q < 8; q++)
                split2(a_st[2 * q], a_st[2 * q + 1], h[q], l[q]);
            unsigned base = (unsigned)(m * A_STRIDE + kh) * 2;
            STS128A(sb + OFF_AH(buf) + base,      h[0], h[1], h[2], h[3]);
            STS128A(sb + OFF_AH(buf) + base + 16, h[4], h[5], h[6], h[7]);
            STS128A(sb + OFF_AL(buf) + base,      l[0], l[1], l[2], l[3]);
            STS128A(sb + OFF_AL(buf) + base + 16, l[4], l[5], l[6], l[7]);
        } else {
            int m  = tid >> 3;
            int kq = (tid & 7) * 4;
            unsigned h[2], l[2];
            split2(a_st[0], a_st[1], h[0], l[0]);
            split2(a_st[2], a_st[3], h[1], l[1]);
            unsigned base = (unsigned)(m * A_STRIDE + kq) * 2;
            STS64A(sb + OFF_AH(buf) + base, h[0], h[1]);
            STS64A(sb + OFF_AL(buf) + base, l[0], l[1]);
        }
        // ---- B ----
        unsigned base = (unsigned)(kloc * B_STRIDE + nbb) * 2;
        if (MODE == 0) {
            unsigned h[8], l[8];
            #pragma unroll
            for (int q = 0; q < 8; q++)
                split2(b_st[2 * q], b_st[2 * q + 1], h[q], l[q]);
            STS128A(sb + OFF_BH(buf) + base,      h[0], h[1], h[2], h[3]);
            STS128A(sb + OFF_BH(buf) + base + 16, h[4], h[5], h[6], h[7]);
            STS128A(sb + OFF_BL(buf) + base,      l[0], l[1], l[2], l[3]);
            STS128A(sb + OFF_BL(buf) + base + 16, l[4], l[5], l[6], l[7]);
        } else {
            STS128A(sb + OFF_BH(buf) + base,
                    __float_as_uint(b_st[0]), __float_as_uint(b_st[1]),
                    __float_as_uint(b_st[2]), __float_as_uint(b_st[3]));
            STS128A(sb + OFF_BH(buf) + base + 16,
                    __float_as_uint(b_st[4]), __float_as_uint(b_st[5]),
                    __float_as_uint(b_st[6]), __float_as_uint(b_st[7]));
            STS128A(sb + OFF_BL(buf) + base,
                    __float_as_uint(b_st[8]), __float_as_uint(b_st[9]),
                    __float_as_uint(b_st[10]), __float_as_uint(b_st[11]));
            STS128A(sb + OFF_BL(buf) + base + 16,
                    __float_as_uint(b_st[12]), __float_as_uint(b_st[13]),
                    __float_as_uint(b_st[14]), __float_as_uint(b_st[15]));
        }
    };

    // -------------------- compute (smem -> mma) -----------------------------
    const int wm = wid % WARP_M;
    const int wn = wid / WARP_M;
    const int mb  = wm * MFRAG * 16;
    const int nbw = wn * NFRAG * 8;

    auto COMPUTE = [&](int buf) {
        const unsigned ah_base = sb + OFF_AH(buf);
        const unsigned al_base = sb + OFF_AL(buf);
        const unsigned bh_base = sb + OFF_BH(buf);
        const unsigned bl_base = sb + OFF_BL(buf);
        #pragma unroll
        for (int ks = 0; ks < BK; ks += 16) {
            unsigned ah[MFRAG][4], al[MFRAG][4];
            {
                int arow = mb + (lane & 15);
                int acol = ks + (lane >> 4) * 8;
                #pragma unroll
                for (int f = 0; f < MFRAG; f++) {
                    unsigned off = (unsigned)((arow + f * 16) * A_STRIDE + acol) * 2;
                    ldsm_x4(ah[f], ah_base + off);
                    ldsm_x4(al[f], al_base + off);
                }
            }
            #pragma unroll
            for (int g = 0; g < NFRAG / 2; g++) {
                unsigned bh[4], bl[4];
                int brow = ks + (lane & 15);
                int bcol = nbw + g * 16 + (lane >> 4) * 8;
                unsigned off = (unsigned)(brow * B_STRIDE + bcol) * 2;
                ldsm_x4_t(bh, bh_base + off);
                ldsm_x4_t(bl, bl_base + off);
                #pragma unroll
                for (int f = 0; f < MFRAG; f++) {
                    #pragma unroll
                    for (int h2 = 0; h2 < 2; h2++) {
                        float* c = acc[f][g * 2 + h2];
                        mma_bf16(c, ah[f], bh + h2 * 2);
                        mma_bf16(c, ah[f], bl + h2 * 2);
                        mma_bf16(c, al[f], bh + h2 * 2);
                    }
                }
            }
        }
    };

    // -------------------- main pipeline -------------------------------------
    LOAD(0);
    STORE(0);
    __syncthreads();
    for (int i = 0; i < iters; i++) {
        if (i + 1 < iters) LOAD((i + 1) * BK);
        COMPUTE(i & 1);
        if (i + 1 < iters) {
            STORE((i + 1) & 1);
            __syncthreads();
        }
    }

    // -------------------- epilogue ------------------------------------------
    #pragma unroll
    for (int f = 0; f < MFRAG; f++) {
        #pragma unroll
        for (int j = 0; j < NFRAG; j++) {
            int r0  = m0 + mb + f * 16 + (lane >> 2);
            int col = n0 + nbw + j * 8 + (lane & 3) * 2;
            float2 v0 = make_float2(acc[f][j][0], acc[f][j][1]);
            float2 v1 = make_float2(acc[f][j][2], acc[f][j][3]);
            if (RELU) {
                v0.x = fmaxf(v0.x, 0.f); v0.y = fmaxf(v0.y, 0.f);
                v1.x = fmaxf(v1.x, 0.f); v1.y = fmaxf(v1.y, 0.f);
            }
            if (r0 < M)
                *reinterpret_cast<float2*>(C + (size_t)r0 * HW + col) = v0;
            if (r0 + 8 < M)
                *reinterpret_cast<float2*>(C + (size_t)(r0 + 8) * HW + col) = v1;
        }
    }
}

// ============================================================================
// Bilinear sampling -> k-major pre-split bf16 S: shi/slo [6912][4096]
// grid (16, 6912), block 256. k = by, n = bx*256 + tid.
// ============================================================================
__global__ __launch_bounds__(256)
void sample_kernel(const float* __restrict__ ref,
                   const float* __restrict__ off,
                   __nv_bfloat16* __restrict__ shi,
                   __nv_bfloat16* __restrict__ slo)
{
    int k = blockIdx.y;                              // 0..6911
    int n = blockIdx.x * 256 + threadIdx.x;          // 0..4095
    int c = k / 9;
    int t = k - c * 9;
    int ti = t / 3;
    int tj = t - ti * 3;
    int y = n >> 6, x = n & 63;

    float dy = off[(2 * t)     * HW + n];
    float dx = off[(2 * t + 1) * HW + n];
    float py = (float)(y - 1 + ti) + dy;
    float px = (float)(x - 1 + tj) + dx;

    float y0f = floorf(py), x0f = floorf(px);
    float wy1 = py - y0f,  wx1 = px - x0f;
    float wy0 = 1.f - wy1, wx0 = 1.f - wx1;
    int y0 = (int)y0f, x0 = (int)x0f;

    const float* r = ref + (size_t)c * HW;
    float v = 0.f;
    if (((unsigned)y0 < 64u) && ((unsigned)x0 < 64u))
        v += wy0 * wx0 * r[y0 * 64 + x0];
    if (((unsigned)y0 < 64u) && ((unsigned)(x0 + 1) < 64u))
        v += wy0 * wx1 * r[y0 * 64 + x0 + 1];
    if (((unsigned)(y0 + 1) < 64u) && ((unsigned)x0 < 64u))
        v += wy1 * wx0 * r[(y0 + 1) * 64 + x0];
    if (((unsigned)(y0 + 1) < 64u) && ((unsigned)(x0 + 1) < 64u))
        v += wy1 * wx1 * r[(y0 + 1) * 64 + x0 + 1];

    size_t oidx = (size_t)k * HW + n;
    __nv_bfloat16 h = __float2bfloat16(v);
    shi[oidx] = h;
    slo[oidx] = __float2bfloat16(v - __bfloat162float(h));
}

// ============================================================================
extern "C" void kernel_launch(void* const* d_in, const int* in_sizes, int n_in,
                              void* d_out, int out_size)
{
    const float* x_in  = (const float*)d_in[0];
    const float* x_ref = (const float*)d_in[1];
    const float* w1    = (const float*)d_in[2];
    const float* w2    = (const float*)d_in[3];
    const float* w3    = (const float*)d_in[4];
    const float* wo    = (const float*)d_in[5];
    const float* wd    = (const float*)d_in[6];
    float* out = (float*)d_out;

    float *cat, *h1, *h2, *est, *off;
    __nv_bfloat16 *shi, *slo;
    cudaGetSymbolAddress((void**)&cat, g_cat);
    cudaGetSymbolAddress((void**)&h1,  g_h1);
    cudaGetSymbolAddress((void**)&h2,  g_h2);
    cudaGetSymbolAddress((void**)&est, g_est);
    cudaGetSymbolAddress((void**)&off, g_off);
    cudaGetSymbolAddress((void**)&shi, g_shi);
    cudaGetSymbolAddress((void**)&slo, g_slo);

    cudaFuncSetAttribute(gemm_mma<0, true,  4, 2, 128>,
                         cudaFuncAttributeMaxDynamicSharedMemorySize, SMEM_BYTES);
    cudaFuncSetAttribute(gemm_mma<0, false, 4, 2, 128>,
                         cudaFuncAttributeMaxDynamicSharedMemorySize, SMEM_BYTES);
    cudaFuncSetAttribute(gemm_mma<0, false, 1, 8, 32>,
                         cudaFuncAttributeMaxDynamicSharedMemorySize, SMEM_BYTES);
    cudaFuncSetAttribute(gemm_mma<1, false, 4, 2, 128>,
                         cudaFuncAttributeMaxDynamicSharedMemorySize, SMEM_BYTES);

    // concat(x, ref) -> g_cat
    cudaMemcpyAsync(cat,            x_in,  (size_t)768 * HW * 4, cudaMemcpyDeviceToDevice);
    cudaMemcpyAsync(cat + 768 * HW, x_ref, (size_t)768 * HW * 4, cudaMemcpyDeviceToDevice);

    // conv1: 1536 -> 192, relu
    gemm_mma<0, true,  4, 2, 128><<<dim3(32, 2),  256, SMEM_BYTES>>>(
        w1, cat, nullptr, nullptr, h1, 192, 13824);
    // conv2: 192 -> 192, relu
    gemm_mma<0, true,  4, 2, 128><<<dim3(32, 2),  256, SMEM_BYTES>>>(
        w2, h1, nullptr, nullptr, h2, 192, 1728);
    // conv3: 192 -> 1536
    gemm_mma<0, false, 4, 2, 128><<<dim3(32, 12), 256, SMEM_BYTES>>>(
        w3, h2, nullptr, nullptr, est, 1536, 1728);
    // conv4: 1536 -> 18 (offsets), small-M layout
    gemm_mma<0, false, 1, 8, 32><<<dim3(32, 1),   256, SMEM_BYTES>>>(
        wo, est, nullptr, nullptr, off, 18, 13824);
    // bilinear sampling -> k-major bf16 hi/lo S
    sample_kernel<<<dim3(16, 6912), 256>>>(x_ref, off, shi, slo);
    // deform GEMM: out[768][4096] = wd[768][6912] @ S
    gemm_mma<1, false, 4, 2, 128><<<dim3(32, 6),  256, SMEM_BYTES>>>(
        wd, nullptr, shi, slo, out, 768, 6912);
}

// round 6
// speedup vs baseline: 2.8283x; 1.3614x over previous
#include <cuda_runtime.h>
#include <cuda_bf16.h>

// ============================================================================
// DeformableConvBlock via mma.sync (m16n8k16 bf16) split-precision GEMMs.
// (tcgen05 unavailable: harness ptxas targets sm_103, not sm_103a.)
//
// Stages (C[M][4096] = A[M][K] * B[K][4096]):
//   conv1: A=w1 [192][13824],  B=im2col(cat)   ReLU   BM=64, grid(32,3), 2 CTA/SM
//   conv2: A=w2 [192][1728],   B=im2col(h1)    ReLU   BM=64, grid(32,3)
//   conv3: A=w3 [1536][1728],  B=im2col(h2)           BM=64, grid(32,24)
//   conv4: A=wo [18][13824],   B=im2col(est)          BM=32, SPLIT-K x8, atomics
//   deform:A=wd [768][6912],   B=S bf16 hi/lo k-major BM=64, grid(32,12)
// Precision: fp32 -> bf16 hi+lo; acc += Ah*Bh + Ah*Bl + Al*Bh  (f32 acc).
// ============================================================================

#define HW 4096

// ---------------- device scratch --------------------------------------------
__device__ float g_cat[1536 * HW];
__device__ float g_h1 [192  * HW];
__device__ float g_h2 [192  * HW];
__device__ float g_est[1536 * HW];
__device__ float g_off[18   * HW];
__device__ __nv_bfloat16 g_shi[(size_t)6912 * HW];
__device__ __nv_bfloat16 g_slo[(size_t)6912 * HW];

// ---------------- smem geometry ---------------------------------------------
#define A_STRIDE 40     // bf16 elems per A row (32 data + 8 pad)
#define B_STRIDE 136    // bf16 elems per B row (128 data + 8 pad)

// ---------------- PTX helpers ------------------------------------------------
__device__ __forceinline__ unsigned smem_to_u32(const void* p) {
    unsigned a;
    asm("{ .reg .u64 t; cvta.to.shared.u64 t, %1; cvt.u32.u64 %0, t; }"
        : "=r"(a) : "l"(p));
    return a;
}
__device__ __forceinline__ void ldsm_x4(unsigned* r, unsigned addr) {
    asm volatile("ldmatrix.sync.aligned.m8n8.x4.shared.b16 {%0,%1,%2,%3}, [%4];"
                 : "=r"(r[0]), "=r"(r[1]), "=r"(r[2]), "=r"(r[3]) : "r"(addr));
}
__device__ __forceinline__ void ldsm_x4_t(unsigned* r, unsigned addr) {
    asm volatile("ldmatrix.sync.aligned.m8n8.x4.trans.shared.b16 {%0,%1,%2,%3}, [%4];"
                 : "=r"(r[0]), "=r"(r[1]), "=r"(r[2]), "=r"(r[3]) : "r"(addr));
}
__device__ __forceinline__ void mma_bf16(float* c, const unsigned* a, const unsigned* b) {
    asm volatile(
        "mma.sync.aligned.m16n8k16.row.col.f32.bf16.bf16.f32 "
        "{%0,%1,%2,%3}, {%4,%5,%6,%7}, {%8,%9}, {%0,%1,%2,%3};"
        : "+f"(c[0]), "+f"(c[1]), "+f"(c[2]), "+f"(c[3])
        : "r"(a[0]), "r"(a[1]), "r"(a[2]), "r"(a[3]), "r"(b[0]), "r"(b[1]));
}
#define STS128A(addr, r0, r1, r2, r3) \
    asm volatile("st.shared.v4.b32 [%0], {%1, %2, %3, %4};" \
                 :: "r"((unsigned)(addr)), "r"(r0), "r"(r1), "r"(r2), "r"(r3) : "memory")
#define STS64A(addr, r0, r1) \
    asm volatile("st.shared.v2.b32 [%0], {%1, %2};" \
                 :: "r"((unsigned)(addr)), "r"(r0), "r"(r1) : "memory")

__device__ __forceinline__ void split2(float a, float b, unsigned& h, unsigned& l) {
    __nv_bfloat16 ha = __float2bfloat16(a);
    __nv_bfloat16 hb = __float2bfloat16(b);
    __nv_bfloat16 la = __float2bfloat16(a - __bfloat162float(ha));
    __nv_bfloat16 lb = __float2bfloat16(b - __bfloat162float(hb));
    __nv_bfloat162 hp = __halves2bfloat162(ha, hb);
    __nv_bfloat162 lp = __halves2bfloat162(la, lb);
    h = *reinterpret_cast<unsigned*>(&hp);
    l = *reinterpret_cast<unsigned*>(&lp);
}

// ============================================================================
// GEMM kernel. 256 threads (8 warps = WARP_M x WARP_N). BN=128, BK=32.
// MODE 0: B = im2col(srcF fp32, pad=1).  MODE 1: B = bf16 hi/lo [K][4096].
// SPLITK: blockIdx.y = K-split index (m0=0), epilogue atomicAdd.
//         else blockIdx.y = m-tile, epilogue store.
// ============================================================================
template<int MODE, bool RELU, int WARP_M, int WARP_N, int BM, int MINB, bool SPLITK>
__global__ __launch_bounds__(256, MINB)
void gemm_mma(const float* __restrict__ A,
              const float* __restrict__ srcF,
              const __nv_bfloat16* __restrict__ bhi,
              const __nv_bfloat16* __restrict__ blo,
              float* __restrict__ C, int M, int Kfull, int kcnt)
{
    constexpr int BN = 128, BK = 32;
    constexpr int MFRAG = BM / (WARP_M * 16);
    constexpr int NFRAG = BN / (WARP_N * 8);
    constexpr int A_ELEMS = (BM == 128) ? 16 : (BM == 64 ? 8 : 4);
    constexpr int ASZ = BM * A_STRIDE * 2;
    constexpr int BSZ = 32 * B_STRIDE * 2;
    // smem offsets
    auto OFF_AH = [](int b) { return b * ASZ; };
    auto OFF_AL = [](int b) { return 2 * ASZ + b * ASZ; };
    auto OFF_BH = [](int b) { return 4 * ASZ + b * BSZ; };
    auto OFF_BL = [](int b) { return 4 * ASZ + 2 * BSZ + b * BSZ; };

    extern __shared__ char smem[];
    const unsigned sb = smem_to_u32(smem);
    const int tid  = threadIdx.x;
    const int wid  = tid >> 5;
    const int lane = tid & 31;
    const int n0 = blockIdx.x * BN;
    const int m0 = SPLITK ? 0 : blockIdx.y * BM;
    const int kb = SPLITK ? blockIdx.y * kcnt : 0;

    const int kloc = tid >> 3;          // B-loader row within tile
    const int nbb  = (tid & 7) * 16;    // B-loader col base

    float a_st[A_ELEMS];
    float b_st[16];

    float acc[MFRAG][NFRAG][4];
    #pragma unroll
    for (int f = 0; f < MFRAG; f++)
        #pragma unroll
        for (int g = 0; g < NFRAG; g++)
            #pragma unroll
            for (int q = 0; q < 4; q++) acc[f][g][q] = 0.f;

    const int iters = kcnt / BK;

    // -------------------- tile load (global -> regs); k0g is global K pos ---
    auto LOAD = [&](int k0g) {
        // ---- A ----
        if constexpr (BM == 128) {
            int m  = tid >> 1;
            int kh = (tid & 1) * 16;
            int gm = m0 + m;
            const float4* p =
                reinterpret_cast<const float4*>(A + (size_t)gm * Kfull + k0g + kh);
            #pragma unroll
            for (int q = 0; q < 4; q++) {
                float4 v = (gm < M) ? p[q] : make_float4(0.f, 0.f, 0.f, 0.f);
                a_st[q * 4 + 0] = v.x; a_st[q * 4 + 1] = v.y;
                a_st[q * 4 + 2] = v.z; a_st[q * 4 + 3] = v.w;
            }
        } else if constexpr (BM == 64) {
            int m  = tid >> 2;
            int kh = (tid & 3) * 8;
            int gm = m0 + m;
            const float4* p =
                reinterpret_cast<const float4*>(A + (size_t)gm * Kfull + k0g + kh);
            #pragma unroll
            for (int q = 0; q < 2; q++) {
                float4 v = (gm < M) ? p[q] : make_float4(0.f, 0.f, 0.f, 0.f);
                a_st[q * 4 + 0] = v.x; a_st[q * 4 + 1] = v.y;
                a_st[q * 4 + 2] = v.z; a_st[q * 4 + 3] = v.w;
            }
        } else {  // BM == 32
            int m  = tid >> 3;
            int kq = (tid & 7) * 4;
            int gm = m0 + m;
            float4 v = (gm < M)
                ? *reinterpret_cast<const float4*>(A + (size_t)gm * Kfull + k0g + kq)
                : make_float4(0.f, 0.f, 0.f, 0.f);
            a_st[0] = v.x; a_st[1] = v.y; a_st[2] = v.z; a_st[3] = v.w;
        }
        // ---- B ----
        if (MODE == 0) {
            int gk = k0g + kloc;
            int c  = gk / 9;
            int tap = gk - c * 9;
            int ti = tap / 3;
            int tj = tap - ti * 3;
            int n  = n0 + nbb;
            int y  = n >> 6;
            int xb = n & 63;
            int py = y + ti - 1;
            bool yok = (unsigned)py < 64u;
            const float* src = srcF + (size_t)c * HW + py * 64 + (xb + tj - 1);
            #pragma unroll
            for (int j = 0; j < 16; j++) {
                int px = xb + tj - 1 + j;
                b_st[j] = (yok && (unsigned)px < 64u) ? __ldg(src + j) : 0.f;
            }
        } else {
            size_t gix = (size_t)(k0g + kloc) * HW + n0 + nbb;
            uint4 h0 = *reinterpret_cast<const uint4*>(bhi + gix);
            uint4 h1 = *reinterpret_cast<const uint4*>(bhi + gix + 8);
            uint4 l0 = *reinterpret_cast<const uint4*>(blo + gix);
            uint4 l1 = *reinterpret_cast<const uint4*>(blo + gix + 8);
            b_st[0]  = __uint_as_float(h0.x); b_st[1]  = __uint_as_float(h0.y);
            b_st[2]  = __uint_as_float(h0.z); b_st[3]  = __uint_as_float(h0.w);
            b_st[4]  = __uint_as_float(h1.x); b_st[5]  = __uint_as_float(h1.y);
            b_st[6]  = __uint_as_float(h1.z); b_st[7]  = __uint_as_float(h1.w);
            b_st[8]  = __uint_as_float(l0.x); b_st[9]  = __uint_as_float(l0.y);
            b_st[10] = __uint_as_float(l0.z); b_st[11] = __uint_as_float(l0.w);
            b_st[12] = __uint_as_float(l1.x); b_st[13] = __uint_as_float(l1.y);
            b_st[14] = __uint_as_float(l1.z); b_st[15] = __uint_as_float(l1.w);
        }
    };

    // -------------------- tile store (regs -> smem, bf16 split) -------------
    auto STORE = [&](int buf) {
        // ---- A ----
        if constexpr (BM == 128) {
            int m  = tid >> 1;
            int kh = (tid & 1) * 16;
            unsigned h[8], l[8];
            #pragma unroll
            for (int q = 0; q < 8; q++)
                split2(a_st[2 * q], a_st[2 * q + 1], h[q], l[q]);
            unsigned base = (unsigned)(m * A_STRIDE + kh) * 2;
            STS128A(sb + OFF_AH(buf) + base,      h[0], h[1], h[2], h[3]);
            STS128A(sb + OFF_AH(buf) + base + 16, h[4], h[5], h[6], h[7]);
            STS128A(sb + OFF_AL(buf) + base,      l[0], l[1], l[2], l[3]);
            STS128A(sb + OFF_AL(buf) + base + 16, l[4], l[5], l[6], l[7]);
        } else if constexpr (BM == 64) {
            int m  = tid >> 2;
            int kh = (tid & 3) * 8;
            unsigned h[4], l[4];
            #pragma unroll
            for (int q = 0; q < 4; q++)
                split2(a_st[2 * q], a_st[2 * q + 1], h[q], l[q]);
            unsigned base = (unsigned)(m * A_STRIDE + kh) * 2;
            STS128A(sb + OFF_AH(buf) + base, h[0], h[1], h[2], h[3]);
            STS128A(sb + OFF_AL(buf) + base, l[0], l[1], l[2], l[3]);
        } else {
            int m  = tid >> 3;
            int kq = (tid & 7) * 4;
            unsigned h[2], l[2];
            split2(a_st[0], a_st[1], h[0], l[0]);
            split2(a_st[2], a_st[3], h[1], l[1]);
            unsigned base = (unsigned)(m * A_STRIDE + kq) * 2;
            STS64A(sb + OFF_AH(buf) + base, h[0], h[1]);
            STS64A(sb + OFF_AL(buf) + base, l[0], l[1]);
        }
        // ---- B ----
        unsigned base = (unsigned)(kloc * B_STRIDE + nbb) * 2;
        if (MODE == 0) {
            unsigned h[8], l[8];
            #pragma unroll
            for (int q = 0; q < 8; q++)
                split2(b_st[2 * q], b_st[2 * q + 1], h[q], l[q]);
            STS128A(sb + OFF_BH(buf) + base,      h[0], h[1], h[2], h[3]);
            STS128A(sb + OFF_BH(buf) + base + 16, h[4], h[5], h[6], h[7]);
            STS128A(sb + OFF_BL(buf) + base,      l[0], l[1], l[2], l[3]);
            STS128A(sb + OFF_BL(buf) + base + 16, l[4], l[5], l[6], l[7]);
        } else {
            STS128A(sb + OFF_BH(buf) + base,
                    __float_as_uint(b_st[0]), __float_as_uint(b_st[1]),
                    __float_as_uint(b_st[2]), __float_as_uint(b_st[3]));
            STS128A(sb + OFF_BH(buf) + base + 16,
                    __float_as_uint(b_st[4]), __float_as_uint(b_st[5]),
                    __float_as_uint(b_st[6]), __float_as_uint(b_st[7]));
            STS128A(sb + OFF_BL(buf) + base,
                    __float_as_uint(b_st[8]), __float_as_uint(b_st[9]),
                    __float_as_uint(b_st[10]), __float_as_uint(b_st[11]));
            STS128A(sb + OFF_BL(buf) + base + 16,
                    __float_as_uint(b_st[12]), __float_as_uint(b_st[13]),
                    __float_as_uint(b_st[14]), __float_as_uint(b_st[15]));
        }
    };

    // -------------------- compute -------------------------------------------
    const int wm  = wid % WARP_M;
    const int wn  = wid / WARP_M;
    const int mb  = wm * MFRAG * 16;
    const int nbw = wn * NFRAG * 8;

    auto COMPUTE = [&](int buf) {
        const unsigned ah_base = sb + OFF_AH(buf);
        const unsigned al_base = sb + OFF_AL(buf);
        const unsigned bh_base = sb + OFF_BH(buf);
        const unsigned bl_base = sb + OFF_BL(buf);
        #pragma unroll
        for (int ks = 0; ks < BK; ks += 16) {
            unsigned ah[MFRAG][4], al[MFRAG][4];
            {
                int arow = mb + (lane & 15);
                int acol = ks + (lane >> 4) * 8;
                #pragma unroll
                for (int f = 0; f < MFRAG; f++) {
                    unsigned off = (unsigned)((arow + f * 16) * A_STRIDE + acol) * 2;
                    ldsm_x4(ah[f], ah_base + off);
                    ldsm_x4(al[f], al_base + off);
                }
            }
            #pragma unroll
            for (int g = 0; g < NFRAG / 2; g++) {
                unsigned bh[4], bl[4];
                int brow = ks + (lane & 15);
                int bcol = nbw + g * 16 + (lane >> 4) * 8;
                unsigned off = (unsigned)(brow * B_STRIDE + bcol) * 2;
                ldsm_x4_t(bh, bh_base + off);
                ldsm_x4_t(bl, bl_base + off);
                #pragma unroll
                for (int f = 0; f < MFRAG; f++) {
                    #pragma unroll
                    for (int h2 = 0; h2 < 2; h2++) {
                        float* c = acc[f][g * 2 + h2];
                        mma_bf16(c, ah[f], bh + h2 * 2);
                        mma_bf16(c, ah[f], bl + h2 * 2);
                        mma_bf16(c, al[f], bh + h2 * 2);
                    }
                }
            }
        }
    };

    // -------------------- main pipeline -------------------------------------
    LOAD(kb);
    STORE(0);
    __syncthreads();
    for (int i = 0; i < iters; i++) {
        if (i + 1 < iters) LOAD(kb + (i + 1) * BK);
        COMPUTE(i & 1);
        if (i + 1 < iters) {
            STORE((i + 1) & 1);
            __syncthreads();
        }
    }

    // -------------------- epilogue ------------------------------------------
    #pragma unroll
    for (int f = 0; f < MFRAG; f++) {
        #pragma unroll
        for (int j = 0; j < NFRAG; j++) {
            int r0  = m0 + mb + f * 16 + (lane >> 2);
            int col = n0 + nbw + j * 8 + (lane & 3) * 2;
            float2 v0 = make_float2(acc[f][j][0], acc[f][j][1]);
            float2 v1 = make_float2(acc[f][j][2], acc[f][j][3]);
            if (RELU) {
                v0.x = fmaxf(v0.x, 0.f); v0.y = fmaxf(v0.y, 0.f);
                v1.x = fmaxf(v1.x, 0.f); v1.y = fmaxf(v1.y, 0.f);
            }
            if (SPLITK) {
                if (r0 < M) {
                    atomicAdd(C + (size_t)r0 * HW + col,     v0.x);
                    atomicAdd(C + (size_t)r0 * HW + col + 1, v0.y);
                }
                if (r0 + 8 < M) {
                    atomicAdd(C + (size_t)(r0 + 8) * HW + col,     v1.x);
                    atomicAdd(C + (size_t)(r0 + 8) * HW + col + 1, v1.y);
                }
            } else {
                if (r0 < M)
                    *reinterpret_cast<float2*>(C + (size_t)r0 * HW + col) = v0;
                if (r0 + 8 < M)
                    *reinterpret_cast<float2*>(C + (size_t)(r0 + 8) * HW + col) = v1;
            }
        }
    }
}

// ============================================================================
// Bilinear sampling -> k-major pre-split bf16 S: shi/slo [6912][4096]
// ============================================================================
__global__ __launch_bounds__(256)
void sample_kernel(const float* __restrict__ ref,
                   const float* __restrict__ off,
                   __nv_bfloat16* __restrict__ shi,
                   __nv_bfloat16* __restrict__ slo)
{
    int k = blockIdx.y;                              // 0..6911
    int n = blockIdx.x * 256 + threadIdx.x;          // 0..4095
    int c = k / 9;
    int t = k - c * 9;
    int ti = t / 3;
    int tj = t - ti * 3;
    int y = n >> 6, x = n & 63;

    float dy = off[(2 * t)     * HW + n];
    float dx = off[(2 * t + 1) * HW + n];
    float py = (float)(y - 1 + ti) + dy;
    float px = (float)(x - 1 + tj) + dx;

    float y0f = floorf(py), x0f = floorf(px);
    float wy1 = py - y0f,  wx1 = px - x0f;
    float wy0 = 1.f - wy1, wx0 = 1.f - wx1;
    int y0 = (int)y0f, x0 = (int)x0f;

    const float* r = ref + (size_t)c * HW;
    float v = 0.f;
    if (((unsigned)y0 < 64u) && ((unsigned)x0 < 64u))
        v += wy0 * wx0 * r[y0 * 64 + x0];
    if (((unsigned)y0 < 64u) && ((unsigned)(x0 + 1) < 64u))
        v += wy0 * wx1 * r[y0 * 64 + x0 + 1];
    if (((unsigned)(y0 + 1) < 64u) && ((unsigned)x0 < 64u))
        v += wy1 * wx0 * r[(y0 + 1) * 64 + x0];
    if (((unsigned)(y0 + 1) < 64u) && ((unsigned)(x0 + 1) < 64u))
        v += wy1 * wx1 * r[(y0 + 1) * 64 + x0 + 1];

    size_t oidx = (size_t)k * HW + n;
    __nv_bfloat16 h = __float2bfloat16(v);
    shi[oidx] = h;
    slo[oidx] = __float2bfloat16(v - __bfloat162float(h));
}

// ============================================================================
extern "C" void kernel_launch(void* const* d_in, const int* in_sizes, int n_in,
                              void* d_out, int out_size)
{
    const float* x_in  = (const float*)d_in[0];
    const float* x_ref = (const float*)d_in[1];
    const float* w1    = (const float*)d_in[2];
    const float* w2    = (const float*)d_in[3];
    const float* w3    = (const float*)d_in[4];
    const float* wo    = (const float*)d_in[5];
    const float* wd    = (const float*)d_in[6];
    float* out = (float*)d_out;

    float *cat, *h1, *h2, *est, *off;
    __nv_bfloat16 *shi, *slo;
    cudaGetSymbolAddress((void**)&cat, g_cat);
    cudaGetSymbolAddress((void**)&h1,  g_h1);
    cudaGetSymbolAddress((void**)&h2,  g_h2);
    cudaGetSymbolAddress((void**)&est, g_est);
    cudaGetSymbolAddress((void**)&off, g_off);
    cudaGetSymbolAddress((void**)&shi, g_shi);
    cudaGetSymbolAddress((void**)&slo, g_slo);

    // smem: BM=64 -> 4*5120 + 4*8704 = 55296 ; BM=32 -> 4*2560 + 4*8704 = 45056
    constexpr int SM64 = 4 * (64 * A_STRIDE * 2) + 4 * (32 * B_STRIDE * 2);
    constexpr int SM32 = 4 * (32 * A_STRIDE * 2) + 4 * (32 * B_STRIDE * 2);

    cudaFuncSetAttribute((const void*)gemm_mma<0, true,  2, 4, 64, 2, false>,
                         cudaFuncAttributeMaxDynamicSharedMemorySize, SM64);
    cudaFuncSetAttribute((const void*)gemm_mma<0, false, 2, 4, 64, 2, false>,
                         cudaFuncAttributeMaxDynamicSharedMemorySize, SM64);
    cudaFuncSetAttribute((const void*)gemm_mma<0, false, 1, 8, 32, 2, true>,
                         cudaFuncAttributeMaxDynamicSharedMemorySize, SM32);
    cudaFuncSetAttribute((const void*)gemm_mma<1, false, 2, 4, 64, 2, false>,
                         cudaFuncAttributeMaxDynamicSharedMemorySize, SM64);

    // concat(x, ref) -> g_cat ; zero the split-K accumulator
    cudaMemcpyAsync(cat,            x_in,  (size_t)768 * HW * 4, cudaMemcpyDeviceToDevice);
    cudaMemcpyAsync(cat + 768 * HW, x_ref, (size_t)768 * HW * 4, cudaMemcpyDeviceToDevice);
    cudaMemsetAsync(off, 0, (size_t)18 * HW * 4);

    // conv1: 1536 -> 192, relu
    gemm_mma<0, true,  2, 4, 64, 2, false><<<dim3(32, 3),  256, SM64>>>(
        w1, cat, nullptr, nullptr, h1, 192, 13824, 13824);
    // conv2: 192 -> 192, relu
    gemm_mma<0, true,  2, 4, 64, 2, false><<<dim3(32, 3),  256, SM64>>>(
        w2, h1, nullptr, nullptr, h2, 192, 1728, 1728);
    // conv3: 192 -> 1536
    gemm_mma<0, false, 2, 4, 64, 2, false><<<dim3(32, 24), 256, SM64>>>(
        w3, h2, nullptr, nullptr, est, 1536, 1728, 1728);
    // conv4: 1536 -> 18 (offsets), split-K x8 with atomic accumulation
    gemm_mma<0, false, 1, 8, 32, 2, true><<<dim3(32, 8),   256, SM32>>>(
        wo, est, nullptr, nullptr, off, 18, 13824, 1728);
    // bilinear sampling -> k-major bf16 hi/lo S
    sample_kernel<<<dim3(16, 6912), 256>>>(x_ref, off, shi, slo);
    // deform GEMM: out[768][4096] = wd[768][6912] @ S
    gemm_mma<1, false, 2, 4, 64, 2, false><<<dim3(32, 12), 256, SM64>>>(
        wd, nullptr, shi, slo, out, 768, 6912, 6912);
}

// round 7
// speedup vs baseline: 3.1979x; 1.1307x over previous
#include <cuda_runtime.h>
#include <cuda_bf16.h>
#include <cuda_fp16.h>

// ============================================================================
// DeformableConvBlock, round 7.
//   conv1: bf16 3-pass GEMM [192][13824] @ im2col3(cat)        (ReLU)
//   conv2: bf16 3-pass GEMM [192][1728]  @ im2col3(h1)         (ReLU)
//   offsets: COMPOSED conv3∘conv4:
//       woT = transpose(wo)                       (tiny kernel)
//       G[162][1728] = woT[162][1536] @ w3[1536][1728]   (bf16 3-pass GEMM)
//       Wc[18][4800] = 5x5-collapse(G)            (tiny kernel)
//       off = Wc @ im2col5(h2)  (interior exact; split-K x5, atomics)
//       border ring (496 px) recomputed exactly in fp32 from G
//   sampling: bilinear -> S fp16 [6912][4096]
//   deform: fp16 1-pass GEMM out[768][4096] = wd @ S
// ============================================================================

#define HW 4096

// ---------------- device scratch --------------------------------------------
__device__ float g_cat[1536 * HW];
__device__ float g_h1 [192  * HW];
__device__ float g_h2 [192  * HW];
__device__ float g_off[18   * HW];
__device__ float g_woT[162 * 1536];
__device__ float g_G  [162 * 1728];
__device__ float g_Wc [18 * 4800];
__device__ __half g_sh[(size_t)6912 * HW];

// ---------------- smem geometry ---------------------------------------------
#define A_STRIDE 40     // bf16/fp16 elems per A row (32 data + 8 pad)
#define B_STRIDE 136    // elems per B row (128 data + 8 pad)

// ---------------- PTX helpers ------------------------------------------------
__device__ __forceinline__ unsigned smem_to_u32(const void* p) {
    unsigned a;
    asm("{ .reg .u64 t; cvta.to.shared.u64 t, %1; cvt.u32.u64 %0, t; }"
        : "=r"(a) : "l"(p));
    return a;
}
__device__ __forceinline__ void ldsm_x4(unsigned* r, unsigned addr) {
    asm volatile("ldmatrix.sync.aligned.m8n8.x4.shared.b16 {%0,%1,%2,%3}, [%4];"
                 : "=r"(r[0]), "=r"(r[1]), "=r"(r[2]), "=r"(r[3]) : "r"(addr));
}
__device__ __forceinline__ void ldsm_x4_t(unsigned* r, unsigned addr) {
    asm volatile("ldmatrix.sync.aligned.m8n8.x4.trans.shared.b16 {%0,%1,%2,%3}, [%4];"
                 : "=r"(r[0]), "=r"(r[1]), "=r"(r[2]), "=r"(r[3]) : "r"(addr));
}
__device__ __forceinline__ void mma_bf16(float* c, const unsigned* a, const unsigned* b) {
    asm volatile(
        "mma.sync.aligned.m16n8k16.row.col.f32.bf16.bf16.f32 "
        "{%0,%1,%2,%3}, {%4,%5,%6,%7}, {%8,%9}, {%0,%1,%2,%3};"
        : "+f"(c[0]), "+f"(c[1]), "+f"(c[2]), "+f"(c[3])
        : "r"(a[0]), "r"(a[1]), "r"(a[2]), "r"(a[3]), "r"(b[0]), "r"(b[1]));
}
__device__ __forceinline__ void mma_f16(float* c, const unsigned* a, const unsigned* b) {
    asm volatile(
        "mma.sync.aligned.m16n8k16.row.col.f32.f16.f16.f32 "
        "{%0,%1,%2,%3}, {%4,%5,%6,%7}, {%8,%9}, {%0,%1,%2,%3};"
        : "+f"(c[0]), "+f"(c[1]), "+f"(c[2]), "+f"(c[3])
        : "r"(a[0]), "r"(a[1]), "r"(a[2]), "r"(a[3]), "r"(b[0]), "r"(b[1]));
}
#define STS128A(addr, r0, r1, r2, r3) \
    asm volatile("st.shared.v4.b32 [%0], {%1, %2, %3, %4};" \
                 :: "r"((unsigned)(addr)), "r"(r0), "r"(r1), "r"(r2), "r"(r3) : "memory")
#define STS64A(addr, r0, r1) \
    asm volatile("st.shared.v2.b32 [%0], {%1, %2};" \
                 :: "r"((unsigned)(addr)), "r"(r0), "r"(r1) : "memory")

__device__ __forceinline__ void split2(float a, float b, unsigned& h, unsigned& l) {
    __nv_bfloat16 ha = __float2bfloat16(a);
    __nv_bfloat16 hb = __float2bfloat16(b);
    __nv_bfloat16 la = __float2bfloat16(a - __bfloat162float(ha));
    __nv_bfloat16 lb = __float2bfloat16(b - __bfloat162float(hb));
    __nv_bfloat162 hp = __halves2bfloat162(ha, hb);
    __nv_bfloat162 lp = __halves2bfloat162(la, lb);
    h = *reinterpret_cast<unsigned*>(&hp);
    l = *reinterpret_cast<unsigned*>(&lp);
}
__device__ __forceinline__ unsigned packh2(float a, float b) {
    __half2 p = __floats2half2_rn(a, b);
    return *reinterpret_cast<unsigned*>(&p);
}

// ============================================================================
// GEMM kernel. 256 threads (8 warps = WARP_M x WARP_N). BN=128, BK=32.
// MODE 0: B = im2col(srcF fp32, TSxTS taps, pad=TS/2), N-space = 64x64 image.
// MODE 1: B = fp16 S [Kfull][4096] (requires PREC=1).
// MODE 3: B = fp32 row-major [Kfull][Nb] (srcF pointer).
// PREC 0: bf16 hi/lo 3-pass.  PREC 1: fp16 single pass.
// SPLITK: blockIdx.y = K-split (m0=0), atomicAdd epilogue.
// C is [M][ldc], cols guarded by Nb.
// ============================================================================
template<int MODE, int PREC, bool RELU, int WARP_M, int WARP_N, int BM,
         int MINB, bool SPLITK, int TS>
__global__ __launch_bounds__(256, MINB)
void gemm_mma(const float* __restrict__ A,
              const float* __restrict__ srcF,
              const __half* __restrict__ bh16,
              float* __restrict__ C, int M, int Kfull, int kcnt,
              int Nb, int ldc)
{
    constexpr int BN = 128, BK = 32;
    constexpr int MFRAG = BM / (WARP_M * 16);
    constexpr int NFRAG = BN / (WARP_N * 8);
    constexpr int A_ELEMS = (BM == 128) ? 16 : (BM == 64 ? 8 : 4);
    constexpr int NS  = (PREC == 0) ? 2 : 1;
    constexpr int ASZ = BM * A_STRIDE * 2;
    constexpr int BSZ = 32 * B_STRIDE * 2;
    constexpr int TAPS = TS * TS;
    constexpr int PD   = TS / 2;
    auto OFF_A = [](int buf, int s) { return (buf * NS + s) * ASZ; };
    auto OFF_B = [](int buf, int s) { return 2 * NS * ASZ + (buf * NS + s) * BSZ; };

    extern __shared__ char smem[];
    const unsigned sb = smem_to_u32(smem);
    const int tid  = threadIdx.x;
    const int wid  = tid >> 5;
    const int lane = tid & 31;
    const int n0 = blockIdx.x * BN;
    const int m0 = SPLITK ? 0 : blockIdx.y * BM;
    const int kb = SPLITK ? blockIdx.y * kcnt : 0;

    const int kloc = tid >> 3;          // B-loader row within tile
    const int nbb  = (tid & 7) * 16;    // B-loader col base

    float a_st[A_ELEMS];
    float b_st[16];
    uint4 b_raw[2];

    float acc[MFRAG][NFRAG][4];
    #pragma unroll
    for (int f = 0; f < MFRAG; f++)
        #pragma unroll
        for (int g = 0; g < NFRAG; g++)
            #pragma unroll
            for (int q = 0; q < 4; q++) acc[f][g][q] = 0.f;

    const int iters = kcnt / BK;

    // -------------------- tile load (global -> regs) ------------------------
    auto LOAD = [&](int k0g) {
        // ---- A ----
        if constexpr (BM == 128) {
            int m  = tid >> 1;
            int kh = (tid & 1) * 16;
            int gm = m0 + m;
            const float4* p =
                reinterpret_cast<const float4*>(A + (size_t)gm * Kfull + k0g + kh);
            #pragma unroll
            for (int q = 0; q < 4; q++) {
                float4 v = (gm < M) ? p[q] : make_float4(0.f, 0.f, 0.f, 0.f);
                a_st[q * 4 + 0] = v.x; a_st[q * 4 + 1] = v.y;
                a_st[q * 4 + 2] = v.z; a_st[q * 4 + 3] = v.w;
            }
        } else if constexpr (BM == 64) {
            int m  = tid >> 2;
            int kh = (tid & 3) * 8;
            int gm = m0 + m;
            const float4* p =
                reinterpret_cast<const float4*>(A + (size_t)gm * Kfull + k0g + kh);
            #pragma unroll
            for (int q = 0; q < 2; q++) {
                float4 v = (gm < M) ? p[q] : make_float4(0.f, 0.f, 0.f, 0.f);
                a_st[q * 4 + 0] = v.x; a_st[q * 4 + 1] = v.y;
                a_st[q * 4 + 2] = v.z; a_st[q * 4 + 3] = v.w;
            }
        } else {  // BM == 32
            int m  = tid >> 3;
            int kq = (tid & 7) * 4;
            int gm = m0 + m;
            float4 v = (gm < M)
                ? *reinterpret_cast<const float4*>(A + (size_t)gm * Kfull + k0g + kq)
                : make_float4(0.f, 0.f, 0.f, 0.f);
            a_st[0] = v.x; a_st[1] = v.y; a_st[2] = v.z; a_st[3] = v.w;
        }
        // ---- B ----
        if constexpr (MODE == 0) {
            int gk = k0g + kloc;
            int c  = gk / TAPS;
            int tap = gk - c * TAPS;
            int ti = tap / TS;
            int tj = tap - ti * TS;
            int n  = n0 + nbb;
            int y  = n >> 6;
            int xb = n & 63;
            int py = y + ti - PD;
            bool yok = (unsigned)py < 64u;
            const float* src = srcF + (size_t)c * HW + py * 64 + (xb + tj - PD);
            #pragma unroll
            for (int j = 0; j < 16; j++) {
                int px = xb + tj - PD + j;
                b_st[j] = (yok && (unsigned)px < 64u) ? __ldg(src + j) : 0.f;
            }
        } else if constexpr (MODE == 1) {
            const uint4* p = reinterpret_cast<const uint4*>(
                bh16 + (size_t)(k0g + kloc) * HW + n0 + nbb);
            b_raw[0] = p[0];
            b_raw[1] = p[1];
        } else {  // MODE 3
            const float* src = srcF + (size_t)(k0g + kloc) * Nb;
            #pragma unroll
            for (int j = 0; j < 16; j++) {
                int n = n0 + nbb + j;
                b_st[j] = (n < Nb) ? __ldg(src + n) : 0.f;
            }
        }
    };

    // -------------------- tile store (regs -> smem) -------------------------
    auto STORE = [&](int buf) {
        // ---- A ----
        if constexpr (BM == 128) {
            int m  = tid >> 1;
            int kh = (tid & 1) * 16;
            unsigned base = (unsigned)(m * A_STRIDE + kh) * 2;
            if constexpr (PREC == 0) {
                unsigned h[8], l[8];
                #pragma unroll
                for (int q = 0; q < 8; q++)
                    split2(a_st[2 * q], a_st[2 * q + 1], h[q], l[q]);
                STS128A(sb + OFF_A(buf, 0) + base,      h[0], h[1], h[2], h[3]);
                STS128A(sb + OFF_A(buf, 0) + base + 16, h[4], h[5], h[6], h[7]);
                STS128A(sb + OFF_A(buf, 1) + base,      l[0], l[1], l[2], l[3]);
                STS128A(sb + OFF_A(buf, 1) + base + 16, l[4], l[5], l[6], l[7]);
            } else {
                unsigned h[8];
                #pragma unroll
                for (int q = 0; q < 8; q++)
                    h[q] = packh2(a_st[2 * q], a_st[2 * q + 1]);
                STS128A(sb + OFF_A(buf, 0) + base,      h[0], h[1], h[2], h[3]);
                STS128A(sb + OFF_A(buf, 0) + base + 16, h[4], h[5], h[6], h[7]);
            }
        } else if constexpr (BM == 64) {
            int m  = tid >> 2;
            int kh = (tid & 3) * 8;
            unsigned base = (unsigned)(m * A_STRIDE + kh) * 2;
            if constexpr (PREC == 0) {
                unsigned h[4], l[4];
                #pragma unroll
                for (int q = 0; q < 4; q++)
                    split2(a_st[2 * q], a_st[2 * q + 1], h[q], l[q]);
                STS128A(sb + OFF_A(buf, 0) + base, h[0], h[1], h[2], h[3]);
                STS128A(sb + OFF_A(buf, 1) + base, l[0], l[1], l[2], l[3]);
            } else {
                unsigned h[4];
                #pragma unroll
                for (int q = 0; q < 4; q++)
                    h[q] = packh2(a_st[2 * q], a_st[2 * q + 1]);
                STS128A(sb + OFF_A(buf, 0) + base, h[0], h[1], h[2], h[3]);
            }
        } else {
            int m  = tid >> 3;
            int kq = (tid & 7) * 4;
            unsigned base = (unsigned)(m * A_STRIDE + kq) * 2;
            if constexpr (PREC == 0) {
                unsigned h[2], l[2];
                split2(a_st[0], a_st[1], h[0], l[0]);
                split2(a_st[2], a_st[3], h[1], l[1]);
                STS64A(sb + OFF_A(buf, 0) + base, h[0], h[1]);
                STS64A(sb + OFF_A(buf, 1) + base, l[0], l[1]);
            } else {
                STS64A(sb + OFF_A(buf, 0) + base,
                       packh2(a_st[0], a_st[1]), packh2(a_st[2], a_st[3]));
            }
        }
        // ---- B ----
        unsigned base = (unsigned)(kloc * B_STRIDE + nbb) * 2;
        if constexpr (MODE == 1) {
            STS128A(sb + OFF_B(buf, 0) + base,
                    b_raw[0].x, b_raw[0].y, b_raw[0].z, b_raw[0].w);
            STS128A(sb + OFF_B(buf, 0) + base + 16,
                    b_raw[1].x, b_raw[1].y, b_raw[1].z, b_raw[1].w);
        } else if constexpr (PREC == 0) {
            unsigned h[8], l[8];
            #pragma unroll
            for (int q = 0; q < 8; q++)
                split2(b_st[2 * q], b_st[2 * q + 1], h[q], l[q]);
            STS128A(sb + OFF_B(buf, 0) + base,      h[0], h[1], h[2], h[3]);
            STS128A(sb + OFF_B(buf, 0) + base + 16, h[4], h[5], h[6], h[7]);
            STS128A(sb + OFF_B(buf, 1) + base,      l[0], l[1], l[2], l[3]);
            STS128A(sb + OFF_B(buf, 1) + base + 16, l[4], l[5], l[6], l[7]);
        } else {
            unsigned h[8];
            #pragma unroll
            for (int q = 0; q < 8; q++)
                h[q] = packh2(b_st[2 * q], b_st[2 * q + 1]);
            STS128A(sb + OFF_B(buf, 0) + base,      h[0], h[1], h[2], h[3]);
            STS128A(sb + OFF_B(buf, 0) + base + 16, h[4], h[5], h[6], h[7]);
        }
    };

    // -------------------- compute -------------------------------------------
    const int wm  = wid % WARP_M;
    const int wn  = wid / WARP_M;
    const int mb  = wm * MFRAG * 16;
    const int nbw = wn * NFRAG * 8;

    auto COMPUTE = [&](int buf) {
        #pragma unroll
        for (int ks = 0; ks < BK; ks += 16) {
            unsigned ah[MFRAG][4], al[MFRAG][4];
            {
                int arow = mb + (lane & 15);
                int acol = ks + (lane >> 4) * 8;
                #pragma unroll
                for (int f = 0; f < MFRAG; f++) {
                    unsigned off = (unsigned)((arow + f * 16) * A_STRIDE + acol) * 2;
                    ldsm_x4(ah[f], sb + OFF_A(buf, 0) + off);
                    if constexpr (PREC == 0)
                        ldsm_x4(al[f], sb + OFF_A(buf, 1) + off);
                }
            }
            #pragma unroll
            for (int g = 0; g < NFRAG / 2; g++) {
                unsigned bh[4], bl[4];
                int brow = ks + (lane & 15);
                int bcol = nbw + g * 16 + (lane >> 4) * 8;
                unsigned off = (unsigned)(brow * B_STRIDE + bcol) * 2;
                ldsm_x4_t(bh, sb + OFF_B(buf, 0) + off);
                if constexpr (PREC == 0)
                    ldsm_x4_t(bl, sb + OFF_B(buf, 1) + off);
                #pragma unroll
                for (int f = 0; f < MFRAG; f++) {
                    #pragma unroll
                    for (int h2x = 0; h2x < 2; h2x++) {
                        float* c = acc[f][g * 2 + h2x];
                        if constexpr (PREC == 0) {
                            mma_bf16(c, ah[f], bh + h2x * 2);
                            mma_bf16(c, ah[f], bl + h2x * 2);
                            mma_bf16(c, al[f], bh + h2x * 2);
                        } else {
                            mma_f16(c, ah[f], bh + h2x * 2);
                        }
                    }
                }
            }
        }
    };

    // -------------------- main pipeline -------------------------------------
    LOAD(kb);
    STORE(0);
    __syncthreads();
    for (int i = 0; i < iters; i++) {
        if (i + 1 < iters) LOAD(kb + (i + 1) * BK);
        COMPUTE(i & 1);
        if (i + 1 < iters) {
            STORE((i + 1) & 1);
            __syncthreads();
        }
    }

    // -------------------- epilogue ------------------------------------------
    #pragma unroll
    for (int f = 0; f < MFRAG; f++) {
        #pragma unroll
        for (int j = 0; j < NFRAG; j++) {
            int r0  = m0 + mb + f * 16 + (lane >> 2);
            int col = n0 + nbw + j * 8 + (lane & 3) * 2;
            if (col >= Nb) continue;
            float2 v0 = make_float2(acc[f][j][0], acc[f][j][1]);
            float2 v1 = make_float2(acc[f][j][2], acc[f][j][3]);
            if (RELU) {
                v0.x = fmaxf(v0.x, 0.f); v0.y = fmaxf(v0.y, 0.f);
                v1.x = fmaxf(v1.x, 0.f); v1.y = fmaxf(v1.y, 0.f);
            }
            if (SPLITK) {
                if (r0 < M) {
                    atomicAdd(C + (size_t)r0 * ldc + col,     v0.x);
                    atomicAdd(C + (size_t)r0 * ldc + col + 1, v0.y);
                }
                if (r0 + 8 < M) {
                    atomicAdd(C + (size_t)(r0 + 8) * ldc + col,     v1.x);
                    atomicAdd(C + (size_t)(r0 + 8) * ldc + col + 1, v1.y);
                }
            } else {
                if (r0 < M)
                    *reinterpret_cast<float2*>(C + (size_t)r0 * ldc + col) = v0;
                if (r0 + 8 < M)
                    *reinterpret_cast<float2*>(C + (size_t)(r0 + 8) * ldc + col) = v1;
            }
        }
    }
}

// ============================================================================
// Small helper kernels for the conv3∘conv4 composition
// ============================================================================
// woT[(o*9+t1)][m] = wo[o][m][t1]
__global__ __launch_bounds__(256)
void transpose_wo(const float* __restrict__ wo, float* __restrict__ woT)
{
    int id = blockIdx.x * 256 + threadIdx.x;
    if (id >= 162 * 1536) return;
    int row = id / 1536;        // o*9 + t1
    int m   = id - row * 1536;
    int o   = row / 9;
    int t1  = row - o * 9;
    woT[id] = wo[(size_t)o * 13824 + m * 9 + t1];
}

// Wc[o][c*25 + u] = sum_{t1+t2=u} G[(o*9+t1)][c*9+t2]
__global__ __launch_bounds__(256)
void build_wc(const float* __restrict__ G, float* __restrict__ Wc)
{
    int id = blockIdx.x * 256 + threadIdx.x;
    if (id >= 18 * 4800) return;
    int o   = id / 4800;
    int rem = id - o * 4800;
    int c   = rem / 25;
    int u   = rem - c * 25;
    int uy  = u / 5, ux = u - uy * 5;
    float s = 0.f;
    #pragma unroll
    for (int t1y = 0; t1y < 3; t1y++) {
        int t2y = uy - t1y;
        if ((unsigned)t2y >= 3u) continue;
        #pragma unroll
        for (int t1x = 0; t1x < 3; t1x++) {
            int t2x = ux - t1x;
            if ((unsigned)t2x >= 3u) continue;
            s += G[(size_t)(o * 9 + t1y * 3 + t1x) * 1728 + c * 9 + t2y * 3 + t2x];
        }
    }
    Wc[id] = s;
}

// Exact recomputation of the 2-wide border ring (sequential-conv semantics).
// grid (64,64), block 192 (one thread per channel c); interior blocks exit.
__global__ __launch_bounds__(192)
void border_fix(const float* __restrict__ h2, const float* __restrict__ G,
                float* __restrict__ off)
{
    int x = blockIdx.x, y = blockIdx.y;
    if (x >= 2 && x < 62 && y >= 2 && y < 62) return;
    int c = threadIdx.x;  // 0..191

    float acc[18];
    #pragma unroll
    for (int o = 0; o < 18; o++) acc[o] = 0.f;

    const float* h2c = h2 + (size_t)c * HW;
    for (int t1y = 0; t1y < 3; t1y++) {
        int qy = y + t1y - 1;
        if ((unsigned)qy >= 64u) continue;
        for (int t1x = 0; t1x < 3; t1x++) {
            int qx = x + t1x - 1;
            if ((unsigned)qx >= 64u) continue;
            int t1 = t1y * 3 + t1x;
            for (int t2y = 0; t2y < 3; t2y++) {
                int ry = qy + t2y - 1;
                if ((unsigned)ry >= 64u) continue;
                for (int t2x = 0; t2x < 3; t2x++) {
                    int rx = qx + t2x - 1;
                    if ((unsigned)rx >= 64u) continue;
                    float v = h2c[ry * 64 + rx];
                    const float* g = G + (size_t)t1 * 1728 + c * 9 + t2y * 3 + t2x;
                    #pragma unroll
                    for (int o = 0; o < 18; o++)
                        acc[o] += g[(size_t)o * 9 * 1728] * v;
                }
            }
        }
    }

    __shared__ float red[18];
    if (threadIdx.x < 18) red[threadIdx.x] = 0.f;
    __syncthreads();
    #pragma unroll
    for (int o = 0; o < 18; o++) atomicAdd(&red[o], acc[o]);
    __syncthreads();
    if (threadIdx.x < 18)
        off[(size_t)threadIdx.x * HW + y * 64 + x] = red[threadIdx.x];
}

// ============================================================================
// Bilinear sampling -> fp16 S [6912][4096] (k-major)
// ============================================================================
__global__ __launch_bounds__(256)
void sample_kernel(const float* __restrict__ ref,
                   const float* __restrict__ off,
                   __half* __restrict__ sh)
{
    int k = blockIdx.y;                              // 0..6911
    int n = blockIdx.x * 256 + threadIdx.x;          // 0..4095
    int c = k / 9;
    int t = k - c * 9;
    int ti = t / 3;
    int tj = t - ti * 3;
    int y = n >> 6, x = n & 63;

    float dy = off[(2 * t)     * HW + n];
    float dx = off[(2 * t + 1) * HW + n];
    float py = (float)(y - 1 + ti) + dy;
    float px = (float)(x - 1 + tj) + dx;

    float y0f = floorf(py), x0f = floorf(px);
    float wy1 = py - y0f,  wx1 = px - x0f;
    float wy0 = 1.f - wy1, wx0 = 1.f - wx1;
    int y0 = (int)y0f, x0 = (int)x0f;

    const float* r = ref + (size_t)c * HW;
    float v = 0.f;
    if (((unsigned)y0 < 64u) && ((unsigned)x0 < 64u))
        v += wy0 * wx0 * r[y0 * 64 + x0];
    if (((unsigned)y0 < 64u) && ((unsigned)(x0 + 1) < 64u))
        v += wy0 * wx1 * r[y0 * 64 + x0 + 1];
    if (((unsigned)(y0 + 1) < 64u) && ((unsigned)x0 < 64u))
        v += wy1 * wx0 * r[(y0 + 1) * 64 + x0];
    if (((unsigned)(y0 + 1) < 64u) && ((unsigned)(x0 + 1) < 64u))
        v += wy1 * wx1 * r[(y0 + 1) * 64 + x0 + 1];

    sh[(size_t)k * HW + n] = __float2half(v);
}

// ============================================================================
extern "C" void kernel_launch(void* const* d_in, const int* in_sizes, int n_in,
                              void* d_out, int out_size)
{
    const float* x_in  = (const float*)d_in[0];
    const float* x_ref = (const float*)d_in[1];
    const float* w1    = (const float*)d_in[2];
    const float* w2    = (const float*)d_in[3];
    const float* w3    = (const float*)d_in[4];   // [1536][192][3][3] = [1536][1728]
    const float* wo    = (const float*)d_in[5];   // [18][1536][3][3]
    const float* wd    = (const float*)d_in[6];   // [768][768][3][3] = [768][6912]
    float* out = (float*)d_out;

    float *cat, *h1, *h2, *off, *woT, *G, *Wc;
    __half* sh;
    cudaGetSymbolAddress((void**)&cat, g_cat);
    cudaGetSymbolAddress((void**)&h1,  g_h1);
    cudaGetSymbolAddress((void**)&h2,  g_h2);
    cudaGetSymbolAddress((void**)&off, g_off);
    cudaGetSymbolAddress((void**)&woT, g_woT);
    cudaGetSymbolAddress((void**)&G,   g_G);
    cudaGetSymbolAddress((void**)&Wc,  g_Wc);
    cudaGetSymbolAddress((void**)&sh,  g_sh);

    // smem sizes
    constexpr int SM64_BF = 2 * 2 * (64 * A_STRIDE * 2 + 32 * B_STRIDE * 2); // 55296
    constexpr int SM32_BF = 2 * 2 * (32 * A_STRIDE * 2 + 32 * B_STRIDE * 2); // 45056
    constexpr int SM64_FP = 2 * 1 * (64 * A_STRIDE * 2 + 32 * B_STRIDE * 2); // 27648

    cudaFuncSetAttribute((const void*)gemm_mma<0, 0, true,  2, 4, 64, 2, false, 3>,
                         cudaFuncAttributeMaxDynamicSharedMemorySize, SM64_BF);
    cudaFuncSetAttribute((const void*)gemm_mma<3, 0, false, 2, 4, 64, 2, false, 3>,
                         cudaFuncAttributeMaxDynamicSharedMemorySize, SM64_BF);
    cudaFuncSetAttribute((const void*)gemm_mma<0, 0, false, 1, 8, 32, 2, true, 5>,
                         cudaFuncAttributeMaxDynamicSharedMemorySize, SM32_BF);
    cudaFuncSetAttribute((const void*)gemm_mma<1, 1, false, 2, 4, 64, 2, false, 3>,
                         cudaFuncAttributeMaxDynamicSharedMemorySize, SM64_FP);

    // concat(x, ref) -> g_cat ; zero the split-K offset accumulator
    cudaMemcpyAsync(cat,            x_in,  (size_t)768 * HW * 4, cudaMemcpyDeviceToDevice);
    cudaMemcpyAsync(cat + 768 * HW, x_ref, (size_t)768 * HW * 4, cudaMemcpyDeviceToDevice);
    cudaMemsetAsync(off, 0, (size_t)18 * HW * 4);

    // --- weight composition (depends only on weights) ---
    transpose_wo<<<(162 * 1536 + 255) / 256, 256>>>(wo, woT);
    // G[162][1728] = woT[162][1536] @ w3[1536][1728]
    gemm_mma<3, 0, false, 2, 4, 64, 2, false, 3><<<dim3(14, 3), 256, SM64_BF>>>(
        woT, w3, nullptr, G, 162, 1536, 1536, 1728, 1728);
    build_wc<<<(18 * 4800 + 255) / 256, 256>>>(G, Wc);

    // conv1: 1536 -> 192, relu (bf16 3-pass)
    gemm_mma<0, 0, true, 2, 4, 64, 2, false, 3><<<dim3(32, 3), 256, SM64_BF>>>(
        w1, cat, nullptr, h1, 192, 13824, 13824, HW, HW);
    // conv2: 192 -> 192, relu (bf16 3-pass)
    gemm_mma<0, 0, true, 2, 4, 64, 2, false, 3><<<dim3(32, 3), 256, SM64_BF>>>(
        w2, h1, nullptr, h2, 192, 1728, 1728, HW, HW);

    // offsets: composed 5x5 conv (interior exact), split-K x5 atomics
    gemm_mma<0, 0, false, 1, 8, 32, 2, true, 5><<<dim3(32, 5), 256, SM32_BF>>>(
        Wc, h2, nullptr, off, 18, 4800, 960, HW, HW);
    // exact border ring (overwrites composed values at border pixels)
    border_fix<<<dim3(64, 64), 192>>>(h2, G, off);

    // bilinear sampling -> fp16 S
    sample_kernel<<<dim3(16, 6912), 256>>>(x_ref, off, sh);

    // deform GEMM: out[768][4096] = wd[768][6912] @ S   (fp16 1-pass)
    gemm_mma<1, 1, false, 2, 4, 64, 2, false, 3><<<dim3(32, 12), 256, SM64_FP>>>(
        wd, nullptr, sh, out, 768, 6912, 6912, HW, HW);
}

// round 8
// speedup vs baseline: 3.5454x; 1.1086x over previous
#include <cuda_runtime.h>
#include <cuda_bf16.h>
#include <cuda_fp16.h>

// ============================================================================
// DeformableConvBlock, round 8.
//   conv1: bf16 3-pass GEMM [192][13824] @ im2col3(concat)  SPLIT-K x4, raw out
//   conv2: bf16 3-pass GEMM [192][1728]  @ im2col3(relu(h1))  (ReLU epilogue)
//   offsets: composed conv3∘conv4 (5x5 conv, interior exact) + fp32 border ring
//   sampling: bilinear -> S fp16 [6912][4096]
//   deform: fp16 1-pass GEMM out = wd @ S, BM=128
// ============================================================================

#define HW 4096

// ---------------- device scratch --------------------------------------------
__device__ float g_h1 [192  * HW];
__device__ float g_h2 [192  * HW];
__device__ float g_off[18   * HW];
__device__ float g_woT[162 * 1536];
__device__ float g_G  [162 * 1728];
__device__ float g_Wc [18 * 4800];
__device__ __half g_sh[(size_t)6912 * HW];

// ---------------- smem geometry ---------------------------------------------
#define A_STRIDE 40     // bf16/fp16 elems per A row (32 data + 8 pad)
#define B_STRIDE 136    // elems per B row (128 data + 8 pad)

// ---------------- PTX helpers ------------------------------------------------
__device__ __forceinline__ unsigned smem_to_u32(const void* p) {
    unsigned a;
    asm("{ .reg .u64 t; cvta.to.shared.u64 t, %1; cvt.u32.u64 %0, t; }"
        : "=r"(a) : "l"(p));
    return a;
}
__device__ __forceinline__ void ldsm_x4(unsigned* r, unsigned addr) {
    asm volatile("ldmatrix.sync.aligned.m8n8.x4.shared.b16 {%0,%1,%2,%3}, [%4];"
                 : "=r"(r[0]), "=r"(r[1]), "=r"(r[2]), "=r"(r[3]) : "r"(addr));
}
__device__ __forceinline__ void ldsm_x4_t(unsigned* r, unsigned addr) {
    asm volatile("ldmatrix.sync.aligned.m8n8.x4.trans.shared.b16 {%0,%1,%2,%3}, [%4];"
                 : "=r"(r[0]), "=r"(r[1]), "=r"(r[2]), "=r"(r[3]) : "r"(addr));
}
__device__ __forceinline__ void mma_bf16(float* c, const unsigned* a, const unsigned* b) {
    asm volatile(
        "mma.sync.aligned.m16n8k16.row.col.f32.bf16.bf16.f32 "
        "{%0,%1,%2,%3}, {%4,%5,%6,%7}, {%8,%9}, {%0,%1,%2,%3};"
        : "+f"(c[0]), "+f"(c[1]), "+f"(c[2]), "+f"(c[3])
        : "r"(a[0]), "r"(a[1]), "r"(a[2]), "r"(a[3]), "r"(b[0]), "r"(b[1]));
}
__device__ __forceinline__ void mma_f16(float* c, const unsigned* a, const unsigned* b) {
    asm volatile(
        "mma.sync.aligned.m16n8k16.row.col.f32.f16.f16.f32 "
        "{%0,%1,%2,%3}, {%4,%5,%6,%7}, {%8,%9}, {%0,%1,%2,%3};"
        : "+f"(c[0]), "+f"(c[1]), "+f"(c[2]), "+f"(c[3])
        : "r"(a[0]), "r"(a[1]), "r"(a[2]), "r"(a[3]), "r"(b[0]), "r"(b[1]));
}
#define STS128A(addr, r0, r1, r2, r3) \
    asm volatile("st.shared.v4.b32 [%0], {%1, %2, %3, %4};" \
                 :: "r"((unsigned)(addr)), "r"(r0), "r"(r1), "r"(r2), "r"(r3) : "memory")
#define STS64A(addr, r0, r1) \
    asm volatile("st.shared.v2.b32 [%0], {%1, %2};" \
                 :: "r"((unsigned)(addr)), "r"(r0), "r"(r1) : "memory")

__device__ __forceinline__ void split2(float a, float b, unsigned& h, unsigned& l) {
    __nv_bfloat16 ha = __float2bfloat16(a);
    __nv_bfloat16 hb = __float2bfloat16(b);
    __nv_bfloat16 la = __float2bfloat16(a - __bfloat162float(ha));
    __nv_bfloat16 lb = __float2bfloat16(b - __bfloat162float(hb));
    __nv_bfloat162 hp = __halves2bfloat162(ha, hb);
    __nv_bfloat162 lp = __halves2bfloat162(la, lb);
    h = *reinterpret_cast<unsigned*>(&hp);
    l = *reinterpret_cast<unsigned*>(&lp);
}
__device__ __forceinline__ unsigned packh2(float a, float b) {
    __half2 p = __floats2half2_rn(a, b);
    return *reinterpret_cast<unsigned*>(&p);
}

// ============================================================================
// GEMM kernel. 256 threads (8 warps = WARP_M x WARP_N). BN=128, BK=32.
// MODE 0: B = im2col(src fp32, TSxTS taps, pad=TS/2); CONCAT: c>=768 -> srcF2.
// MODE 1: B = fp16 S [Kfull][4096] (PREC must be 1).
// MODE 3: B = fp32 row-major [Kfull][Nb].
// PREC 0: bf16 hi/lo 3-pass.  PREC 1: fp16 single pass.
// RELU_B: fmaxf(v,0) applied to B elements in MODE 0 loader.
// SPLITK: blockIdx.z = K-split (kb = z*kcnt), atomicAdd epilogue.
// ============================================================================
template<int MODE, int PREC, bool RELU, bool RELU_B, bool CONCAT,
         int WARP_M, int WARP_N, int BM, int MINB, bool SPLITK, int TS>
__global__ __launch_bounds__(256, MINB)
void gemm_mma(const float* __restrict__ A,
              const float* __restrict__ srcF,
              const float* __restrict__ srcF2,
              const __half* __restrict__ bh16,
              float* __restrict__ C, int M, int Kfull, int kcnt,
              int Nb, int ldc)
{
    constexpr int BN = 128, BK = 32;
    constexpr int MFRAG = BM / (WARP_M * 16);
    constexpr int NFRAG = BN / (WARP_N * 8);
    constexpr int A_ELEMS = (BM == 128) ? 16 : (BM == 64 ? 8 : 4);
    constexpr int NS  = (PREC == 0) ? 2 : 1;
    constexpr int ASZ = BM * A_STRIDE * 2;
    constexpr int BSZ = 32 * B_STRIDE * 2;
    constexpr int TAPS = TS * TS;
    constexpr int PD   = TS / 2;
    auto OFF_A = [](int buf, int s) { return (buf * NS + s) * ASZ; };
    auto OFF_B = [](int buf, int s) { return 2 * NS * ASZ + (buf * NS + s) * BSZ; };

    extern __shared__ char smem[];
    const unsigned sb = smem_to_u32(smem);
    const int tid  = threadIdx.x;
    const int wid  = tid >> 5;
    const int lane = tid & 31;
    const int n0 = blockIdx.x * BN;
    const int m0 = blockIdx.y * BM;
    const int kb = SPLITK ? blockIdx.z * kcnt : 0;

    const int kloc = tid >> 3;          // B-loader row within tile
    const int nbb  = (tid & 7) * 16;    // B-loader col base

    float a_st[A_ELEMS];
    float b_st[16];
    uint4 b_raw[2];

    float acc[MFRAG][NFRAG][4];
    #pragma unroll
    for (int f = 0; f < MFRAG; f++)
        #pragma unroll
        for (int g = 0; g < NFRAG; g++)
            #pragma unroll
            for (int q = 0; q < 4; q++) acc[f][g][q] = 0.f;

    const int iters = kcnt / BK;

    // -------------------- tile load (global -> regs) ------------------------
    auto LOAD = [&](int k0g) {
        // ---- A ----
        if constexpr (BM == 128) {
            int m  = tid >> 1;
            int kh = (tid & 1) * 16;
            int gm = m0 + m;
            const float4* p =
                reinterpret_cast<const float4*>(A + (size_t)gm * Kfull + k0g + kh);
            #pragma unroll
            for (int q = 0; q < 4; q++) {
                float4 v = (gm < M) ? p[q] : make_float4(0.f, 0.f, 0.f, 0.f);
                a_st[q * 4 + 0] = v.x; a_st[q * 4 + 1] = v.y;
                a_st[q * 4 + 2] = v.z; a_st[q * 4 + 3] = v.w;
            }
        } else if constexpr (BM == 64) {
            int m  = tid >> 2;
            int kh = (tid & 3) * 8;
            int gm = m0 + m;
            const float4* p =
                reinterpret_cast<const float4*>(A + (size_t)gm * Kfull + k0g + kh);
            #pragma unroll
            for (int q = 0; q < 2; q++) {
                float4 v = (gm < M) ? p[q] : make_float4(0.f, 0.f, 0.f, 0.f);
                a_st[q * 4 + 0] = v.x; a_st[q * 4 + 1] = v.y;
                a_st[q * 4 + 2] = v.z; a_st[q * 4 + 3] = v.w;
            }
        } else {  // BM == 32
            int m  = tid >> 3;
            int kq = (tid & 7) * 4;
            int gm = m0 + m;
            float4 v = (gm < M)
                ? *reinterpret_cast<const float4*>(A + (size_t)gm * Kfull + k0g + kq)
                : make_float4(0.f, 0.f, 0.f, 0.f);
            a_st[0] = v.x; a_st[1] = v.y; a_st[2] = v.z; a_st[3] = v.w;
        }
        // ---- B ----
        if constexpr (MODE == 0) {
            int gk = k0g + kloc;
            int c  = gk / TAPS;
            int tap = gk - c * TAPS;
            int ti = tap / TS;
            int tj = tap - ti * TS;
            int n  = n0 + nbb;
            int y  = n >> 6;
            int xb = n & 63;
            int py = y + ti - PD;
            bool yok = (unsigned)py < 64u;
            const float* base;
            if (CONCAT && c >= 768) base = srcF2 + (size_t)(c - 768) * HW;
            else                    base = srcF + (size_t)c * HW;
            const float* src = base + py * 64 + (xb + tj - PD);
            #pragma unroll
            for (int j = 0; j < 16; j++) {
                int px = xb + tj - PD + j;
                float v = (yok && (unsigned)px < 64u) ? __ldg(src + j) : 0.f;
                if (RELU_B) v = fmaxf(v, 0.f);
                b_st[j] = v;
            }
        } else if constexpr (MODE == 1) {
            const uint4* p = reinterpret_cast<const uint4*>(
                bh16 + (size_t)(k0g + kloc) * HW + n0 + nbb);
            b_raw[0] = p[0];
            b_raw[1] = p[1];
        } else {  // MODE 3
            const float* src = srcF + (size_t)(k0g + kloc) * Nb;
            #pragma unroll
            for (int j = 0; j < 16; j++) {
                int n = n0 + nbb + j;
                b_st[j] = (n < Nb) ? __ldg(src + n) : 0.f;
            }
        }
    };

    // -------------------- tile store (regs -> smem) -------------------------
    auto STORE = [&](int buf) {
        // ---- A ----
        if constexpr (BM == 128) {
            int m  = tid >> 1;
            int kh = (tid & 1) * 16;
            unsigned base = (unsigned)(m * A_STRIDE + kh) * 2;
            if constexpr (PREC == 0) {
                unsigned h[8], l[8];
                #pragma unroll
                for (int q = 0; q < 8; q++)
                    split2(a_st[2 * q], a_st[2 * q + 1], h[q], l[q]);
                STS128A(sb + OFF_A(buf, 0) + base,      h[0], h[1], h[2], h[3]);
                STS128A(sb + OFF_A(buf, 0) + base + 16, h[4], h[5], h[6], h[7]);
                STS128A(sb + OFF_A(buf, 1) + base,      l[0], l[1], l[2], l[3]);
                STS128A(sb + OFF_A(buf, 1) + base + 16, l[4], l[5], l[6], l[7]);
            } else {
                unsigned h[8];
                #pragma unroll
                for (int q = 0; q < 8; q++)
                    h[q] = packh2(a_st[2 * q], a_st[2 * q + 1]);
                STS128A(sb + OFF_A(buf, 0) + base,      h[0], h[1], h[2], h[3]);
                STS128A(sb + OFF_A(buf, 0) + base + 16, h[4], h[5], h[6], h[7]);
            }
        } else if constexpr (BM == 64) {
            int m  = tid >> 2;
            int kh = (tid & 3) * 8;
            unsigned base = (unsigned)(m * A_STRIDE + kh) * 2;
            if constexpr (PREC == 0) {
                unsigned h[4], l[4];
                #pragma unroll
                for (int q = 0; q < 4; q++)
                    split2(a_st[2 * q], a_st[2 * q + 1], h[q], l[q]);
                STS128A(sb + OFF_A(buf, 0) + base, h[0], h[1], h[2], h[3]);
                STS128A(sb + OFF_A(buf, 1) + base, l[0], l[1], l[2], l[3]);
            } else {
                unsigned h[4];
                #pragma unroll
                for (int q = 0; q < 4; q++)
                    h[q] = packh2(a_st[2 * q], a_st[2 * q + 1]);
                STS128A(sb + OFF_A(buf, 0) + base, h[0], h[1], h[2], h[3]);
            }
        } else {
            int m  = tid >> 3;
            int kq = (tid & 7) * 4;
            unsigned base = (unsigned)(m * A_STRIDE + kq) * 2;
            if constexpr (PREC == 0) {
                unsigned h[2], l[2];
                split2(a_st[0], a_st[1], h[0], l[0]);
                split2(a_st[2], a_st[3], h[1], l[1]);
                STS64A(sb + OFF_A(buf, 0) + base, h[0], h[1]);
                STS64A(sb + OFF_A(buf, 1) + base, l[0], l[1]);
            } else {
                STS64A(sb + OFF_A(buf, 0) + base,
                       packh2(a_st[0], a_st[1]), packh2(a_st[2], a_st[3]));
            }
        }
        // ---- B ----
        unsigned base = (unsigned)(kloc * B_STRIDE + nbb) * 2;
        if constexpr (MODE == 1) {
            STS128A(sb + OFF_B(buf, 0) + base,
                    b_raw[0].x, b_raw[0].y, b_raw[0].z, b_raw[0].w);
            STS128A(sb + OFF_B(buf, 0) + base + 16,
                    b_raw[1].x, b_raw[1].y, b_raw[1].z, b_raw[1].w);
        } else if constexpr (PREC == 0) {
            unsigned h[8], l[8];
            #pragma unroll
            for (int q = 0; q < 8; q++)
                split2(b_st[2 * q], b_st[2 * q + 1], h[q], l[q]);
            STS128A(sb + OFF_B(buf, 0) + base,      h[0], h[1], h[2], h[3]);
            STS128A(sb + OFF_B(buf, 0) + base + 16, h[4], h[5], h[6], h[7]);
            STS128A(sb + OFF_B(buf, 1) + base,      l[0], l[1], l[2], l[3]);
            STS128A(sb + OFF_B(buf, 1) + base + 16, l[4], l[5], l[6], l[7]);
        } else {
            unsigned h[8];
            #pragma unroll
            for (int q = 0; q < 8; q++)
                h[q] = packh2(b_st[2 * q], b_st[2 * q + 1]);
            STS128A(sb + OFF_B(buf, 0) + base,      h[0], h[1], h[2], h[3]);
            STS128A(sb + OFF_B(buf, 0) + base + 16, h[4], h[5], h[6], h[7]);
        }
    };

    // -------------------- compute -------------------------------------------
    const int wm  = wid % WARP_M;
    const int wn  = wid / WARP_M;
    const int mb  = wm * MFRAG * 16;
    const int nbw = wn * NFRAG * 8;

    auto COMPUTE = [&](int buf) {
        #pragma unroll
        for (int ks = 0; ks < BK; ks += 16) {
            unsigned ah[MFRAG][4], al[MFRAG][4];
            {
                int arow = mb + (lane & 15);
                int acol = ks + (lane >> 4) * 8;
                #pragma unroll
                for (int f = 0; f < MFRAG; f++) {
                    unsigned off = (unsigned)((arow + f * 16) * A_STRIDE + acol) * 2;
                    ldsm_x4(ah[f], sb + OFF_A(buf, 0) + off);
                    if constexpr (PREC == 0)
                        ldsm_x4(al[f], sb + OFF_A(buf, 1) + off);
                }
            }
            #pragma unroll
            for (int g = 0; g < NFRAG / 2; g++) {
                unsigned bh[4], bl[4];
                int brow = ks + (lane & 15);
                int bcol = nbw + g * 16 + (lane >> 4) * 8;
                unsigned off = (unsigned)(brow * B_STRIDE + bcol) * 2;
                ldsm_x4_t(bh, sb + OFF_B(buf, 0) + off);
                if constexpr (PREC == 0)
                    ldsm_x4_t(bl, sb + OFF_B(buf, 1) + off);
                #pragma unroll
                for (int f = 0; f < MFRAG; f++) {
                    #pragma unroll
                    for (int h2x = 0; h2x < 2; h2x++) {
                        float* c = acc[f][g * 2 + h2x];
                        if constexpr (PREC == 0) {
                            mma_bf16(c, ah[f], bh + h2x * 2);
                            mma_bf16(c, ah[f], bl + h2x * 2);
                            mma_bf16(c, al[f], bh + h2x * 2);
                        } else {
                            mma_f16(c, ah[f], bh + h2x * 2);
                        }
                    }
                }
            }
        }
    };

    // -------------------- main pipeline -------------------------------------
    LOAD(kb);
    STORE(0);
    __syncthreads();
    for (int i = 0; i < iters; i++) {
        if (i + 1 < iters) LOAD(kb + (i + 1) * BK);
        COMPUTE(i & 1);
        if (i + 1 < iters) {
            STORE((i + 1) & 1);
            __syncthreads();
        }
    }

    // -------------------- epilogue ------------------------------------------
    #pragma unroll
    for (int f = 0; f < MFRAG; f++) {
        #pragma unroll
        for (int j = 0; j < NFRAG; j++) {
            int r0  = m0 + mb + f * 16 + (lane >> 2);
            int col = n0 + nbw + j * 8 + (lane & 3) * 2;
            if (col >= Nb) continue;
            float2 v0 = make_float2(acc[f][j][0], acc[f][j][1]);
            float2 v1 = make_float2(acc[f][j][2], acc[f][j][3]);
            if (RELU) {
                v0.x = fmaxf(v0.x, 0.f); v0.y = fmaxf(v0.y, 0.f);
                v1.x = fmaxf(v1.x, 0.f); v1.y = fmaxf(v1.y, 0.f);
            }
            if (SPLITK) {
                if (r0 < M) {
                    atomicAdd(C + (size_t)r0 * ldc + col,     v0.x);
                    atomicAdd(C + (size_t)r0 * ldc + col + 1, v0.y);
                }
                if (r0 + 8 < M) {
                    atomicAdd(C + (size_t)(r0 + 8) * ldc + col,     v1.x);
                    atomicAdd(C + (size_t)(r0 + 8) * ldc + col + 1, v1.y);
                }
            } else {
                if (r0 < M)
                    *reinterpret_cast<float2*>(C + (size_t)r0 * ldc + col) = v0;
                if (r0 + 8 < M)
                    *reinterpret_cast<float2*>(C + (size_t)(r0 + 8) * ldc + col) = v1;
            }
        }
    }
}

// ============================================================================
// Small helper kernels for the conv3∘conv4 composition
// ============================================================================
__global__ __launch_bounds__(256)
void transpose_wo(const float* __restrict__ wo, float* __restrict__ woT)
{
    int id = blockIdx.x * 256 + threadIdx.x;
    if (id >= 162 * 1536) return;
    int row = id / 1536;        // o*9 + t1
    int m   = id - row * 1536;
    int o   = row / 9;
    int t1  = row - o * 9;
    woT[id] = wo[(size_t)o * 13824 + m * 9 + t1];
}

__global__ __launch_bounds__(256)
void build_wc(const float* __restrict__ G, float* __restrict__ Wc)
{
    int id = blockIdx.x * 256 + threadIdx.x;
    if (id >= 18 * 4800) return;
    int o   = id / 4800;
    int rem = id - o * 4800;
    int c   = rem / 25;
    int u   = rem - c * 25;
    int uy  = u / 5, ux = u - uy * 5;
    float s = 0.f;
    #pragma unroll
    for (int t1y = 0; t1y < 3; t1y++) {
        int t2y = uy - t1y;
        if ((unsigned)t2y >= 3u) continue;
        #pragma unroll
        for (int t1x = 0; t1x < 3; t1x++) {
            int t2x = ux - t1x;
            if ((unsigned)t2x >= 3u) continue;
            s += G[(size_t)(o * 9 + t1y * 3 + t1x) * 1728 + c * 9 + t2y * 3 + t2x];
        }
    }
    Wc[id] = s;
}

// Exact fp32 recomputation of the border ring (496 px).
__global__ __launch_bounds__(192)
void border_fix(const float* __restrict__ h2, const float* __restrict__ G,
                float* __restrict__ off)
{
    int x = blockIdx.x, y = blockIdx.y;
    if (x >= 2 && x < 62 && y >= 2 && y < 62) return;
    int c = threadIdx.x;  // 0..191

    float acc[18];
    #pragma unroll
    for (int o = 0; o < 18; o++) acc[o] = 0.f;

    const float* h2c = h2 + (size_t)c * HW;
    for (int t1y = 0; t1y < 3; t1y++) {
        int qy = y + t1y - 1;
        if ((unsigned)qy >= 64u) continue;
        for (int t1x = 0; t1x < 3; t1x++) {
            int qx = x + t1x - 1;
            if ((unsigned)qx >= 64u) continue;
            int t1 = t1y * 3 + t1x;
            for (int t2y = 0; t2y < 3; t2y++) {
                int ry = qy + t2y - 1;
                if ((unsigned)ry >= 64u) continue;
                for (int t2x = 0; t2x < 3; t2x++) {
                    int rx = qx + t2x - 1;
                    if ((unsigned)rx >= 64u) continue;
                    float v = h2c[ry * 64 + rx];
                    const float* g = G + (size_t)t1 * 1728 + c * 9 + t2y * 3 + t2x;
                    #pragma unroll
                    for (int o = 0; o < 18; o++)
                        acc[o] += g[(size_t)o * 9 * 1728] * v;
                }
            }
        }
    }

    __shared__ float red[18];
    if (threadIdx.x < 18) red[threadIdx.x] = 0.f;
    __syncthreads();
    #pragma unroll
    for (int o = 0; o < 18; o++) atomicAdd(&red[o], acc[o]);
    __syncthreads();
    if (threadIdx.x < 18)
        off[(size_t)threadIdx.x * HW + y * 64 + x] = red[threadIdx.x];
}

// ============================================================================
// Bilinear sampling -> fp16 S [6912][4096] (k-major)
// ============================================================================
__global__ __launch_bounds__(256)
void sample_kernel(const float* __restrict__ ref,
                   const float* __restrict__ off,
                   __half* __restrict__ sh)
{
    int k = blockIdx.y;                              // 0..6911
    int n = blockIdx.x * 256 + threadIdx.x;          // 0..4095
    int c = k / 9;
    int t = k - c * 9;
    int ti = t / 3;
    int tj = t - ti * 3;
    int y = n >> 6, x = n & 63;

    float dy = off[(2 * t)     * HW + n];
    float dx = off[(2 * t + 1) * HW + n];
    float py = (float)(y - 1 + ti) + dy;
    float px = (float)(x - 1 + tj) + dx;

    float y0f = floorf(py), x0f = floorf(px);
    float wy1 = py - y0f,  wx1 = px - x0f;
    float wy0 = 1.f - wy1, wx0 = 1.f - wx1;
    int y0 = (int)y0f, x0 = (int)x0f;

    const float* r = ref + (size_t)c * HW;
    float v = 0.f;
    if (((unsigned)y0 < 64u) && ((unsigned)x0 < 64u))
        v += wy0 * wx0 * r[y0 * 64 + x0];
    if (((unsigned)y0 < 64u) && ((unsigned)(x0 + 1) < 64u))
        v += wy0 * wx1 * r[y0 * 64 + x0 + 1];
    if (((unsigned)(y0 + 1) < 64u) && ((unsigned)x0 < 64u))
        v += wy1 * wx0 * r[(y0 + 1) * 64 + x0];
    if (((unsigned)(y0 + 1) < 64u) && ((unsigned)(x0 + 1) < 64u))
        v += wy1 * wx1 * r[(y0 + 1) * 64 + x0 + 1];

    sh[(size_t)k * HW + n] = __float2half(v);
}

// ============================================================================
extern "C" void kernel_launch(void* const* d_in, const int* in_sizes, int n_in,
                              void* d_out, int out_size)
{
    const float* x_in  = (const float*)d_in[0];
    const float* x_ref = (const float*)d_in[1];
    const float* w1    = (const float*)d_in[2];
    const float* w2    = (const float*)d_in[3];
    const float* w3    = (const float*)d_in[4];
    const float* wo    = (const float*)d_in[5];
    const float* wd    = (const float*)d_in[6];
    float* out = (float*)d_out;

    float *h1, *h2, *off, *woT, *G, *Wc;
    __half* sh;
    cudaGetSymbolAddress((void**)&h1,  g_h1);
    cudaGetSymbolAddress((void**)&h2,  g_h2);
    cudaGetSymbolAddress((void**)&off, g_off);
    cudaGetSymbolAddress((void**)&woT, g_woT);
    cudaGetSymbolAddress((void**)&G,   g_G);
    cudaGetSymbolAddress((void**)&Wc,  g_Wc);
    cudaGetSymbolAddress((void**)&sh,  g_sh);

    constexpr int SM64_BF  = 2 * 2 * (64 * A_STRIDE * 2 + 32 * B_STRIDE * 2);  // 55296
    constexpr int SM32_BF  = 2 * 2 * (32 * A_STRIDE * 2 + 32 * B_STRIDE * 2);  // 45056
    constexpr int SM128_FP = 2 * 1 * (128 * A_STRIDE * 2 + 32 * B_STRIDE * 2); // 37888

    cudaFuncSetAttribute(
        (const void*)gemm_mma<3, 0, false, false, false, 2, 4, 64, 2, false, 3>,
        cudaFuncAttributeMaxDynamicSharedMemorySize, SM64_BF);
    cudaFuncSetAttribute(
        (const void*)gemm_mma<0, 0, false, false, true, 2, 4, 64, 2, true, 3>,
        cudaFuncAttributeMaxDynamicSharedMemorySize, SM64_BF);
    cudaFuncSetAttribute(
        (const void*)gemm_mma<0, 0, true, true, false, 2, 4, 64, 2, false, 3>,
        cudaFuncAttributeMaxDynamicSharedMemorySize, SM64_BF);
    cudaFuncSetAttribute(
        (const void*)gemm_mma<0, 0, false, false, false, 1, 8, 32, 2, true, 5>,
        cudaFuncAttributeMaxDynamicSharedMemorySize, SM32_BF);
    cudaFuncSetAttribute(
        (const void*)gemm_mma<1, 1, false, false, false, 4, 2, 128, 2, false, 3>,
        cudaFuncAttributeMaxDynamicSharedMemorySize, SM128_FP);

    // zero the split-K accumulators
    cudaMemsetAsync(h1,  0, (size_t)192 * HW * 4);
    cudaMemsetAsync(off, 0, (size_t)18  * HW * 4);

    // --- weight composition (conv3 ∘ conv4) ---
    transpose_wo<<<(162 * 1536 + 255) / 256, 256>>>(wo, woT);
    gemm_mma<3, 0, false, false, false, 2, 4, 64, 2, false, 3>
        <<<dim3(14, 3), 256, SM64_BF>>>(
        woT, w3, nullptr, nullptr, G, 162, 1536, 1536, 1728, 1728);
    build_wc<<<(18 * 4800 + 255) / 256, 256>>>(G, Wc);

    // conv1: 1536 -> 192, concat loader, SPLIT-K x4, raw output (no ReLU)
    gemm_mma<0, 0, false, false, true, 2, 4, 64, 2, true, 3>
        <<<dim3(32, 3, 4), 256, SM64_BF>>>(
        w1, x_in, x_ref, nullptr, h1, 192, 13824, 3456, HW, HW);

    // conv2: 192 -> 192, ReLU on B (h1) in loader, ReLU epilogue
    gemm_mma<0, 0, true, true, false, 2, 4, 64, 2, false, 3>
        <<<dim3(32, 3), 256, SM64_BF>>>(
        w2, h1, nullptr, nullptr, h2, 192, 1728, 1728, HW, HW);

    // offsets: composed 5x5 conv (interior), split-K x5 atomics
    gemm_mma<0, 0, false, false, false, 1, 8, 32, 2, true, 5>
        <<<dim3(32, 1, 5), 256, SM32_BF>>>(
        Wc, h2, nullptr, nullptr, off, 18, 4800, 960, HW, HW);
    // exact border ring
    border_fix<<<dim3(64, 64), 192>>>(h2, G, off);

    // bilinear sampling -> fp16 S
    sample_kernel<<<dim3(16, 6912), 256>>>(x_ref, off, sh);

    // deform GEMM: out[768][4096] = wd[768][6912] @ S  (fp16 1-pass, BM=128)
    gemm_mma<1, 1, false, false, false, 4, 2, 128, 2, false, 3>
        <<<dim3(32, 6), 256, SM128_FP>>>(
        wd, nullptr, nullptr, sh, out, 768, 6912, 6912, HW, HW);
}

// round 9
// speedup vs baseline: 4.3417x; 1.2246x over previous
#include <cuda_runtime.h>
#include <cuda_bf16.h>
#include <cuda_fp16.h>

// ============================================================================
// DeformableConvBlock, round 9.
//   conv1: fp16 2-pass GEMM (A=w1 split hi/lo, B single fp16) SPLIT-K x3
//   conv2: bf16 3-pass GEMM (relu(h1) loader) SPLIT-K x3, raw out
//   offsets: composed conv3∘conv4 (5x5, interior) SPLIT-K x10 + fp32 border
//            (h2 consumed with ReLU applied in loaders)
//   sampling: bilinear -> S fp16 [6912][4096]
//   deform: fp16 1-pass GEMM out = wd @ S, BM=128
// ============================================================================

#define HW 4096

// ---------------- device scratch --------------------------------------------
__device__ float g_h1 [192  * HW];
__device__ float g_h2 [192  * HW];   // RAW (pre-ReLU) conv2 output
__device__ float g_off[18   * HW];
__device__ float g_woT[162 * 1536];
__device__ float g_G  [162 * 1728];
__device__ float g_Wc [18 * 4800];
__device__ __half g_sh[(size_t)6912 * HW];

// ---------------- smem geometry ---------------------------------------------
#define A_STRIDE 40     // elems per A row (32 data + 8 pad)
#define B_STRIDE 136    // elems per B row (128 data + 8 pad)

// ---------------- PTX helpers ------------------------------------------------
__device__ __forceinline__ unsigned smem_to_u32(const void* p) {
    unsigned a;
    asm("{ .reg .u64 t; cvta.to.shared.u64 t, %1; cvt.u32.u64 %0, t; }"
        : "=r"(a) : "l"(p));
    return a;
}
__device__ __forceinline__ void ldsm_x4(unsigned* r, unsigned addr) {
    asm volatile("ldmatrix.sync.aligned.m8n8.x4.shared.b16 {%0,%1,%2,%3}, [%4];"
                 : "=r"(r[0]), "=r"(r[1]), "=r"(r[2]), "=r"(r[3]) : "r"(addr));
}
__device__ __forceinline__ void ldsm_x4_t(unsigned* r, unsigned addr) {
    asm volatile("ldmatrix.sync.aligned.m8n8.x4.trans.shared.b16 {%0,%1,%2,%3}, [%4];"
                 : "=r"(r[0]), "=r"(r[1]), "=r"(r[2]), "=r"(r[3]) : "r"(addr));
}
__device__ __forceinline__ void mma_bf16(float* c, const unsigned* a, const unsigned* b) {
    asm volatile(
        "mma.sync.aligned.m16n8k16.row.col.f32.bf16.bf16.f32 "
        "{%0,%1,%2,%3}, {%4,%5,%6,%7}, {%8,%9}, {%0,%1,%2,%3};"
        : "+f"(c[0]), "+f"(c[1]), "+f"(c[2]), "+f"(c[3])
        : "r"(a[0]), "r"(a[1]), "r"(a[2]), "r"(a[3]), "r"(b[0]), "r"(b[1]));
}
__device__ __forceinline__ void mma_f16(float* c, const unsigned* a, const unsigned* b) {
    asm volatile(
        "mma.sync.aligned.m16n8k16.row.col.f32.f16.f16.f32 "
        "{%0,%1,%2,%3}, {%4,%5,%6,%7}, {%8,%9}, {%0,%1,%2,%3};"
        : "+f"(c[0]), "+f"(c[1]), "+f"(c[2]), "+f"(c[3])
        : "r"(a[0]), "r"(a[1]), "r"(a[2]), "r"(a[3]), "r"(b[0]), "r"(b[1]));
}
#define STS128A(addr, r0, r1, r2, r3) \
    asm volatile("st.shared.v4.b32 [%0], {%1, %2, %3, %4};" \
                 :: "r"((unsigned)(addr)), "r"(r0), "r"(r1), "r"(r2), "r"(r3) : "memory")
#define STS64A(addr, r0, r1) \
    asm volatile("st.shared.v2.b32 [%0], {%1, %2};" \
                 :: "r"((unsigned)(addr)), "r"(r0), "r"(r1) : "memory")

// bf16 hi/lo split (pair -> packed)
__device__ __forceinline__ void split2(float a, float b, unsigned& h, unsigned& l) {
    __nv_bfloat16 ha = __float2bfloat16(a);
    __nv_bfloat16 hb = __float2bfloat16(b);
    __nv_bfloat16 la = __float2bfloat16(a - __bfloat162float(ha));
    __nv_bfloat16 lb = __float2bfloat16(b - __bfloat162float(hb));
    __nv_bfloat162 hp = __halves2bfloat162(ha, hb);
    __nv_bfloat162 lp = __halves2bfloat162(la, lb);
    h = *reinterpret_cast<unsigned*>(&hp);
    l = *reinterpret_cast<unsigned*>(&lp);
}
// fp16 hi/lo split (pair -> packed)
__device__ __forceinline__ void splith2(float a, float b, unsigned& h, unsigned& l) {
    __half ha = __float2half(a);
    __half hb = __float2half(b);
    __half la = __float2half(a - __half2float(ha));
    __half lb = __float2half(b - __half2float(hb));
    __half2 hp = __halves2half2(ha, hb);
    __half2 lp = __halves2half2(la, lb);
    h = *reinterpret_cast<unsigned*>(&hp);
    l = *reinterpret_cast<unsigned*>(&lp);
}
__device__ __forceinline__ unsigned packh2(float a, float b) {
    __half2 p = __floats2half2_rn(a, b);
    return *reinterpret_cast<unsigned*>(&p);
}

// ============================================================================
// GEMM kernel. 256 threads (8 warps = WARP_M x WARP_N). BN=128, BK=32.
// MODE 0: B = im2col(src fp32, TSxTS taps, pad=TS/2); CONCAT: c>=768 -> srcF2.
// MODE 1: B = fp16 S [Kfull][4096].
// MODE 3: B = fp32 row-major [Kfull][Nb].
// PREC 0: bf16 hi/lo 3-pass (A 2 sets, B 2 sets).
// PREC 1: fp16 single pass  (A 1 set,  B 1 set).
// PREC 2: fp16 2-pass       (A 2 sets hi/lo, B 1 set) — exact A, fp16-rounded B.
// RELU_B: fmaxf(v,0) on B elements in MODE 0 loader.
// SPLITK: blockIdx.z = K-split (kb = z*kcnt), atomicAdd epilogue.
// ============================================================================
template<int MODE, int PREC, bool RELU, bool RELU_B, bool CONCAT,
         int WARP_M, int WARP_N, int BM, int MINB, bool SPLITK, int TS>
__global__ __launch_bounds__(256, MINB)
void gemm_mma(const float* __restrict__ A,
              const float* __restrict__ srcF,
              const float* __restrict__ srcF2,
              const __half* __restrict__ bh16,
              float* __restrict__ C, int M, int Kfull, int kcnt,
              int Nb, int ldc)
{
    constexpr int BN = 128, BK = 32;
    constexpr int MFRAG = BM / (WARP_M * 16);
    constexpr int NFRAG = BN / (WARP_N * 8);
    constexpr int A_ELEMS = (BM == 128) ? 16 : (BM == 64 ? 8 : 4);
    constexpr int NS_A = (PREC == 1) ? 1 : 2;
    constexpr int NS_B = (PREC == 0) ? 2 : 1;
    constexpr int ASZ = BM * A_STRIDE * 2;
    constexpr int BSZ = 32 * B_STRIDE * 2;
    constexpr int TAPS = TS * TS;
    constexpr int PD   = TS / 2;
    auto OFF_A = [](int buf, int s) { return (buf * NS_A + s) * ASZ; };
    auto OFF_B = [](int buf, int s) { return 2 * NS_A * ASZ + (buf * NS_B + s) * BSZ; };

    extern __shared__ char smem[];
    const unsigned sb = smem_to_u32(smem);
    const int tid  = threadIdx.x;
    const int wid  = tid >> 5;
    const int lane = tid & 31;
    const int n0 = blockIdx.x * BN;
    const int m0 = blockIdx.y * BM;
    const int kb = SPLITK ? blockIdx.z * kcnt : 0;

    const int kloc = tid >> 3;          // B-loader row within tile
    const int nbb  = (tid & 7) * 16;    // B-loader col base

    float a_st[A_ELEMS];
    float b_st[16];
    uint4 b_raw[2];

    float acc[MFRAG][NFRAG][4];
    #pragma unroll
    for (int f = 0; f < MFRAG; f++)
        #pragma unroll
        for (int g = 0; g < NFRAG; g++)
            #pragma unroll
            for (int q = 0; q < 4; q++) acc[f][g][q] = 0.f;

    const int iters = kcnt / BK;

    // -------------------- tile load (global -> regs) ------------------------
    auto LOAD = [&](int k0g) {
        // ---- A ----
        if constexpr (BM == 128) {
            int m  = tid >> 1;
            int kh = (tid & 1) * 16;
            int gm = m0 + m;
            const float4* p =
                reinterpret_cast<const float4*>(A + (size_t)gm * Kfull + k0g + kh);
            #pragma unroll
            for (int q = 0; q < 4; q++) {
                float4 v = (gm < M) ? p[q] : make_float4(0.f, 0.f, 0.f, 0.f);
                a_st[q * 4 + 0] = v.x; a_st[q * 4 + 1] = v.y;
                a_st[q * 4 + 2] = v.z; a_st[q * 4 + 3] = v.w;
            }
        } else if constexpr (BM == 64) {
            int m  = tid >> 2;
            int kh = (tid & 3) * 8;
            int gm = m0 + m;
            const float4* p =
                reinterpret_cast<const float4*>(A + (size_t)gm * Kfull + k0g + kh);
            #pragma unroll
            for (int q = 0; q < 2; q++) {
                float4 v = (gm < M) ? p[q] : make_float4(0.f, 0.f, 0.f, 0.f);
                a_st[q * 4 + 0] = v.x; a_st[q * 4 + 1] = v.y;
                a_st[q * 4 + 2] = v.z; a_st[q * 4 + 3] = v.w;
            }
        } else {  // BM == 32
            int m  = tid >> 3;
            int kq = (tid & 7) * 4;
            int gm = m0 + m;
            float4 v = (gm < M)
                ? *reinterpret_cast<const float4*>(A + (size_t)gm * Kfull + k0g + kq)
                : make_float4(0.f, 0.f, 0.f, 0.f);
            a_st[0] = v.x; a_st[1] = v.y; a_st[2] = v.z; a_st[3] = v.w;
        }
        // ---- B ----
        if constexpr (MODE == 0) {
            int gk = k0g + kloc;
            int c  = gk / TAPS;
            int tap = gk - c * TAPS;
            int ti = tap / TS;
            int tj = tap - ti * TS;
            int n  = n0 + nbb;
            int y  = n >> 6;
            int xb = n & 63;
            int py = y + ti - PD;
            bool yok = (unsigned)py < 64u;
            const float* base;
            if (CONCAT && c >= 768) base = srcF2 + (size_t)(c - 768) * HW;
            else                    base = srcF + (size_t)c * HW;
            const float* src = base + py * 64 + (xb + tj - PD);
            #pragma unroll
            for (int j = 0; j < 16; j++) {
                int px = xb + tj - PD + j;
                float v = (yok && (unsigned)px < 64u) ? __ldg(src + j) : 0.f;
                if (RELU_B) v = fmaxf(v, 0.f);
                b_st[j] = v;
            }
        } else if constexpr (MODE == 1) {
            const uint4* p = reinterpret_cast<const uint4*>(
                bh16 + (size_t)(k0g + kloc) * HW + n0 + nbb);
            b_raw[0] = p[0];
            b_raw[1] = p[1];
        } else {  // MODE 3
            const float* src = srcF + (size_t)(k0g + kloc) * Nb;
            #pragma unroll
            for (int j = 0; j < 16; j++) {
                int n = n0 + nbb + j;
                b_st[j] = (n < Nb) ? __ldg(src + n) : 0.f;
            }
        }
    };

    // -------------------- tile store (regs -> smem) -------------------------
    auto STORE_A_PAIRS = [&](int buf, unsigned base, const float* src, int npairs) {
        if constexpr (PREC == 0) {
            unsigned h[8], l[8];
            for (int q = 0; q < npairs; q++)
                split2(src[2 * q], src[2 * q + 1], h[q], l[q]);
            for (int q4 = 0; q4 < npairs / 4; q4++) {
                STS128A(sb + OFF_A(buf, 0) + base + q4 * 16,
                        h[q4 * 4], h[q4 * 4 + 1], h[q4 * 4 + 2], h[q4 * 4 + 3]);
                STS128A(sb + OFF_A(buf, 1) + base + q4 * 16,
                        l[q4 * 4], l[q4 * 4 + 1], l[q4 * 4 + 2], l[q4 * 4 + 3]);
            }
            if (npairs == 2) {
                STS64A(sb + OFF_A(buf, 0) + base, h[0], h[1]);
                STS64A(sb + OFF_A(buf, 1) + base, l[0], l[1]);
            }
        } else if constexpr (PREC == 2) {
            unsigned h[8], l[8];
            for (int q = 0; q < npairs; q++)
                splith2(src[2 * q], src[2 * q + 1], h[q], l[q]);
            for (int q4 = 0; q4 < npairs / 4; q4++) {
                STS128A(sb + OFF_A(buf, 0) + base + q4 * 16,
                        h[q4 * 4], h[q4 * 4 + 1], h[q4 * 4 + 2], h[q4 * 4 + 3]);
                STS128A(sb + OFF_A(buf, 1) + base + q4 * 16,
                        l[q4 * 4], l[q4 * 4 + 1], l[q4 * 4 + 2], l[q4 * 4 + 3]);
            }
            if (npairs == 2) {
                STS64A(sb + OFF_A(buf, 0) + base, h[0], h[1]);
                STS64A(sb + OFF_A(buf, 1) + base, l[0], l[1]);
            }
        } else {
            unsigned h[8];
            for (int q = 0; q < npairs; q++)
                h[q] = packh2(src[2 * q], src[2 * q + 1]);
            for (int q4 = 0; q4 < npairs / 4; q4++)
                STS128A(sb + OFF_A(buf, 0) + base + q4 * 16,
                        h[q4 * 4], h[q4 * 4 + 1], h[q4 * 4 + 2], h[q4 * 4 + 3]);
            if (npairs == 2)
                STS64A(sb + OFF_A(buf, 0) + base, h[0], h[1]);
        }
    };

    auto STORE = [&](int buf) {
        // ---- A ----
        if constexpr (BM == 128) {
            int m  = tid >> 1;
            int kh = (tid & 1) * 16;
            STORE_A_PAIRS(buf, (unsigned)(m * A_STRIDE + kh) * 2, a_st, 8);
        } else if constexpr (BM == 64) {
            int m  = tid >> 2;
            int kh = (tid & 3) * 8;
            STORE_A_PAIRS(buf, (unsigned)(m * A_STRIDE + kh) * 2, a_st, 4);
        } else {
            int m  = tid >> 3;
            int kq = (tid & 7) * 4;
            STORE_A_PAIRS(buf, (unsigned)(m * A_STRIDE + kq) * 2, a_st, 2);
        }
        // ---- B ----
        unsigned base = (unsigned)(kloc * B_STRIDE + nbb) * 2;
        if constexpr (MODE == 1) {
            STS128A(sb + OFF_B(buf, 0) + base,
                    b_raw[0].x, b_raw[0].y, b_raw[0].z, b_raw[0].w);
            STS128A(sb + OFF_B(buf, 0) + base + 16,
                    b_raw[1].x, b_raw[1].y, b_raw[1].z, b_raw[1].w);
        } else if constexpr (PREC == 0) {
            unsigned h[8], l[8];
            #pragma unroll
            for (int q = 0; q < 8; q++)
                split2(b_st[2 * q], b_st[2 * q + 1], h[q], l[q]);
            STS128A(sb + OFF_B(buf, 0) + base,      h[0], h[1], h[2], h[3]);
            STS128A(sb + OFF_B(buf, 0) + base + 16, h[4], h[5], h[6], h[7]);
            STS128A(sb + OFF_B(buf, 1) + base,      l[0], l[1], l[2], l[3]);
            STS128A(sb + OFF_B(buf, 1) + base + 16, l[4], l[5], l[6], l[7]);
        } else {
            unsigned h[8];
            #pragma unroll
            for (int q = 0; q < 8; q++)
                h[q] = packh2(b_st[2 * q], b_st[2 * q + 1]);
            STS128A(sb + OFF_B(buf, 0) + base,      h[0], h[1], h[2], h[3]);
            STS128A(sb + OFF_B(buf, 0) + base + 16, h[4], h[5], h[6], h[7]);
        }
    };

    // -------------------- compute -------------------------------------------
    const int wm  = wid % WARP_M;
    const int wn  = wid / WARP_M;
    const int mb  = wm * MFRAG * 16;
    const int nbw = wn * NFRAG * 8;

    auto COMPUTE = [&](int buf) {
        #pragma unroll
        for (int ks = 0; ks < BK; ks += 16) {
            unsigned ah[MFRAG][4], al[MFRAG][4];
            {
                int arow = mb + (lane & 15);
                int acol = ks + (lane >> 4) * 8;
                #pragma unroll
                for (int f = 0; f < MFRAG; f++) {
                    unsigned off = (unsigned)((arow + f * 16) * A_STRIDE + acol) * 2;
                    ldsm_x4(ah[f], sb + OFF_A(buf, 0) + off);
                    if constexpr (NS_A == 2)
                        ldsm_x4(al[f], sb + OFF_A(buf, 1) + off);
                }
            }
            #pragma unroll
            for (int g = 0; g < NFRAG / 2; g++) {
                unsigned bh[4], bl[4];
                int brow = ks + (lane & 15);
                int bcol = nbw + g * 16 + (lane >> 4) * 8;
                unsigned off = (unsigned)(brow * B_STRIDE + bcol) * 2;
                ldsm_x4_t(bh, sb + OFF_B(buf, 0) + off);
                if constexpr (NS_B == 2)
                    ldsm_x4_t(bl, sb + OFF_B(buf, 1) + off);
                #pragma unroll
                for (int f = 0; f < MFRAG; f++) {
                    #pragma unroll
                    for (int h2x = 0; h2x < 2; h2x++) {
                        float* c = acc[f][g * 2 + h2x];
                        if constexpr (PREC == 0) {
                            mma_bf16(c, ah[f], bh + h2x * 2);
                            mma_bf16(c, ah[f], bl + h2x * 2);
                            mma_bf16(c, al[f], bh + h2x * 2);
                        } else if constexpr (PREC == 2) {
                            mma_f16(c, ah[f], bh + h2x * 2);
                            mma_f16(c, al[f], bh + h2x * 2);
                        } else {
                            mma_f16(c, ah[f], bh + h2x * 2);
                        }
                    }
                }
            }
        }
    };

    // -------------------- main pipeline -------------------------------------
    LOAD(kb);
    STORE(0);
    __syncthreads();
    for (int i = 0; i < iters; i++) {
        if (i + 1 < iters) LOAD(kb + (i + 1) * BK);
        COMPUTE(i & 1);
        if (i + 1 < iters) {
            STORE((i + 1) & 1);
            __syncthreads();
        }
    }

    // -------------------- epilogue ------------------------------------------
    #pragma unroll
    for (int f = 0; f < MFRAG; f++) {
        #pragma unroll
        for (int j = 0; j < NFRAG; j++) {
            int r0  = m0 + mb + f * 16 + (lane >> 2);
            int col = n0 + nbw + j * 8 + (lane & 3) * 2;
            if (col >= Nb) continue;
            float2 v0 = make_float2(acc[f][j][0], acc[f][j][1]);
            float2 v1 = make_float2(acc[f][j][2], acc[f][j][3]);
            if (RELU) {
                v0.x = fmaxf(v0.x, 0.f); v0.y = fmaxf(v0.y, 0.f);
                v1.x = fmaxf(v1.x, 0.f); v1.y = fmaxf(v1.y, 0.f);
            }
            if (SPLITK) {
                if (r0 < M) {
                    atomicAdd(C + (size_t)r0 * ldc + col,     v0.x);
                    atomicAdd(C + (size_t)r0 * ldc + col + 1, v0.y);
                }
                if (r0 + 8 < M) {
                    atomicAdd(C + (size_t)(r0 + 8) * ldc + col,     v1.x);
                    atomicAdd(C + (size_t)(r0 + 8) * ldc + col + 1, v1.y);
                }
            } else {
                if (r0 < M)
                    *reinterpret_cast<float2*>(C + (size_t)r0 * ldc + col) = v0;
                if (r0 + 8 < M)
                    *reinterpret_cast<float2*>(C + (size_t)(r0 + 8) * ldc + col) = v1;
            }
        }
    }
}

// ============================================================================
// Small helper kernels for the conv3∘conv4 composition
// ============================================================================
__global__ __launch_bounds__(256)
void transpose_wo(const float* __restrict__ wo, float* __restrict__ woT)
{
    int id = blockIdx.x * 256 + threadIdx.x;
    if (id >= 162 * 1536) return;
    int row = id / 1536;        // o*9 + t1
    int m   = id - row * 1536;
    int o   = row / 9;
    int t1  = row - o * 9;
    woT[id] = wo[(size_t)o * 13824 + m * 9 + t1];
}

__global__ __launch_bounds__(256)
void build_wc(const float* __restrict__ G, float* __restrict__ Wc)
{
    int id = blockIdx.x * 256 + threadIdx.x;
    if (id >= 18 * 4800) return;
    int o   = id / 4800;
    int rem = id - o * 4800;
    int c   = rem / 25;
    int u   = rem - c * 25;
    int uy  = u / 5, ux = u - uy * 5;
    float s = 0.f;
    #pragma unroll
    for (int t1y = 0; t1y < 3; t1y++) {
        int t2y = uy - t1y;
        if ((unsigned)t2y >= 3u) continue;
        #pragma unroll
        for (int t1x = 0; t1x < 3; t1x++) {
            int t2x = ux - t1x;
            if ((unsigned)t2x >= 3u) continue;
            s += G[(size_t)(o * 9 + t1y * 3 + t1x) * 1728 + c * 9 + t2y * 3 + t2x];
        }
    }
    Wc[id] = s;
}

// Exact fp32 recomputation of the border ring (496 px). h2 is RAW -> relu here.
__global__ __launch_bounds__(192)
void border_fix(const float* __restrict__ h2, const float* __restrict__ G,
                float* __restrict__ off)
{
    int x = blockIdx.x, y = blockIdx.y;
    if (x >= 2 && x < 62 && y >= 2 && y < 62) return;
    int c = threadIdx.x;  // 0..191

    float acc[18];
    #pragma unroll
    for (int o = 0; o < 18; o++) acc[o] = 0.f;

    const float* h2c = h2 + (size_t)c * HW;
    for (int t1y = 0; t1y < 3; t1y++) {
        int qy = y + t1y - 1;
        if ((unsigned)qy >= 64u) continue;
        for (int t1x = 0; t1x < 3; t1x++) {
            int qx = x + t1x - 1;
            if ((unsigned)qx >= 64u) continue;
            int t1 = t1y * 3 + t1x;
            for (int t2y = 0; t2y < 3; t2y++) {
                int ry = qy + t2y - 1;
                if ((unsigned)ry >= 64u) continue;
                for (int t2x = 0; t2x < 3; t2x++) {
                    int rx = qx + t2x - 1;
                    if ((unsigned)rx >= 64u) continue;
                    float v = fmaxf(h2c[ry * 64 + rx], 0.f);
                    const float* g = G + (size_t)t1 * 1728 + c * 9 + t2y * 3 + t2x;
                    #pragma unroll
                    for (int o = 0; o < 18; o++)
                        acc[o] += g[(size_t)o * 9 * 1728] * v;
                }
            }
        }
    }

    __shared__ float red[18];
    if (threadIdx.x < 18) red[threadIdx.x] = 0.f;
    __syncthreads();
    #pragma unroll
    for (int o = 0; o < 18; o++) atomicAdd(&red[o], acc[o]);
    __syncthreads();
    if (threadIdx.x < 18)
        off[(size_t)threadIdx.x * HW + y * 64 + x] = red[threadIdx.x];
}

// ============================================================================
// Bilinear sampling -> fp16 S [6912][4096] (k-major)
// ============================================================================
__global__ __launch_bounds__(256)
void sample_kernel(const float* __restrict__ ref,
                   const float* __restrict__ off,
                   __half* __restrict__ sh)
{
    int k = blockIdx.y;                              // 0..6911
    int n = blockIdx.x * 256 + threadIdx.x;          // 0..4095
    int c = k / 9;
    int t = k - c * 9;
    int ti = t / 3;
    int tj = t - ti * 3;
    int y = n >> 6, x = n & 63;

    float dy = off[(2 * t)     * HW + n];
    float dx = off[(2 * t + 1) * HW + n];
    float py = (float)(y - 1 + ti) + dy;
    float px = (float)(x - 1 + tj) + dx;

    float y0f = floorf(py), x0f = floorf(px);
    float wy1 = py - y0f,  wx1 = px - x0f;
    float wy0 = 1.f - wy1, wx0 = 1.f - wx1;
    int y0 = (int)y0f, x0 = (int)x0f;

    const float* r = ref + (size_t)c * HW;
    float v = 0.f;
    if (((unsigned)y0 < 64u) && ((unsigned)x0 < 64u))
        v += wy0 * wx0 * r[y0 * 64 + x0];
    if (((unsigned)y0 < 64u) && ((unsigned)(x0 + 1) < 64u))
        v += wy0 * wx1 * r[y0 * 64 + x0 + 1];
    if (((unsigned)(y0 + 1) < 64u) && ((unsigned)x0 < 64u))
        v += wy1 * wx0 * r[(y0 + 1) * 64 + x0];
    if (((unsigned)(y0 + 1) < 64u) && ((unsigned)(x0 + 1) < 64u))
        v += wy1 * wx1 * r[(y0 + 1) * 64 + x0 + 1];

    sh[(size_t)k * HW + n] = __float2half(v);
}

// ============================================================================
extern "C" void kernel_launch(void* const* d_in, const int* in_sizes, int n_in,
                              void* d_out, int out_size)
{
    const float* x_in  = (const float*)d_in[0];
    const float* x_ref = (const float*)d_in[1];
    const float* w1    = (const float*)d_in[2];
    const float* w2    = (const float*)d_in[3];
    const float* w3    = (const float*)d_in[4];
    const float* wo    = (const float*)d_in[5];
    const float* wd    = (const float*)d_in[6];
    float* out = (float*)d_out;

    float *h1, *h2, *off, *woT, *G, *Wc;
    __half* sh;
    cudaGetSymbolAddress((void**)&h1,  g_h1);
    cudaGetSymbolAddress((void**)&h2,  g_h2);
    cudaGetSymbolAddress((void**)&off, g_off);
    cudaGetSymbolAddress((void**)&woT, g_woT);
    cudaGetSymbolAddress((void**)&G,   g_G);
    cudaGetSymbolAddress((void**)&Wc,  g_Wc);
    cudaGetSymbolAddress((void**)&sh,  g_sh);

    constexpr int SM64_BF  = 2 * (2 * (64 * A_STRIDE * 2) + 2 * (32 * B_STRIDE * 2)); // 55296
    constexpr int SM64_P2  = 2 * (2 * (64 * A_STRIDE * 2) + 1 * (32 * B_STRIDE * 2)); // 37888
    constexpr int SM32_BF  = 2 * (2 * (32 * A_STRIDE * 2) + 2 * (32 * B_STRIDE * 2)); // 45056
    constexpr int SM128_FP = 2 * (1 * (128 * A_STRIDE * 2) + 1 * (32 * B_STRIDE * 2)); // 37888

    cudaFuncSetAttribute(
        (const void*)gemm_mma<3, 0, false, false, false, 2, 4, 64, 2, false, 3>,
        cudaFuncAttributeMaxDynamicSharedMemorySize, SM64_BF);
    cudaFuncSetAttribute(
        (const void*)gemm_mma<0, 2, false, false, true, 2, 4, 64, 2, true, 3>,
        cudaFuncAttributeMaxDynamicSharedMemorySize, SM64_P2);
    cudaFuncSetAttribute(
        (const void*)gemm_mma<0, 0, false, true, false, 2, 4, 64, 2, true, 3>,
        cudaFuncAttributeMaxDynamicSharedMemorySize, SM64_BF);
    cudaFuncSetAttribute(
        (const void*)gemm_mma<0, 0, false, true, false, 1, 8, 32, 2, true, 5>,
        cudaFuncAttributeMaxDynamicSharedMemorySize, SM32_BF);
    cudaFuncSetAttribute(
        (const void*)gemm_mma<1, 1, false, false, false, 4, 2, 128, 2, false, 3>,
        cudaFuncAttributeMaxDynamicSharedMemorySize, SM128_FP);

    // zero split-K accumulators
    cudaMemsetAsync(h1,  0, (size_t)192 * HW * 4);
    cudaMemsetAsync(h2,  0, (size_t)192 * HW * 4);
    cudaMemsetAsync(off, 0, (size_t)18  * HW * 4);

    // --- weight composition (conv3 ∘ conv4) ---
    transpose_wo<<<(162 * 1536 + 255) / 256, 256>>>(wo, woT);
    gemm_mma<3, 0, false, false, false, 2, 4, 64, 2, false, 3>
        <<<dim3(14, 3), 256, SM64_BF>>>(
        woT, w3, nullptr, nullptr, G, 162, 1536, 1536, 1728, 1728);
    build_wc<<<(18 * 4800 + 255) / 256, 256>>>(G, Wc);

    // conv1: 1536 -> 192, fp16 2-pass, concat loader, SPLIT-K x3, raw out
    gemm_mma<0, 2, false, false, true, 2, 4, 64, 2, true, 3>
        <<<dim3(32, 3, 3), 256, SM64_P2>>>(
        w1, x_in, x_ref, nullptr, h1, 192, 13824, 4608, HW, HW);

    // conv2: 192 -> 192, bf16 3-pass, relu(h1) loader, SPLIT-K x3, raw out
    gemm_mma<0, 0, false, true, false, 2, 4, 64, 2, true, 3>
        <<<dim3(32, 3, 3), 256, SM64_BF>>>(
        w2, h1, nullptr, nullptr, h2, 192, 1728, 576, HW, HW);

    // offsets: composed 5x5 conv (interior), relu(h2) loader, SPLIT-K x10
    gemm_mma<0, 0, false, true, false, 1, 8, 32, 2, true, 5>
        <<<dim3(32, 1, 10), 256, SM32_BF>>>(
        Wc, h2, nullptr, nullptr, off, 18, 4800, 480, HW, HW);
    // exact border ring (relu applied inside)
    border_fix<<<dim3(64, 64), 192>>>(h2, G, off);

    // bilinear sampling -> fp16 S
    sample_kernel<<<dim3(16, 6912), 256>>>(x_ref, off, sh);

    // deform GEMM: out[768][4096] = wd[768][6912] @ S  (fp16 1-pass, BM=128)
    gemm_mma<1, 1, false, false, false, 4, 2, 128, 2, false, 3>
        <<<dim3(32, 6), 256, SM128_FP>>>(
        wd, nullptr, nullptr, sh, out, 768, 6912, 6912, HW, HW);
}

// round 14
// speedup vs baseline: 4.5836x; 1.0557x over previous
#include <cuda_runtime.h>
#include <cuda_bf16.h>
#include <cuda_fp16.h>

// ============================================================================
// DeformableConvBlock, round 10.
//   im2col precompute (fp16, coalesced): B1h=concat/3x3, B2h=relu(h1)/3x3,
//                                        B3h=relu(h2)/5x5
//   conv1: fp16 2-pass GEMM (A=w1 hi/lo) @ B1h        SPLIT-K x3
//   conv2: fp16 2-pass GEMM (A=w2 hi/lo) @ B2h        SPLIT-K x3, raw out
//   offsets: composed conv3∘conv4 weights (bf16 3-pass G-GEMM) ->
//            fp16 2-pass GEMM @ B3h SPLIT-K x10 + fp32 border ring
//   sampling: bilinear -> S fp16 [6912][4096]
//   deform: fp16 1-pass GEMM out = wd @ S, BM=128, SPLIT-K x2 (atomics)
// ============================================================================

#define HW 4096

// ---------------- device scratch --------------------------------------------
__device__ float g_h1 [192  * HW];
__device__ float g_h2 [192  * HW];   // RAW (pre-ReLU) conv2 output
__device__ float g_off[18   * HW];
__device__ float g_woT[162 * 1536];
__device__ float g_G  [162 * 1728];
__device__ float g_Wc [18 * 4800];
__device__ __half g_sh[(size_t)6912 * HW];
__device__ __half g_b1[(size_t)13824 * HW];
__device__ __half g_b2[(size_t)1728  * HW];
__device__ __half g_b3[(size_t)4800  * HW];

// ---------------- smem geometry ---------------------------------------------
#define A_STRIDE 40     // elems per A row (32 data + 8 pad)
#define B_STRIDE 136    // elems per B row (128 data + 8 pad)

// ---------------- PTX helpers ------------------------------------------------
__device__ __forceinline__ unsigned smem_to_u32(const void* p) {
    unsigned a;
    asm("{ .reg .u64 t; cvta.to.shared.u64 t, %1; cvt.u32.u64 %0, t; }"
        : "=r"(a) : "l"(p));
    return a;
}
__device__ __forceinline__ void ldsm_x4(unsigned* r, unsigned addr) {
    asm volatile("ldmatrix.sync.aligned.m8n8.x4.shared.b16 {%0,%1,%2,%3}, [%4];"
                 : "=r"(r[0]), "=r"(r[1]), "=r"(r[2]), "=r"(r[3]) : "r"(addr));
}
__device__ __forceinline__ void ldsm_x4_t(unsigned* r, unsigned addr) {
    asm volatile("ldmatrix.sync.aligned.m8n8.x4.trans.shared.b16 {%0,%1,%2,%3}, [%4];"
                 : "=r"(r[0]), "=r"(r[1]), "=r"(r[2]), "=r"(r[3]) : "r"(addr));
}
__device__ __forceinline__ void mma_bf16(float* c, const unsigned* a, const unsigned* b) {
    asm volatile(
        "mma.sync.aligned.m16n8k16.row.col.f32.bf16.bf16.f32 "
        "{%0,%1,%2,%3}, {%4,%5,%6,%7}, {%8,%9}, {%0,%1,%2,%3};"
        : "+f"(c[0]), "+f"(c[1]), "+f"(c[2]), "+f"(c[3])
        : "r"(a[0]), "r"(a[1]), "r"(a[2]), "r"(a[3]), "r"(b[0]), "r"(b[1]));
}
__device__ __forceinline__ void mma_f16(float* c, const unsigned* a, const unsigned* b) {
    asm volatile(
        "mma.sync.aligned.m16n8k16.row.col.f32.f16.f16.f32 "
        "{%0,%1,%2,%3}, {%4,%5,%6,%7}, {%8,%9}, {%0,%1,%2,%3};"
        : "+f"(c[0]), "+f"(c[1]), "+f"(c[2]), "+f"(c[3])
        : "r"(a[0]), "r"(a[1]), "r"(a[2]), "r"(a[3]), "r"(b[0]), "r"(b[1]));
}
#define STS128A(addr, r0, r1, r2, r3) \
    asm volatile("st.shared.v4.b32 [%0], {%1, %2, %3, %4};" \
                 :: "r"((unsigned)(addr)), "r"(r0), "r"(r1), "r"(r2), "r"(r3) : "memory")
#define STS64A(addr, r0, r1) \
    asm volatile("st.shared.v2.b32 [%0], {%1, %2};" \
                 :: "r"((unsigned)(addr)), "r"(r0), "r"(r1) : "memory")

// bf16 hi/lo split (pair -> packed)
__device__ __forceinline__ void split2(float a, float b, unsigned& h, unsigned& l) {
    __nv_bfloat16 ha = __float2bfloat16(a);
    __nv_bfloat16 hb = __float2bfloat16(b);
    __nv_bfloat16 la = __float2bfloat16(a - __bfloat162float(ha));
    __nv_bfloat16 lb = __float2bfloat16(b - __bfloat162float(hb));
    __nv_bfloat162 hp = __halves2bfloat162(ha, hb);
    __nv_bfloat162 lp = __halves2bfloat162(la, lb);
    h = *reinterpret_cast<unsigned*>(&hp);
    l = *reinterpret_cast<unsigned*>(&lp);
}
// fp16 hi/lo split (pair -> packed)
__device__ __forceinline__ void splith2(float a, float b, unsigned& h, unsigned& l) {
    __half ha = __float2half(a);
    __half hb = __float2half(b);
    __half la = __float2half(a - __half2float(ha));
    __half lb = __float2half(b - __half2float(hb));
    __half2 hp = __halves2half2(ha, hb);
    __half2 lp = __halves2half2(la, lb);
    h = *reinterpret_cast<unsigned*>(&hp);
    l = *reinterpret_cast<unsigned*>(&lp);
}
__device__ __forceinline__ unsigned packh2(float a, float b) {
    __half2 p = __floats2half2_rn(a, b);
    return *reinterpret_cast<unsigned*>(&p);
}

// ============================================================================
// im2col precompute: dst[k][4096] fp16, k = c*TS*TS + ti*TS + tj, pad=TS/2.
// CONCAT_: c>=768 reads src2. RELU_: fmaxf(v,0). 2 elems/thread (half2 store).
// grid (8, K), block 256.
// ============================================================================
template<int TS, bool RELU_, bool CONCAT_>
__global__ __launch_bounds__(256)
void im2col_half(const float* __restrict__ src, const float* __restrict__ src2,
                 __half* __restrict__ dst)
{
    constexpr int TAPS = TS * TS;
    constexpr int PD   = TS / 2;
    int k  = blockIdx.y;
    int n  = blockIdx.x * 512 + threadIdx.x * 2;
    int c  = k / TAPS;
    int tap = k - c * TAPS;
    int ti = tap / TS;
    int tj = tap - ti * TS;
    const float* base;
    if (CONCAT_ && c >= 768) base = src2 + (size_t)(c - 768) * HW;
    else                     base = src + (size_t)c * HW;

    float v[2];
    #pragma unroll
    for (int j = 0; j < 2; j++) {
        int nn = n + j;
        int y = nn >> 6, x = nn & 63;
        int py = y + ti - PD;
        int px = x + tj - PD;
        float t = 0.f;
        if (((unsigned)py < 64u) && ((unsigned)px < 64u))
            t = __ldg(base + py * 64 + px);
        if (RELU_) t = fmaxf(t, 0.f);
        v[j] = t;
    }
    *reinterpret_cast<__half2*>(dst + (size_t)k * HW + n) =
        __floats2half2_rn(v[0], v[1]);
}

// ============================================================================
// GEMM kernel. 256 threads (8 warps = WARP_M x WARP_N). BN=128, BK=32.
// MODE 1: B = fp16 [Kfull][4096] (vectorized loads).
// MODE 3: B = fp32 row-major [Kfull][Nb].
// PREC 0: bf16 hi/lo 3-pass.  PREC 1: fp16 1-pass.  PREC 2: fp16 A-hi/lo 2-pass.
// SPLITK: blockIdx.z = K-split (kb = z*kcnt), atomicAdd epilogue.
// ============================================================================
template<int MODE, int PREC, bool RELU,
         int WARP_M, int WARP_N, int BM, int MINB, bool SPLITK>
__global__ __launch_bounds__(256, MINB)
void gemm_mma(const float* __restrict__ A,
              const float* __restrict__ srcF,
              const __half* __restrict__ bh16,
              float* __restrict__ C, int M, int Kfull, int kcnt,
              int Nb, int ldc)
{
    constexpr int BN = 128, BK = 32;
    constexpr int MFRAG = BM / (WARP_M * 16);
    constexpr int NFRAG = BN / (WARP_N * 8);
    constexpr int A_ELEMS = (BM == 128) ? 16 : (BM == 64 ? 8 : 4);
    constexpr int NS_A = (PREC == 1) ? 1 : 2;
    constexpr int NS_B = (PREC == 0) ? 2 : 1;
    constexpr int ASZ = BM * A_STRIDE * 2;
    constexpr int BSZ = 32 * B_STRIDE * 2;
    auto OFF_A = [](int buf, int s) { return (buf * NS_A + s) * ASZ; };
    auto OFF_B = [](int buf, int s) { return 2 * NS_A * ASZ + (buf * NS_B + s) * BSZ; };

    extern __shared__ char smem[];
    const unsigned sb = smem_to_u32(smem);
    const int tid  = threadIdx.x;
    const int wid  = tid >> 5;
    const int lane = tid & 31;
    const int n0 = blockIdx.x * BN;
    const int m0 = blockIdx.y * BM;
    const int kb = SPLITK ? blockIdx.z * kcnt : 0;

    const int kloc = tid >> 3;          // B-loader row within tile
    const int nbb  = (tid & 7) * 16;    // B-loader col base

    float a_st[A_ELEMS];
    float b_st[16];
    uint4 b_raw[2];

    float acc[MFRAG][NFRAG][4];
    #pragma unroll
    for (int f = 0; f < MFRAG; f++)
        #pragma unroll
        for (int g = 0; g < NFRAG; g++)
            #pragma unroll
            for (int q = 0; q < 4; q++) acc[f][g][q] = 0.f;

    const int iters = kcnt / BK;

    // -------------------- tile load (global -> regs) ------------------------
    auto LOAD = [&](int k0g) {
        // ---- A ----
        if constexpr (BM == 128) {
            int m  = tid >> 1;
            int kh = (tid & 1) * 16;
            int gm = m0 + m;
            const float4* p =
                reinterpret_cast<const float4*>(A + (size_t)gm * Kfull + k0g + kh);
            #pragma unroll
            for (int q = 0; q < 4; q++) {
                float4 v = (gm < M) ? p[q] : make_float4(0.f, 0.f, 0.f, 0.f);
                a_st[q * 4 + 0] = v.x; a_st[q * 4 + 1] = v.y;
                a_st[q * 4 + 2] = v.z; a_st[q * 4 + 3] = v.w;
            }
        } else if constexpr (BM == 64) {
            int m  = tid >> 2;
            int kh = (tid & 3) * 8;
            int gm = m0 + m;
            const float4* p =
                reinterpret_cast<const float4*>(A + (size_t)gm * Kfull + k0g + kh);
            #pragma unroll
            for (int q = 0; q < 2; q++) {
                float4 v = (gm < M) ? p[q] : make_float4(0.f, 0.f, 0.f, 0.f);
                a_st[q * 4 + 0] = v.x; a_st[q * 4 + 1] = v.y;
                a_st[q * 4 + 2] = v.z; a_st[q * 4 + 3] = v.w;
            }
        } else {  // BM == 32
            int m  = tid >> 3;
            int kq = (tid & 7) * 4;
            int gm = m0 + m;
            float4 v = (gm < M)
                ? *reinterpret_cast<const float4*>(A + (size_t)gm * Kfull + k0g + kq)
                : make_float4(0.f, 0.f, 0.f, 0.f);
            a_st[0] = v.x; a_st[1] = v.y; a_st[2] = v.z; a_st[3] = v.w;
        }
        // ---- B ----
        if constexpr (MODE == 1) {
            const uint4* p = reinterpret_cast<const uint4*>(
                bh16 + (size_t)(k0g + kloc) * HW + n0 + nbb);
            b_raw[0] = p[0];
            b_raw[1] = p[1];
        } else {  // MODE 3
            const float* src = srcF + (size_t)(k0g + kloc) * Nb;
            #pragma unroll
            for (int j = 0; j < 16; j++) {
                int n = n0 + nbb + j;
                b_st[j] = (n < Nb) ? __ldg(src + n) : 0.f;
            }
        }
    };

    // -------------------- tile store (regs -> smem) -------------------------
    auto STORE_A_PAIRS = [&](int buf, unsigned base, const float* src, int npairs) {
        if constexpr (PREC == 0) {
            unsigned h[8], l[8];
            for (int q = 0; q < npairs; q++)
                split2(src[2 * q], src[2 * q + 1], h[q], l[q]);
            for (int q4 = 0; q4 < npairs / 4; q4++) {
                STS128A(sb + OFF_A(buf, 0) + base + q4 * 16,
                        h[q4 * 4], h[q4 * 4 + 1], h[q4 * 4 + 2], h[q4 * 4 + 3]);
                STS128A(sb + OFF_A(buf, 1) + base + q4 * 16,
                        l[q4 * 4], l[q4 * 4 + 1], l[q4 * 4 + 2], l[q4 * 4 + 3]);
            }
            if (npairs == 2) {
                STS64A(sb + OFF_A(buf, 0) + base, h[0], h[1]);
                STS64A(sb + OFF_A(buf, 1) + base, l[0], l[1]);
            }
        } else if constexpr (PREC == 2) {
            unsigned h[8], l[8];
            for (int q = 0; q < npairs; q++)
                splith2(src[2 * q], src[2 * q + 1], h[q], l[q]);
            for (int q4 = 0; q4 < npairs / 4; q4++) {
                STS128A(sb + OFF_A(buf, 0) + base + q4 * 16,
                        h[q4 * 4], h[q4 * 4 + 1], h[q4 * 4 + 2], h[q4 * 4 + 3]);
                STS128A(sb + OFF_A(buf, 1) + base + q4 * 16,
                        l[q4 * 4], l[q4 * 4 + 1], l[q4 * 4 + 2], l[q4 * 4 + 3]);
            }
            if (npairs == 2) {
                STS64A(sb + OFF_A(buf, 0) + base, h[0], h[1]);
                STS64A(sb + OFF_A(buf, 1) + base, l[0], l[1]);
            }
        } else {
            unsigned h[8];
            for (int q = 0; q < npairs; q++)
                h[q] = packh2(src[2 * q], src[2 * q + 1]);
            for (int q4 = 0; q4 < npairs / 4; q4++)
                STS128A(sb + OFF_A(buf, 0) + base + q4 * 16,
                        h[q4 * 4], h[q4 * 4 + 1], h[q4 * 4 + 2], h[q4 * 4 + 3]);
            if (npairs == 2)
                STS64A(sb + OFF_A(buf, 0) + base, h[0], h[1]);
        }
    };

    auto STORE = [&](int buf) {
        // ---- A ----
        if constexpr (BM == 128) {
            int m  = tid >> 1;
            int kh = (tid & 1) * 16;
            STORE_A_PAIRS(buf, (unsigned)(m * A_STRIDE + kh) * 2, a_st, 8);
        } else if constexpr (BM == 64) {
            int m  = tid >> 2;
            int kh = (tid & 3) * 8;
            STORE_A_PAIRS(buf, (unsigned)(m * A_STRIDE + kh) * 2, a_st, 4);
        } else {
            int m  = tid >> 3;
            int kq = (tid & 7) * 4;
            STORE_A_PAIRS(buf, (unsigned)(m * A_STRIDE + kq) * 2, a_st, 2);
        }
        // ---- B ----
        unsigned base = (unsigned)(kloc * B_STRIDE + nbb) * 2;
        if constexpr (MODE == 1) {
            STS128A(sb + OFF_B(buf, 0) + base,
                    b_raw[0].x, b_raw[0].y, b_raw[0].z, b_raw[0].w);
            STS128A(sb + OFF_B(buf, 0) + base + 16,
                    b_raw[1].x, b_raw[1].y, b_raw[1].z, b_raw[1].w);
        } else if constexpr (PREC == 0) {
            unsigned h[8], l[8];
            #pragma unroll
            for (int q = 0; q < 8; q++)
                split2(b_st[2 * q], b_st[2 * q + 1], h[q], l[q]);
            STS128A(sb + OFF_B(buf, 0) + base,      h[0], h[1], h[2], h[3]);
            STS128A(sb + OFF_B(buf, 0) + base + 16, h[4], h[5], h[6], h[7]);
            STS128A(sb + OFF_B(buf, 1) + base,      l[0], l[1], l[2], l[3]);
            STS128A(sb + OFF_B(buf, 1) + base + 16, l[4], l[5], l[6], l[7]);
        } else {
            unsigned h[8];
            #pragma unroll
            for (int q = 0; q < 8; q++)
                h[q] = packh2(b_st[2 * q], b_st[2 * q + 1]);
            STS128A(sb + OFF_B(buf, 0) + base,      h[0], h[1], h[2], h[3]);
            STS128A(sb + OFF_B(buf, 0) + base + 16, h[4], h[5], h[6], h[7]);
        }
    };

    // -------------------- compute -------------------------------------------
    const int wm  = wid % WARP_M;
    const int wn  = wid / WARP_M;
    const int mb  = wm * MFRAG * 16;
    const int nbw = wn * NFRAG * 8;

    auto COMPUTE = [&](int buf) {
        #pragma unroll
        for (int ks = 0; ks < BK; ks += 16) {
            unsigned ah[MFRAG][4], al[MFRAG][4];
            {
                int arow = mb + (lane & 15);
                int acol = ks + (lane >> 4) * 8;
                #pragma unroll
                for (int f = 0; f < MFRAG; f++) {
                    unsigned off = (unsigned)((arow + f * 16) * A_STRIDE + acol) * 2;
                    ldsm_x4(ah[f], sb + OFF_A(buf, 0) + off);
                    if constexpr (NS_A == 2)
                        ldsm_x4(al[f], sb + OFF_A(buf, 1) + off);
                }
            }
            #pragma unroll
            for (int g = 0; g < NFRAG / 2; g++) {
                unsigned bh[4], bl[4];
                int brow = ks + (lane & 15);
                int bcol = nbw + g * 16 + (lane >> 4) * 8;
                unsigned off = (unsigned)(brow * B_STRIDE + bcol) * 2;
                ldsm_x4_t(bh, sb + OFF_B(buf, 0) + off);
                if constexpr (NS_B == 2)
                    ldsm_x4_t(bl, sb + OFF_B(buf, 1) + off);
                #pragma unroll
                for (int f = 0; f < MFRAG; f++) {
                    #pragma unroll
                    for (int h2x = 0; h2x < 2; h2x++) {
                        float* c = acc[f][g * 2 + h2x];
                        if constexpr (PREC == 0) {
                            mma_bf16(c, ah[f], bh + h2x * 2);
                            mma_bf16(c, ah[f], bl + h2x * 2);
                            mma_bf16(c, al[f], bh + h2x * 2);
                        } else if constexpr (PREC == 2) {
                            mma_f16(c, ah[f], bh + h2x * 2);
                            mma_f16(c, al[f], bh + h2x * 2);
                        } else {
                            mma_f16(c, ah[f], bh + h2x * 2);
                        }
                    }
                }
            }
        }
    };

    // -------------------- main pipeline -------------------------------------
    LOAD(kb);
    STORE(0);
    __syncthreads();
    for (int i = 0; i < iters; i++) {
        if (i + 1 < iters) LOAD(kb + (i + 1) * BK);
        COMPUTE(i & 1);
        if (i + 1 < iters) {
            STORE((i + 1) & 1);
            __syncthreads();
        }
    }

    // -------------------- epilogue ------------------------------------------
    #pragma unroll
    for (int f = 0; f < MFRAG; f++) {
        #pragma unroll
        for (int j = 0; j < NFRAG; j++) {
            int r0  = m0 + mb + f * 16 + (lane >> 2);
            int col = n0 + nbw + j * 8 + (lane & 3) * 2;
            if (col >= Nb) continue;
            float2 v0 = make_float2(acc[f][j][0], acc[f][j][1]);
            float2 v1 = make_float2(acc[f][j][2], acc[f][j][3]);
            if (RELU) {
                v0.x = fmaxf(v0.x, 0.f); v0.y = fmaxf(v0.y, 0.f);
                v1.x = fmaxf(v1.x, 0.f); v1.y = fmaxf(v1.y, 0.f);
            }
            if (SPLITK) {
                if (r0 < M) {
                    atomicAdd(C + (size_t)r0 * ldc + col,     v0.x);
                    atomicAdd(C + (size_t)r0 * ldc + col + 1, v0.y);
                }
                if (r0 + 8 < M) {
                    atomicAdd(C + (size_t)(r0 + 8) * ldc + col,     v1.x);
                    atomicAdd(C + (size_t)(r0 + 8) * ldc + col + 1, v1.y);
                }
            } else {
                if (r0 < M)
                    *reinterpret_cast<float2*>(C + (size_t)r0 * ldc + col) = v0;
                if (r0 + 8 < M)
                    *reinterpret_cast<float2*>(C + (size_t)(r0 + 8) * ldc + col) = v1;
            }
        }
    }
}

// ============================================================================
// Small helper kernels for the conv3∘conv4 composition
// ============================================================================
__global__ __launch_bounds__(256)
void transpose_wo(const float* __restrict__ wo, float* __restrict__ woT)
{
    int id = blockIdx.x * 256 + threadIdx.x;
    if (id >= 162 * 1536) return;
    int row = id / 1536;        // o*9 + t1
    int m   = id - row * 1536;
    int o   = row / 9;
    int t1  = row - o * 9;
    woT[id] = wo[(size_t)o * 13824 + m * 9 + t1];
}

__global__ __launch_bounds__(256)
void build_wc(const float* __restrict__ G, float* __restrict__ Wc)
{
    int id = blockIdx.x * 256 + threadIdx.x;
    if (id >= 18 * 4800) return;
    int o   = id / 4800;
    int rem = id - o * 4800;
    int c   = rem / 25;
    int u   = rem - c * 25;
    int uy  = u / 5, ux = u - uy * 5;
    float s = 0.f;
    #pragma unroll
    for (int t1y = 0; t1y < 3; t1y++) {
        int t2y = uy - t1y;
        if ((unsigned)t2y >= 3u) continue;
        #pragma unroll
        for (int t1x = 0; t1x < 3; t1x++) {
            int t2x = ux - t1x;
            if ((unsigned)t2x >= 3u) continue;
            s += G[(size_t)(o * 9 + t1y * 3 + t1x) * 1728 + c * 9 + t2y * 3 + t2x];
        }
    }
    Wc[id] = s;
}

// Exact fp32 recomputation of the border ring (496 px). h2 is RAW -> relu here.
__global__ __launch_bounds__(192)
void border_fix(const float* __restrict__ h2, const float* __restrict__ G,
                float* __restrict__ off)
{
    int x = blockIdx.x, y = blockIdx.y;
    if (x >= 2 && x < 62 && y >= 2 && y < 62) return;
    int c = threadIdx.x;  // 0..191

    float acc[18];
    #pragma unroll
    for (int o = 0; o < 18; o++) acc[o] = 0.f;

    const float* h2c = h2 + (size_t)c * HW;
    for (int t1y = 0; t1y < 3; t1y++) {
        int qy = y + t1y - 1;
        if ((unsigned)qy >= 64u) continue;
        for (int t1x = 0; t1x < 3; t1x++) {
            int qx = x + t1x - 1;
            if ((unsigned)qx >= 64u) continue;
            int t1 = t1y * 3 + t1x;
            for (int t2y = 0; t2y < 3; t2y++) {
                int ry = qy + t2y - 1;
                if ((unsigned)ry >= 64u) continue;
                for (int t2x = 0; t2x < 3; t2x++) {
                    int rx = qx + t2x - 1;
                    if ((unsigned)rx >= 64u) continue;
                    float v = fmaxf(h2c[ry * 64 + rx], 0.f);
                    const float* g = G + (size_t)t1 * 1728 + c * 9 + t2y * 3 + t2x;
                    #pragma unroll
                    for (int o = 0; o < 18; o++)
                        acc[o] += g[(size_t)o * 9 * 1728] * v;
                }
            }
        }
    }

    __shared__ float red[18];
    if (threadIdx.x < 18) red[threadIdx.x] = 0.f;
    __syncthreads();
    #pragma unroll
    for (int o = 0; o < 18; o++) atomicAdd(&red[o], acc[o]);
    __syncthreads();
    if (threadIdx.x < 18)
        off[(size_t)threadIdx.x * HW + y * 64 + x] = red[threadIdx.x];
}

// ============================================================================
// Bilinear sampling -> fp16 S [6912][4096] (k-major)
// ============================================================================
__global__ __launch_bounds__(256)
void sample_kernel(const float* __restrict__ ref,
                   const float* __restrict__ off,
                   __half* __restrict__ sh)
{
    int k = blockIdx.y;                              // 0..6911
    int n = blockIdx.x * 256 + threadIdx.x;          // 0..4095
    int c = k / 9;
    int t = k - c * 9;
    int ti = t / 3;
    int tj = t - ti * 3;
    int y = n >> 6, x = n & 63;

    float dy = off[(2 * t)     * HW + n];
    float dx = off[(2 * t + 1) * HW + n];
    float py = (float)(y - 1 + ti) + dy;
    float px = (float)(x - 1 + tj) + dx;

    float y0f = floorf(py), x0f = floorf(px);
    float wy1 = py - y0f,  wx1 = px - x0f;
    float wy0 = 1.f - wy1, wx0 = 1.f - wx1;
    int y0 = (int)y0f, x0 = (int)x0f;

    const float* r = ref + (size_t)c * HW;
    float v = 0.f;
    if (((unsigned)y0 < 64u) && ((unsigned)x0 < 64u))
        v += wy0 * wx0 * r[y0 * 64 + x0];
    if (((unsigned)y0 < 64u) && ((unsigned)(x0 + 1) < 64u))
        v += wy0 * wx1 * r[y0 * 64 + x0 + 1];
    if (((unsigned)(y0 + 1) < 64u) && ((unsigned)x0 < 64u))
        v += wy1 * wx0 * r[(y0 + 1) * 64 + x0];
    if (((unsigned)(y0 + 1) < 64u) && ((unsigned)(x0 + 1) < 64u))
        v += wy1 * wx1 * r[(y0 + 1) * 64 + x0 + 1];

    sh[(size_t)k * HW + n] = __float2half(v);
}

// ============================================================================
extern "C" void kernel_launch(void* const* d_in, const int* in_sizes, int n_in,
                              void* d_out, int out_size)
{
    const float* x_in  = (const float*)d_in[0];
    const float* x_ref = (const float*)d_in[1];
    const float* w1    = (const float*)d_in[2];
    const float* w2    = (const float*)d_in[3];
    const float* w3    = (const float*)d_in[4];
    const float* wo    = (const float*)d_in[5];
    const float* wd    = (const float*)d_in[6];
    float* out = (float*)d_out;

    float *h1, *h2, *off, *woT, *G, *Wc;
    __half *sh, *b1, *b2, *b3;
    cudaGetSymbolAddress((void**)&h1,  g_h1);
    cudaGetSymbolAddress((void**)&h2,  g_h2);
    cudaGetSymbolAddress((void**)&off, g_off);
    cudaGetSymbolAddress((void**)&woT, g_woT);
    cudaGetSymbolAddress((void**)&G,   g_G);
    cudaGetSymbolAddress((void**)&Wc,  g_Wc);
    cudaGetSymbolAddress((void**)&sh,  g_sh);
    cudaGetSymbolAddress((void**)&b1,  g_b1);
    cudaGetSymbolAddress((void**)&b2,  g_b2);
    cudaGetSymbolAddress((void**)&b3,  g_b3);

    constexpr int SM64_BF  = 2 * (2 * (64 * A_STRIDE * 2) + 2 * (32 * B_STRIDE * 2)); // 55296
    constexpr int SM64_P2  = 2 * (2 * (64 * A_STRIDE * 2) + 1 * (32 * B_STRIDE * 2)); // 37888
    constexpr int SM32_P2  = 2 * (2 * (32 * A_STRIDE * 2) + 1 * (32 * B_STRIDE * 2)); // 27648
    constexpr int SM128_FP = 2 * (1 * (128 * A_STRIDE * 2) + 1 * (32 * B_STRIDE * 2)); // 37888

    cudaFuncSetAttribute(
        (const void*)gemm_mma<3, 0, false, 2, 4, 64, 2, false>,
        cudaFuncAttributeMaxDynamicSharedMemorySize, SM64_BF);
    cudaFuncSetAttribute(
        (const void*)gemm_mma<1, 2, false, 2, 4, 64, 2, true>,
        cudaFuncAttributeMaxDynamicSharedMemorySize, SM64_P2);
    cudaFuncSetAttribute(
        (const void*)gemm_mma<1, 2, false, 1, 8, 32, 2, true>,
        cudaFuncAttributeMaxDynamicSharedMemorySize, SM32_P2);
    cudaFuncSetAttribute(
        (const void*)gemm_mma<1, 1, false, 4, 2, 128, 2, true>,
        cudaFuncAttributeMaxDynamicSharedMemorySize, SM128_FP);

    // zero split-K accumulators (d_out is poisoned -> must zero for atomics)
    cudaMemsetAsync(h1,  0, (size_t)192 * HW * 4);
    cudaMemsetAsync(h2,  0, (size_t)192 * HW * 4);
    cudaMemsetAsync(off, 0, (size_t)18  * HW * 4);
    cudaMemsetAsync(out, 0, (size_t)768 * HW * 4);

    // --- weight composition (conv3 ∘ conv4) ---
    transpose_wo<<<(162 * 1536 + 255) / 256, 256>>>(wo, woT);
    gemm_mma<3, 0, false, 2, 4, 64, 2, false><<<dim3(14, 3), 256, SM64_BF>>>(
        woT, w3, nullptr, G, 162, 1536, 1536, 1728, 1728);
    build_wc<<<(18 * 4800 + 255) / 256, 256>>>(G, Wc);

    // --- im2col precompute #1 (concat, 3x3) + conv1 ---
    im2col_half<3, false, true><<<dim3(8, 13824), 256>>>(x_in, x_ref, b1);
    gemm_mma<1, 2, false, 2, 4, 64, 2, true><<<dim3(32, 3, 3), 256, SM64_P2>>>(
        w1, nullptr, b1, h1, 192, 13824, 4608, HW, HW);

    // --- im2col precompute #2 (relu(h1), 3x3) + conv2 ---
    im2col_half<3, true, false><<<dim3(8, 1728), 256>>>(h1, nullptr, b2);
    gemm_mma<1, 2, false, 2, 4, 64, 2, true><<<dim3(32, 3, 3), 256, SM64_P2>>>(
        w2, nullptr, b2, h2, 192, 1728, 576, HW, HW);

    // --- im2col precompute #3 (relu(h2), 5x5) + composed offsets ---
    im2col_half<5, true, false><<<dim3(8, 4800), 256>>>(h2, nullptr, b3);
    gemm_mma<1, 2, false, 1, 8, 32, 2, true><<<dim3(32, 1, 10), 256, SM32_P2>>>(
        Wc, nullptr, b3, off, 18, 4800, 480, HW, HW);
    // exact border ring (relu applied inside)
    border_fix<<<dim3(64, 64), 192>>>(h2, G, off);

    // bilinear sampling -> fp16 S
    sample_kernel<<<dim3(16, 6912), 256>>>(x_ref, off, sh);

    // deform GEMM: out = wd @ S  (fp16 1-pass, BM=128, SPLIT-K x2, atomics)
    gemm_mma<1, 1, false, 4, 2, 128, 2, true><<<dim3(32, 6, 2), 256, SM128_FP>>>(
        wd, nullptr, sh, out, 768, 6912, 3456, HW, HW);
}

// round 15
// speedup vs baseline: 5.3435x; 1.1658x over previous
#include <cuda_runtime.h>
#include <cuda_bf16.h>
#include <cuda_fp16.h>

// ============================================================================
// DeformableConvBlock, round 15.
//   shifted-image precompute (fp16, aligned): x1=concat/3sh, x2=relu(h1)/3sh,
//                                             x3=relu(h2)/5sh  (y-padded)
//   conv1: fp16 2-pass GEMM (A=w1 hi/lo) @ shifted-imgs   SPLIT-K x3
//   conv2: fp16 2-pass GEMM                               SPLIT-K x3
//   offsets: composed conv3∘conv4 -> 5x5 GEMM SPLIT-K x10 + fp32 border ring
//   sampling: bilinear -> S fp16 [6912][4096]
//   deform: fp16 1-pass GEMM (A=wd pre-converted fp16), BM=128, SPLIT-K x3
// ============================================================================

#define HW 4096

// ---------------- device scratch --------------------------------------------
__device__ float g_h1 [192  * HW];
__device__ float g_h2 [192  * HW];   // RAW (pre-ReLU) conv2 output
__device__ float g_off[18   * HW];
__device__ float g_woT[162 * 1536];
__device__ float g_G  [162 * 1728];
__device__ float g_Wc [18 * 4800];
__device__ __half g_sh[(size_t)6912 * HW];
__device__ __half g_x1[(size_t)3 * 1536 * 4224];  // 3 x-shifts, y-pad 1 row
__device__ __half g_x2[(size_t)3 * 192  * 4224];
__device__ __half g_x3[(size_t)5 * 192  * 4352];  // 5 x-shifts, y-pad 2 rows
__device__ __half g_wdh[(size_t)768 * 6912];

// ---------------- smem geometry ---------------------------------------------
#define A_STRIDE 40     // elems per A row (32 data + 8 pad)
#define B_STRIDE 136    // elems per B row (128 data + 8 pad)

// ---------------- PTX helpers ------------------------------------------------
__device__ __forceinline__ unsigned smem_to_u32(const void* p) {
    unsigned a;
    asm("{ .reg .u64 t; cvta.to.shared.u64 t, %1; cvt.u32.u64 %0, t; }"
        : "=r"(a) : "l"(p));
    return a;
}
__device__ __forceinline__ void ldsm_x4(unsigned* r, unsigned addr) {
    asm volatile("ldmatrix.sync.aligned.m8n8.x4.shared.b16 {%0,%1,%2,%3}, [%4];"
                 : "=r"(r[0]), "=r"(r[1]), "=r"(r[2]), "=r"(r[3]) : "r"(addr));
}
__device__ __forceinline__ void ldsm_x4_t(unsigned* r, unsigned addr) {
    asm volatile("ldmatrix.sync.aligned.m8n8.x4.trans.shared.b16 {%0,%1,%2,%3}, [%4];"
                 : "=r"(r[0]), "=r"(r[1]), "=r"(r[2]), "=r"(r[3]) : "r"(addr));
}
__device__ __forceinline__ void mma_bf16(float* c, const unsigned* a, const unsigned* b) {
    asm volatile(
        "mma.sync.aligned.m16n8k16.row.col.f32.bf16.bf16.f32 "
        "{%0,%1,%2,%3}, {%4,%5,%6,%7}, {%8,%9}, {%0,%1,%2,%3};"
        : "+f"(c[0]), "+f"(c[1]), "+f"(c[2]), "+f"(c[3])
        : "r"(a[0]), "r"(a[1]), "r"(a[2]), "r"(a[3]), "r"(b[0]), "r"(b[1]));
}
__device__ __forceinline__ void mma_f16(float* c, const unsigned* a, const unsigned* b) {
    asm volatile(
        "mma.sync.aligned.m16n8k16.row.col.f32.f16.f16.f32 "
        "{%0,%1,%2,%3}, {%4,%5,%6,%7}, {%8,%9}, {%0,%1,%2,%3};"
        : "+f"(c[0]), "+f"(c[1]), "+f"(c[2]), "+f"(c[3])
        : "r"(a[0]), "r"(a[1]), "r"(a[2]), "r"(a[3]), "r"(b[0]), "r"(b[1]));
}
#define STS128A(addr, r0, r1, r2, r3) \
    asm volatile("st.shared.v4.b32 [%0], {%1, %2, %3, %4};" \
                 :: "r"((unsigned)(addr)), "r"(r0), "r"(r1), "r"(r2), "r"(r3) : "memory")
#define STS64A(addr, r0, r1) \
    asm volatile("st.shared.v2.b32 [%0], {%1, %2};" \
                 :: "r"((unsigned)(addr)), "r"(r0), "r"(r1) : "memory")

// bf16 hi/lo split
__device__ __forceinline__ void split2(float a, float b, unsigned& h, unsigned& l) {
    __nv_bfloat16 ha = __float2bfloat16(a);
    __nv_bfloat16 hb = __float2bfloat16(b);
    __nv_bfloat16 la = __float2bfloat16(a - __bfloat162float(ha));
    __nv_bfloat16 lb = __float2bfloat16(b - __bfloat162float(hb));
    __nv_bfloat162 hp = __halves2bfloat162(ha, hb);
    __nv_bfloat162 lp = __halves2bfloat162(la, lb);
    h = *reinterpret_cast<unsigned*>(&hp);
    l = *reinterpret_cast<unsigned*>(&lp);
}
// fp16 hi/lo split
__device__ __forceinline__ void splith2(float a, float b, unsigned& h, unsigned& l) {
    __half ha = __float2half(a);
    __half hb = __float2half(b);
    __half la = __float2half(a - __half2float(ha));
    __half lb = __float2half(b - __half2float(hb));
    __half2 hp = __halves2half2(ha, hb);
    __half2 lp = __halves2half2(la, lb);
    h = *reinterpret_cast<unsigned*>(&hp);
    l = *reinterpret_cast<unsigned*>(&lp);
}
__device__ __forceinline__ unsigned packh2(float a, float b) {
    __half2 p = __floats2half2_rn(a, b);
    return *reinterpret_cast<unsigned*>(&p);
}

// ============================================================================
// Shifted-image precompute: dst[(sh*C + c)][LDIM] fp16, LDIM = 4096 + 2*PD*64.
// Padded row r corresponds to image row y = r - PD; x-shift tj = sh - PD is
// pre-applied (zero outside). grid (9, TS*C), block 256, 2 elems/thread.
// ============================================================================
template<int TS, bool RELU_, bool CONCAT_>
__global__ __launch_bounds__(256)
void shift_img(const float* __restrict__ src, const float* __restrict__ src2,
               __half* __restrict__ dst, int C)
{
    constexpr int PD   = TS / 2;
    constexpr int LDIM = 4096 + 2 * PD * 64;
    int sc = blockIdx.y;                 // sh*C + c
    int sh = sc / C;
    int c  = sc - sh * C;
    int tj = sh - PD;
    int e  = (blockIdx.x * 256 + threadIdx.x) * 2;
    if (e >= LDIM) return;

    const float* base;
    if (CONCAT_ && c >= 768) base = src2 + (size_t)(c - 768) * HW;
    else                     base = src + (size_t)c * HW;

    float v[2];
    #pragma unroll
    for (int j = 0; j < 2; j++) {
        int ee = e + j;
        int r  = ee >> 6;
        int x  = ee & 63;
        int py = r - PD;
        int px = x + tj;
        float t = 0.f;
        if (((unsigned)py < 64u) && ((unsigned)px < 64u))
            t = __ldg(base + py * 64 + px);
        if (RELU_) t = fmaxf(t, 0.f);
        v[j] = t;
    }
    *reinterpret_cast<__half2*>(dst + (size_t)sc * LDIM + e) =
        __floats2half2_rn(v[0], v[1]);
}

// fp32 -> fp16 convert (for wd). 2 elems/thread.
__global__ __launch_bounds__(256)
void conv_f2h(const float* __restrict__ src, __half* __restrict__ dst, int n)
{
    int e = (blockIdx.x * 256 + threadIdx.x) * 2;
    if (e >= n) return;
    *reinterpret_cast<__half2*>(dst + e) = __floats2half2_rn(src[e], src[e + 1]);
}

// ============================================================================
// GEMM kernel. 256 threads (8 warps = WARP_M x WARP_N). BN=128, BK=32.
// MODE 1: B = fp16 [Kfull][4096].
// MODE 2: B = shifted fp16 images (TSM taps): row k=(c,ti,tjs) at col n is
//         bh16[(tjs*C + c)*LDIM + ti*64 + n],  LDIM = 4096 + (TSM/2)*128.
// MODE 3: B = fp32 row-major [Kfull][Nb] (srcF).
// PREC 0: bf16 3-pass.  PREC 1: fp16 1-pass.  PREC 2: fp16 A-hi/lo 2-pass.
// AH: A is pre-converted fp16 (ah16), PREC 1, BM=128 only.
// SPLITK: blockIdx.z = K-split (kb = z*kcnt), atomicAdd epilogue.
// ============================================================================
template<int MODE, int PREC, int TSM, bool AH,
         int WARP_M, int WARP_N, int BM, int MINB, bool SPLITK>
__global__ __launch_bounds__(256, MINB)
void gemm_mma(const float* __restrict__ A,
              const float* __restrict__ srcF,
              const __half* __restrict__ ah16,
              const __half* __restrict__ bh16,
              float* __restrict__ C, int M, int Kfull, int kcnt,
              int Nb, int ldc)
{
    constexpr int BN = 128, BK = 32;
    constexpr int MFRAG = BM / (WARP_M * 16);
    constexpr int NFRAG = BN / (WARP_N * 8);
    constexpr int A_ELEMS = (BM == 128) ? 16 : (BM == 64 ? 8 : 4);
    constexpr int NS_A = (PREC == 1) ? 1 : 2;
    constexpr int NS_B = (PREC == 0) ? 2 : 1;
    constexpr int ASZ = BM * A_STRIDE * 2;
    constexpr int BSZ = 32 * B_STRIDE * 2;
    auto OFF_A = [](int buf, int s) { return (buf * NS_A + s) * ASZ; };
    auto OFF_B = [](int buf, int s) { return 2 * NS_A * ASZ + (buf * NS_B + s) * BSZ; };

    extern __shared__ char smem[];
    const unsigned sb = smem_to_u32(smem);
    const int tid  = threadIdx.x;
    const int wid  = tid >> 5;
    const int lane = tid & 31;
    const int n0 = blockIdx.x * BN;
    const int m0 = blockIdx.y * BM;
    const int kb = SPLITK ? blockIdx.z * kcnt : 0;

    const int kloc = tid >> 3;          // B-loader row within tile
    const int nbb  = (tid & 7) * 16;    // B-loader col base

    float a_st[A_ELEMS];
    uint4 a_raw[2];
    float b_st[16];
    uint4 b_raw[2];

    float acc[MFRAG][NFRAG][4];
    #pragma unroll
    for (int f = 0; f < MFRAG; f++)
        #pragma unroll
        for (int g = 0; g < NFRAG; g++)
            #pragma unroll
            for (int q = 0; q < 4; q++) acc[f][g][q] = 0.f;

    const int iters = kcnt / BK;

    // -------------------- tile load (global -> regs) ------------------------
    auto LOAD = [&](int k0g) {
        // ---- A ----
        if constexpr (AH) {   // fp16 A, BM==128
            int m  = tid >> 1;
            int kh = (tid & 1) * 16;
            int gm = m0 + m;
            const uint4* p =
                reinterpret_cast<const uint4*>(ah16 + (size_t)gm * Kfull + k0g + kh);
            a_raw[0] = p[0];
            a_raw[1] = p[1];
        } else if constexpr (BM == 128) {
            int m  = tid >> 1;
            int kh = (tid & 1) * 16;
            int gm = m0 + m;
            const float4* p =
                reinterpret_cast<const float4*>(A + (size_t)gm * Kfull + k0g + kh);
            #pragma unroll
            for (int q = 0; q < 4; q++) {
                float4 v = (gm < M) ? p[q] : make_float4(0.f, 0.f, 0.f, 0.f);
                a_st[q * 4 + 0] = v.x; a_st[q * 4 + 1] = v.y;
                a_st[q * 4 + 2] = v.z; a_st[q * 4 + 3] = v.w;
            }
        } else if constexpr (BM == 64) {
            int m  = tid >> 2;
            int kh = (tid & 3) * 8;
            int gm = m0 + m;
            const float4* p =
                reinterpret_cast<const float4*>(A + (size_t)gm * Kfull + k0g + kh);
            #pragma unroll
            for (int q = 0; q < 2; q++) {
                float4 v = (gm < M) ? p[q] : make_float4(0.f, 0.f, 0.f, 0.f);
                a_st[q * 4 + 0] = v.x; a_st[q * 4 + 1] = v.y;
                a_st[q * 4 + 2] = v.z; a_st[q * 4 + 3] = v.w;
            }
        } else {  // BM == 32
            int m  = tid >> 3;
            int kq = (tid & 7) * 4;
            int gm = m0 + m;
            float4 v = (gm < M)
                ? *reinterpret_cast<const float4*>(A + (size_t)gm * Kfull + k0g + kq)
                : make_float4(0.f, 0.f, 0.f, 0.f);
            a_st[0] = v.x; a_st[1] = v.y; a_st[2] = v.z; a_st[3] = v.w;
        }
        // ---- B ----
        if constexpr (MODE == 1) {
            const uint4* p = reinterpret_cast<const uint4*>(
                bh16 + (size_t)(k0g + kloc) * HW + n0 + nbb);
            b_raw[0] = p[0];
            b_raw[1] = p[1];
        } else if constexpr (MODE == 2) {
            constexpr int TAPS = TSM * TSM;
            constexpr int LDIM = 4096 + (TSM / 2) * 128;
            int gk  = k0g + kloc;
            int c   = gk / TAPS;
            int tap = gk - c * TAPS;
            int ti  = tap / TSM;
            int tjs = tap - ti * TSM;
            int Cch = Kfull / TAPS;
            const uint4* p = reinterpret_cast<const uint4*>(
                bh16 + (size_t)(tjs * Cch + c) * LDIM + ti * 64 + n0 + nbb);
            b_raw[0] = p[0];
            b_raw[1] = p[1];
        } else {  // MODE 3
            const float* src = srcF + (size_t)(k0g + kloc) * Nb;
            #pragma unroll
            for (int j = 0; j < 16; j++) {
                int n = n0 + nbb + j;
                b_st[j] = (n < Nb) ? __ldg(src + n) : 0.f;
            }
        }
    };

    // -------------------- tile store (regs -> smem) -------------------------
    auto STORE_A_PAIRS = [&](int buf, unsigned base, const float* src, int npairs) {
        if constexpr (PREC == 0) {
            unsigned h[8], l[8];
            for (int q = 0; q < npairs; q++)
                split2(src[2 * q], src[2 * q + 1], h[q], l[q]);
            for (int q4 = 0; q4 < npairs / 4; q4++) {
                STS128A(sb + OFF_A(buf, 0) + base + q4 * 16,
                        h[q4 * 4], h[q4 * 4 + 1], h[q4 * 4 + 2], h[q4 * 4 + 3]);
                STS128A(sb + OFF_A(buf, 1) + base + q4 * 16,
                        l[q4 * 4], l[q4 * 4 + 1], l[q4 * 4 + 2], l[q4 * 4 + 3]);
            }
            if (npairs == 2) {
                STS64A(sb + OFF_A(buf, 0) + base, h[0], h[1]);
                STS64A(sb + OFF_A(buf, 1) + base, l[0], l[1]);
            }
        } else if constexpr (PREC == 2) {
            unsigned h[8], l[8];
            for (int q = 0; q < npairs; q++)
                splith2(src[2 * q], src[2 * q + 1], h[q], l[q]);
            for (int q4 = 0; q4 < npairs / 4; q4++) {
                STS128A(sb + OFF_A(buf, 0) + base + q4 * 16,
                        h[q4 * 4], h[q4 * 4 + 1], h[q4 * 4 + 2], h[q4 * 4 + 3]);
                STS128A(sb + OFF_A(buf, 1) + base + q4 * 16,
                        l[q4 * 4], l[q4 * 4 + 1], l[q4 * 4 + 2], l[q4 * 4 + 3]);
            }
            if (npairs == 2) {
                STS64A(sb + OFF_A(buf, 0) + base, h[0], h[1]);
                STS64A(sb + OFF_A(buf, 1) + base, l[0], l[1]);
            }
        } else {
            unsigned h[8];
            for (int q = 0; q < npairs; q++)
                h[q] = packh2(src[2 * q], src[2 * q + 1]);
            for (int q4 = 0; q4 < npairs / 4; q4++)
                STS128A(sb + OFF_A(buf, 0) + base + q4 * 16,
                        h[q4 * 4], h[q4 * 4 + 1], h[q4 * 4 + 2], h[q4 * 4 + 3]);
            if (npairs == 2)
                STS64A(sb + OFF_A(buf, 0) + base, h[0], h[1]);
        }
    };

    auto STORE = [&](int buf) {
        // ---- A ----
        if constexpr (AH) {
            int m  = tid >> 1;
            int kh = (tid & 1) * 16;
            unsigned base = (unsigned)(m * A_STRIDE + kh) * 2;
            STS128A(sb + OFF_A(buf, 0) + base,
                    a_raw[0].x, a_raw[0].y, a_raw[0].z, a_raw[0].w);
            STS128A(sb + OFF_A(buf, 0) + base + 16,
                    a_raw[1].x, a_raw[1].y, a_raw[1].z, a_raw[1].w);
        } else if constexpr (BM == 128) {
            int m  = tid >> 1;
            int kh = (tid & 1) * 16;
            STORE_A_PAIRS(buf, (unsigned)(m * A_STRIDE + kh) * 2, a_st, 8);
        } else if constexpr (BM == 64) {
            int m  = tid >> 2;
            int kh = (tid & 3) * 8;
            STORE_A_PAIRS(buf, (unsigned)(m * A_STRIDE + kh) * 2, a_st, 4);
        } else {
            int m  = tid >> 3;
            int kq = (tid & 7) * 4;
            STORE_A_PAIRS(buf, (unsigned)(m * A_STRIDE + kq) * 2, a_st, 2);
        }
        // ---- B ----
        unsigned base = (unsigned)(kloc * B_STRIDE + nbb) * 2;
        if constexpr (MODE == 1 || MODE == 2) {
            STS128A(sb + OFF_B(buf, 0) + base,
                    b_raw[0].x, b_raw[0].y, b_raw[0].z, b_raw[0].w);
            STS128A(sb + OFF_B(buf, 0) + base + 16,
                    b_raw[1].x, b_raw[1].y, b_raw[1].z, b_raw[1].w);
        } else if constexpr (PREC == 0) {
            unsigned h[8], l[8];
            #pragma unroll
            for (int q = 0; q < 8; q++)
                split2(b_st[2 * q], b_st[2 * q + 1], h[q], l[q]);
            STS128A(sb + OFF_B(buf, 0) + base,      h[0], h[1], h[2], h[3]);
            STS128A(sb + OFF_B(buf, 0) + base + 16, h[4], h[5], h[6], h[7]);
            STS128A(sb + OFF_B(buf, 1) + base,      l[0], l[1], l[2], l[3]);
            STS128A(sb + OFF_B(buf, 1) + base + 16, l[4], l[5], l[6], l[7]);
        } else {
            unsigned h[8];
            #pragma unroll
            for (int q = 0; q < 8; q++)
                h[q] = packh2(b_st[2 * q], b_st[2 * q + 1]);
            STS128A(sb + OFF_B(buf, 0) + base,      h[0], h[1], h[2], h[3]);
            STS128A(sb + OFF_B(buf, 0) + base + 16, h[4], h[5], h[6], h[7]);
        }
    };

    // -------------------- compute -------------------------------------------
    const int wm  = wid % WARP_M;
    const int wn  = wid / WARP_M;
    const int mb  = wm * MFRAG * 16;
    const int nbw = wn * NFRAG * 8;

    auto COMPUTE = [&](int buf) {
        #pragma unroll
        for (int ks = 0; ks < BK; ks += 16) {
            unsigned ah[MFRAG][4], al[MFRAG][4];
            {
                int arow = mb + (lane & 15);
                int acol = ks + (lane >> 4) * 8;
                #pragma unroll
                for (int f = 0; f < MFRAG; f++) {
                    unsigned off = (unsigned)((arow + f * 16) * A_STRIDE + acol) * 2;
                    ldsm_x4(ah[f], sb + OFF_A(buf, 0) + off);
                    if constexpr (NS_A == 2)
                        ldsm_x4(al[f], sb + OFF_A(buf, 1) + off);
                }
            }
            #pragma unroll
            for (int g = 0; g < NFRAG / 2; g++) {
                unsigned bh[4], bl[4];
                int brow = ks + (lane & 15);
                int bcol = nbw + g * 16 + (lane >> 4) * 8;
                unsigned off = (unsigned)(brow * B_STRIDE + bcol) * 2;
                ldsm_x4_t(bh, sb + OFF_B(buf, 0) + off);
                if constexpr (NS_B == 2)
                    ldsm_x4_t(bl, sb + OFF_B(buf, 1) + off);
                #pragma unroll
                for (int f = 0; f < MFRAG; f++) {
                    #pragma unroll
                    for (int h2x = 0; h2x < 2; h2x++) {
                        float* c = acc[f][g * 2 + h2x];
                        if constexpr (PREC == 0) {
                            mma_bf16(c, ah[f], bh + h2x * 2);
                            mma_bf16(c, ah[f], bl + h2x * 2);
                            mma_bf16(c, al[f], bh + h2x * 2);
                        } else if constexpr (PREC == 2) {
                            mma_f16(c, ah[f], bh + h2x * 2);
                            mma_f16(c, al[f], bh + h2x * 2);
                        } else {
                            mma_f16(c, ah[f], bh + h2x * 2);
                        }
                    }
                }
            }
        }
    };

    // -------------------- main pipeline -------------------------------------
    LOAD(kb);
    STORE(0);
    __syncthreads();
    for (int i = 0; i < iters; i++) {
        if (i + 1 < iters) LOAD(kb + (i + 1) * BK);
        COMPUTE(i & 1);
        if (i + 1 < iters) {
            STORE((i + 1) & 1);
            __syncthreads();
        }
    }

    // -------------------- epilogue ------------------------------------------
    #pragma unroll
    for (int f = 0; f < MFRAG; f++) {
        #pragma unroll
        for (int j = 0; j < NFRAG; j++) {
            int r0  = m0 + mb + f * 16 + (lane >> 2);
            int col = n0 + nbw + j * 8 + (lane & 3) * 2;
            if (col >= Nb) continue;
            float2 v0 = make_float2(acc[f][j][0], acc[f][j][1]);
            float2 v1 = make_float2(acc[f][j][2], acc[f][j][3]);
            if (SPLITK) {
                if (r0 < M) {
                    atomicAdd(C + (size_t)r0 * ldc + col,     v0.x);
                    atomicAdd(C + (size_t)r0 * ldc + col + 1, v0.y);
                }
                if (r0 + 8 < M) {
                    atomicAdd(C + (size_t)(r0 + 8) * ldc + col,     v1.x);
                    atomicAdd(C + (size_t)(r0 + 8) * ldc + col + 1, v1.y);
                }
            } else {
                if (r0 < M)
                    *reinterpret_cast<float2*>(C + (size_t)r0 * ldc + col) = v0;
                if (r0 + 8 < M)
                    *reinterpret_cast<float2*>(C + (size_t)(r0 + 8) * ldc + col) = v1;
            }
        }
    }
}

// ============================================================================
// Small helper kernels for the conv3∘conv4 composition
// ============================================================================
__global__ __launch_bounds__(256)
void transpose_wo(const float* __restrict__ wo, float* __restrict__ woT)
{
    int id = blockIdx.x * 256 + threadIdx.x;
    if (id >= 162 * 1536) return;
    int row = id / 1536;        // o*9 + t1
    int m   = id - row * 1536;
    int o   = row / 9;
    int t1  = row - o * 9;
    woT[id] = wo[(size_t)o * 13824 + m * 9 + t1];
}

__global__ __launch_bounds__(256)
void build_wc(const float* __restrict__ G, float* __restrict__ Wc)
{
    int id = blockIdx.x * 256 + threadIdx.x;
    if (id >= 18 * 4800) return;
    int o   = id / 4800;
    int rem = id - o * 4800;
    int c   = rem / 25;
    int u   = rem - c * 25;
    int uy  = u / 5, ux = u - uy * 5;
    float s = 0.f;
    #pragma unroll
    for (int t1y = 0; t1y < 3; t1y++) {
        int t2y = uy - t1y;
        if ((unsigned)t2y >= 3u) continue;
        #pragma unroll
        for (int t1x = 0; t1x < 3; t1x++) {
            int t2x = ux - t1x;
            if ((unsigned)t2x >= 3u) continue;
            s += G[(size_t)(o * 9 + t1y * 3 + t1x) * 1728 + c * 9 + t2y * 3 + t2x];
        }
    }
    Wc[id] = s;
}

// Exact fp32 recomputation of the border ring (496 px). h2 is RAW -> relu here.
__global__ __launch_bounds__(192)
void border_fix(const float* __restrict__ h2, const float* __restrict__ G,
                float* __restrict__ off)
{
    int x = blockIdx.x, y = blockIdx.y;
    if (x >= 2 && x < 62 && y >= 2 && y < 62) return;
    int c = threadIdx.x;  // 0..191

    float acc[18];
    #pragma unroll
    for (int o = 0; o < 18; o++) acc[o] = 0.f;

    const float* h2c = h2 + (size_t)c * HW;
    for (int t1y = 0; t1y < 3; t1y++) {
        int qy = y + t1y - 1;
        if ((unsigned)qy >= 64u) continue;
        for (int t1x = 0; t1x < 3; t1x++) {
            int qx = x + t1x - 1;
            if ((unsigned)qx >= 64u) continue;
            int t1 = t1y * 3 + t1x;
            for (int t2y = 0; t2y < 3; t2y++) {
                int ry = qy + t2y - 1;
                if ((unsigned)ry >= 64u) continue;
                for (int t2x = 0; t2x < 3; t2x++) {
                    int rx = qx + t2x - 1;
                    if ((unsigned)rx >= 64u) continue;
                    float v = fmaxf(h2c[ry * 64 + rx], 0.f);
                    const float* g = G + (size_t)t1 * 1728 + c * 9 + t2y * 3 + t2x;
                    #pragma unroll
                    for (int o = 0; o < 18; o++)
                        acc[o] += g[(size_t)o * 9 * 1728] * v;
                }
            }
        }
    }

    __shared__ float red[18];
    if (threadIdx.x < 18) red[threadIdx.x] = 0.f;
    __syncthreads();
    #pragma unroll
    for (int o = 0; o < 18; o++) atomicAdd(&red[o], acc[o]);
    __syncthreads();
    if (threadIdx.x < 18)
        off[(size_t)threadIdx.x * HW + y * 64 + x] = red[threadIdx.x];
}

// ============================================================================
// Bilinear sampling -> fp16 S [6912][4096] (k-major)
// ============================================================================
__global__ __launch_bounds__(256)
void sample_kernel(const float* __restrict__ ref,
                   const float* __restrict__ off,
                   __half* __restrict__ sh)
{
    int k = blockIdx.y;                              // 0..6911
    int n = blockIdx.x * 256 + threadIdx.x;          // 0..4095
    int c = k / 9;
    int t = k - c * 9;
    int ti = t / 3;
    int tj = t - ti * 3;
    int y = n >> 6, x = n & 63;

    float dy = off[(2 * t)     * HW + n];
    float dx = off[(2 * t + 1) * HW + n];
    float py = (float)(y - 1 + ti) + dy;
    float px = (float)(x - 1 + tj) + dx;

    float y0f = floorf(py), x0f = floorf(px);
    float wy1 = py - y0f,  wx1 = px - x0f;
    float wy0 = 1.f - wy1, wx0 = 1.f - wx1;
    int y0 = (int)y0f, x0 = (int)x0f;

    const float* r = ref + (size_t)c * HW;
    float v = 0.f;
    if (((unsigned)y0 < 64u) && ((unsigned)x0 < 64u))
        v += wy0 * wx0 * r[y0 * 64 + x0];
    if (((unsigned)y0 < 64u) && ((unsigned)(x0 + 1) < 64u))
        v += wy0 * wx1 * r[y0 * 64 + x0 + 1];
    if (((unsigned)(y0 + 1) < 64u) && ((unsigned)x0 < 64u))
        v += wy1 * wx0 * r[(y0 + 1) * 64 + x0];
    if (((unsigned)(y0 + 1) < 64u) && ((unsigned)(x0 + 1) < 64u))
        v += wy1 * wx1 * r[(y0 + 1) * 64 + x0 + 1];

    sh[(size_t)k * HW + n] = __float2half(v);
}

// ============================================================================
extern "C" void kernel_launch(void* const* d_in, const int* in_sizes, int n_in,
                              void* d_out, int out_size)
{
    const float* x_in  = (const float*)d_in[0];
    const float* x_ref = (const float*)d_in[1];
    const float* w1    = (const float*)d_in[2];
    const float* w2    = (const float*)d_in[3];
    const float* w3    = (const float*)d_in[4];
    const float* wo    = (const float*)d_in[5];
    const float* wd    = (const float*)d_in[6];
    float* out = (float*)d_out;

    float *h1, *h2, *off, *woT, *G, *Wc;
    __half *sh, *x1, *x2, *x3, *wdh;
    cudaGetSymbolAddress((void**)&h1,  g_h1);
    cudaGetSymbolAddress((void**)&h2,  g_h2);
    cudaGetSymbolAddress((void**)&off, g_off);
    cudaGetSymbolAddress((void**)&woT, g_woT);
    cudaGetSymbolAddress((void**)&G,   g_G);
    cudaGetSymbolAddress((void**)&Wc,  g_Wc);
    cudaGetSymbolAddress((void**)&sh,  g_sh);
    cudaGetSymbolAddress((void**)&x1,  g_x1);
    cudaGetSymbolAddress((void**)&x2,  g_x2);
    cudaGetSymbolAddress((void**)&x3,  g_x3);
    cudaGetSymbolAddress((void**)&wdh, g_wdh);

    constexpr int SM64_BF  = 2 * (2 * (64 * A_STRIDE * 2) + 2 * (32 * B_STRIDE * 2)); // 55296
    constexpr int SM64_P2  = 2 * (2 * (64 * A_STRIDE * 2) + 1 * (32 * B_STRIDE * 2)); // 37888
    constexpr int SM32_P2  = 2 * (2 * (32 * A_STRIDE * 2) + 1 * (32 * B_STRIDE * 2)); // 27648
    constexpr int SM128_FP = 2 * (1 * (128 * A_STRIDE * 2) + 1 * (32 * B_STRIDE * 2)); // 37888

    cudaFuncSetAttribute(
        (const void*)gemm_mma<3, 0, 3, false, 2, 4, 64, 2, false>,
        cudaFuncAttributeMaxDynamicSharedMemorySize, SM64_BF);
    cudaFuncSetAttribute(
        (const void*)gemm_mma<2, 2, 3, false, 2, 4, 64, 2, true>,
        cudaFuncAttributeMaxDynamicSharedMemorySize, SM64_P2);
    cudaFuncSetAttribute(
        (const void*)gemm_mma<2, 2, 5, false, 1, 8, 32, 2, true>,
        cudaFuncAttributeMaxDynamicSharedMemorySize, SM32_P2);
    cudaFuncSetAttribute(
        (const void*)gemm_mma<1, 1, 3, true, 4, 2, 128, 2, true>,
        cudaFuncAttributeMaxDynamicSharedMemorySize, SM128_FP);

    // zero split-K accumulators (d_out is poisoned -> must zero for atomics)
    cudaMemsetAsync(h1,  0, (size_t)192 * HW * 4);
    cudaMemsetAsync(h2,  0, (size_t)192 * HW * 4);
    cudaMemsetAsync(off, 0, (size_t)18  * HW * 4);
    cudaMemsetAsync(out, 0, (size_t)768 * HW * 4);

    // --- weight composition (conv3 ∘ conv4) + wd fp16 convert ---
    transpose_wo<<<(162 * 1536 + 255) / 256, 256>>>(wo, woT);
    gemm_mma<3, 0, 3, false, 2, 4, 64, 2, false><<<dim3(14, 3), 256, SM64_BF>>>(
        woT, w3, nullptr, nullptr, G, 162, 1536, 1536, 1728, 1728);
    build_wc<<<(18 * 4800 + 255) / 256, 256>>>(G, Wc);
    conv_f2h<<<(768 * 6912) / 512, 256>>>(wd, wdh, 768 * 6912);

    // --- stage 1: shifted concat images + conv1 (SPLIT-K x3) ---
    shift_img<3, false, true><<<dim3(9, 3 * 1536), 256>>>(x_in, x_ref, x1, 1536);
    gemm_mma<2, 2, 3, false, 2, 4, 64, 2, true><<<dim3(32, 3, 3), 256, SM64_P2>>>(
        w1, nullptr, nullptr, x1, h1, 192, 13824, 4608, HW, HW);

    // --- stage 2: shifted relu(h1) images + conv2 (SPLIT-K x3) ---
    shift_img<3, true, false><<<dim3(9, 3 * 192), 256>>>(h1, nullptr, x2, 192);
    gemm_mma<2, 2, 3, false, 2, 4, 64, 2, true><<<dim3(32, 3, 3), 256, SM64_P2>>>(
        w2, nullptr, nullptr, x2, h2, 192, 1728, 576, HW, HW);

    // --- stage 3: shifted relu(h2) 5x5 images + composed offsets (x10) ---
    shift_img<5, true, false><<<dim3(9, 5 * 192), 256>>>(h2, nullptr, x3, 192);
    gemm_mma<2, 2, 5, false, 1, 8, 32, 2, true><<<dim3(32, 1, 10), 256, SM32_P2>>>(
        Wc, nullptr, nullptr, x3, off, 18, 4800, 480, HW, HW);
    // exact border ring (relu applied inside)
    border_fix<<<dim3(64, 64), 192>>>(h2, G, off);

    // bilinear sampling -> fp16 S
    sample_kernel<<<dim3(16, 6912), 256>>>(x_ref, off, sh);

    // deform GEMM: out = wdh @ S  (fp16 1-pass, BM=128, SPLIT-K x3, atomics)
    gemm_mma<1, 1, 3, true, 4, 2, 128, 2, true><<<dim3(32, 6, 3), 256, SM128_FP>>>(
        nullptr, nullptr, wdh, sh, out, 768, 6912, 2304, HW, HW);
}

// round 17
// speedup vs baseline: 5.4659x; 1.0229x over previous
#include <cuda_runtime.h>
#include <cuda_bf16.h>
#include <cuda_fp16.h>

// ============================================================================
// DeformableConvBlock, round 17 (resubmission of round 16 — infra flake).
//   shifted-image B precompute (fp16, aligned) + pre-split fp16 hi/lo A weights
//   conv1: fp16 2-pass GEMM (A=w1 pre-split) @ shifted-imgs   SPLIT-K x3
//   conv2: fp16 2-pass GEMM (A=w2 pre-split)                  SPLIT-K x3
//   offsets: composed conv3∘conv4 -> 5x5 GEMM (A=Wc pre-split) SPLIT-K x10
//            + fp32 border ring
//   sampling: per-tap precomputed bilinear -> S fp16 [6912][4096]
//   deform: fp16 1-pass GEMM (A=wd fp16), BM=128, SPLIT-K x3
// ============================================================================

#define HW 4096

// ---------------- device scratch --------------------------------------------
__device__ float g_h1 [192  * HW];
__device__ float g_h2 [192  * HW];   // RAW (pre-ReLU) conv2 output
__device__ float g_off[18   * HW];
__device__ float g_woT[162 * 1536];
__device__ float g_G  [162 * 1728];
__device__ float g_Wc [18 * 4800];
__device__ __half g_sh[(size_t)6912 * HW];
__device__ __half g_x1[(size_t)3 * 1536 * 4224];  // 3 x-shifts, y-pad 1 row
__device__ __half g_x2[(size_t)3 * 192  * 4224];
__device__ __half g_x3[(size_t)5 * 192  * 4352];  // 5 x-shifts, y-pad 2 rows
__device__ __half g_wdh[(size_t)768 * 6912];
__device__ __half g_w1h[192 * 13824], g_w1l[192 * 13824];
__device__ __half g_w2h[192 * 1728],  g_w2l[192 * 1728];
__device__ __half g_wch[18 * 4800],   g_wcl[18 * 4800];

// ---------------- smem geometry ---------------------------------------------
#define A_STRIDE 40     // elems per A row (32 data + 8 pad)
#define B_STRIDE 136    // elems per B row (128 data + 8 pad)

// ---------------- PTX helpers ------------------------------------------------
__device__ __forceinline__ unsigned smem_to_u32(const void* p) {
    unsigned a;
    asm("{ .reg .u64 t; cvta.to.shared.u64 t, %1; cvt.u32.u64 %0, t; }"
        : "=r"(a) : "l"(p));
    return a;
}
__device__ __forceinline__ void ldsm_x4(unsigned* r, unsigned addr) {
    asm volatile("ldmatrix.sync.aligned.m8n8.x4.shared.b16 {%0,%1,%2,%3}, [%4];"
                 : "=r"(r[0]), "=r"(r[1]), "=r"(r[2]), "=r"(r[3]) : "r"(addr));
}
__device__ __forceinline__ void ldsm_x4_t(unsigned* r, unsigned addr) {
    asm volatile("ldmatrix.sync.aligned.m8n8.x4.trans.shared.b16 {%0,%1,%2,%3}, [%4];"
                 : "=r"(r[0]), "=r"(r[1]), "=r"(r[2]), "=r"(r[3]) : "r"(addr));
}
__device__ __forceinline__ void mma_bf16(float* c, const unsigned* a, const unsigned* b) {
    asm volatile(
        "mma.sync.aligned.m16n8k16.row.col.f32.bf16.bf16.f32 "
        "{%0,%1,%2,%3}, {%4,%5,%6,%7}, {%8,%9}, {%0,%1,%2,%3};"
        : "+f"(c[0]), "+f"(c[1]), "+f"(c[2]), "+f"(c[3])
        : "r"(a[0]), "r"(a[1]), "r"(a[2]), "r"(a[3]), "r"(b[0]), "r"(b[1]));
}
__device__ __forceinline__ void mma_f16(float* c, const unsigned* a, const unsigned* b) {
    asm volatile(
        "mma.sync.aligned.m16n8k16.row.col.f32.f16.f16.f32 "
        "{%0,%1,%2,%3}, {%4,%5,%6,%7}, {%8,%9}, {%0,%1,%2,%3};"
        : "+f"(c[0]), "+f"(c[1]), "+f"(c[2]), "+f"(c[3])
        : "r"(a[0]), "r"(a[1]), "r"(a[2]), "r"(a[3]), "r"(b[0]), "r"(b[1]));
}
#define STS128A(addr, r0, r1, r2, r3) \
    asm volatile("st.shared.v4.b32 [%0], {%1, %2, %3, %4};" \
                 :: "r"((unsigned)(addr)), "r"(r0), "r"(r1), "r"(r2), "r"(r3) : "memory")
#define STS64A(addr, r0, r1) \
    asm volatile("st.shared.v2.b32 [%0], {%1, %2};" \
                 :: "r"((unsigned)(addr)), "r"(r0), "r"(r1) : "memory")

// bf16 hi/lo split
__device__ __forceinline__ void split2(float a, float b, unsigned& h, unsigned& l) {
    __nv_bfloat16 ha = __float2bfloat16(a);
    __nv_bfloat16 hb = __float2bfloat16(b);
    __nv_bfloat16 la = __float2bfloat16(a - __bfloat162float(ha));
    __nv_bfloat16 lb = __float2bfloat16(b - __bfloat162float(hb));
    __nv_bfloat162 hp = __halves2bfloat162(ha, hb);
    __nv_bfloat162 lp = __halves2bfloat162(la, lb);
    h = *reinterpret_cast<unsigned*>(&hp);
    l = *reinterpret_cast<unsigned*>(&lp);
}
__device__ __forceinline__ unsigned packh2(float a, float b) {
    __half2 p = __floats2half2_rn(a, b);
    return *reinterpret_cast<unsigned*>(&p);
}

// ============================================================================
// Shifted-image precompute (B operand).
// ============================================================================
template<int TS, bool RELU_, bool CONCAT_>
__global__ __launch_bounds__(256)
void shift_img(const float* __restrict__ src, const float* __restrict__ src2,
               __half* __restrict__ dst, int C)
{
    constexpr int PD   = TS / 2;
    constexpr int LDIM = 4096 + 2 * PD * 64;
    int sc = blockIdx.y;                 // sh*C + c
    int sh = sc / C;
    int c  = sc - sh * C;
    int tj = sh - PD;
    int e  = (blockIdx.x * 256 + threadIdx.x) * 2;
    if (e >= LDIM) return;

    const float* base;
    if (CONCAT_ && c >= 768) base = src2 + (size_t)(c - 768) * HW;
    else                     base = src + (size_t)c * HW;

    float v[2];
    #pragma unroll
    for (int j = 0; j < 2; j++) {
        int ee = e + j;
        int r  = ee >> 6;
        int x  = ee & 63;
        int py = r - PD;
        int px = x + tj;
        float t = 0.f;
        if (((unsigned)py < 64u) && ((unsigned)px < 64u))
            t = __ldg(base + py * 64 + px);
        if (RELU_) t = fmaxf(t, 0.f);
        v[j] = t;
    }
    *reinterpret_cast<__half2*>(dst + (size_t)sc * LDIM + e) =
        __floats2half2_rn(v[0], v[1]);
}

// fp32 -> fp16 convert (wd). 2 elems/thread.
__global__ __launch_bounds__(256)
void conv_f2h(const float* __restrict__ src, __half* __restrict__ dst, int n)
{
    int e = (blockIdx.x * 256 + threadIdx.x) * 2;
    if (e >= n) return;
    *reinterpret_cast<__half2*>(dst + e) = __floats2half2_rn(src[e], src[e + 1]);
}

// fp32 -> fp16 hi/lo split (conv A weights). 2 elems/thread.
__global__ __launch_bounds__(256)
void presplit_h(const float* __restrict__ src,
                __half* __restrict__ hi, __half* __restrict__ lo, int n)
{
    int e = (blockIdx.x * 256 + threadIdx.x) * 2;
    if (e >= n) return;
    float a = src[e], b = src[e + 1];
    __half ha = __float2half(a), hb = __float2half(b);
    __half la = __float2half(a - __half2float(ha));
    __half lb = __float2half(b - __half2float(hb));
    *reinterpret_cast<__half2*>(hi + e) = __halves2half2(ha, hb);
    *reinterpret_cast<__half2*>(lo + e) = __halves2half2(la, lb);
}

// ============================================================================
// GEMM kernel. 256 threads (8 warps = WARP_M x WARP_N). BN=128, BK=32.
// MODE 1: B = fp16 [Kfull][4096].
// MODE 2: B = shifted fp16 images (TSM taps), LDIM = 4096 + (TSM/2)*128.
// MODE 3: B = fp32 row-major [Kfull][Nb] (srcF).
// PREC 0: bf16 3-pass (fp32 A, fp32 B).  PREC 1: fp16 1-pass.  PREC 2: fp16 2-pass.
// AHM 0: A fp32 (split in-kernel).  AHM 1: A fp16 single (ah).
// AHM 2: A pre-split fp16 hi/lo (ah, al).
// SPLITK: blockIdx.z = K-split (kb = z*kcnt), atomicAdd epilogue.
// ============================================================================
template<int MODE, int PREC, int TSM, int AHM,
         int WARP_M, int WARP_N, int BM, int MINB, bool SPLITK>
__global__ __launch_bounds__(256, MINB)
void gemm_mma(const float* __restrict__ A,
              const float* __restrict__ srcF,
              const __half* __restrict__ ah16,
              const __half* __restrict__ al16,
              const __half* __restrict__ bh16,
              float* __restrict__ C, int M, int Kfull, int kcnt,
              int Nb, int ldc)
{
    constexpr int BN = 128, BK = 32;
    constexpr int MFRAG = BM / (WARP_M * 16);
    constexpr int NFRAG = BN / (WARP_N * 8);
    constexpr int A_ELEMS = (BM == 128) ? 16 : (BM == 64 ? 8 : 4);
    constexpr int NS_A = (PREC == 1) ? 1 : 2;
    constexpr int NS_B = (PREC == 0) ? 2 : 1;
    constexpr int ASZ = BM * A_STRIDE * 2;
    constexpr int BSZ = 32 * B_STRIDE * 2;
    auto OFF_A = [](int buf, int s) { return (buf * NS_A + s) * ASZ; };
    auto OFF_B = [](int buf, int s) { return 2 * NS_A * ASZ + (buf * NS_B + s) * BSZ; };

    extern __shared__ char smem[];
    const unsigned sb = smem_to_u32(smem);
    const int tid  = threadIdx.x;
    const int wid  = tid >> 5;
    const int lane = tid & 31;
    const int n0 = blockIdx.x * BN;
    const int m0 = blockIdx.y * BM;
    const int kb = SPLITK ? blockIdx.z * kcnt : 0;

    const int kloc = tid >> 3;          // B-loader row within tile
    const int nbb  = (tid & 7) * 16;    // B-loader col base

    float a_st[A_ELEMS];
    uint4 a_raw[2];         // AHM1 (BM=128): hi only; AHM2 (BM=64): [0]=hi [1]=lo
    uint2 a_raw2[2];        // AHM2, BM=32
    float b_st[16];
    uint4 b_raw[2];

    float acc[MFRAG][NFRAG][4];
    #pragma unroll
    for (int f = 0; f < MFRAG; f++)
        #pragma unroll
        for (int g = 0; g < NFRAG; g++)
            #pragma unroll
            for (int q = 0; q < 4; q++) acc[f][g][q] = 0.f;

    const int iters = kcnt / BK;

    // -------------------- tile load (global -> regs) ------------------------
    auto LOAD = [&](int k0g) {
        // ---- A ----
        if constexpr (AHM == 1) {     // fp16 single, BM==128
            int m  = tid >> 1;
            int kh = (tid & 1) * 16;
            int gm = m0 + m;
            const uint4* p =
                reinterpret_cast<const uint4*>(ah16 + (size_t)gm * Kfull + k0g + kh);
            a_raw[0] = p[0];
            a_raw[1] = p[1];
        } else if constexpr (AHM == 2 && BM == 64) {
            int m  = tid >> 2;
            int kh = (tid & 3) * 8;
            int gm = m0 + m;
            size_t gix = (size_t)gm * Kfull + k0g + kh;
            a_raw[0] = *reinterpret_cast<const uint4*>(ah16 + gix);
            a_raw[1] = *reinterpret_cast<const uint4*>(al16 + gix);
        } else if constexpr (AHM == 2 && BM == 32) {
            int m  = tid >> 3;
            int kq = (tid & 7) * 4;
            int gm = m0 + m;
            a_raw2[0] = make_uint2(0, 0);
            a_raw2[1] = make_uint2(0, 0);
            if (gm < M) {
                size_t gix = (size_t)gm * Kfull + k0g + kq;
                a_raw2[0] = *reinterpret_cast<const uint2*>(ah16 + gix);
                a_raw2[1] = *reinterpret_cast<const uint2*>(al16 + gix);
            }
        } else if constexpr (BM == 64) {   // AHM 0, fp32 A
            int m  = tid >> 2;
            int kh = (tid & 3) * 8;
            int gm = m0 + m;
            const float4* p =
                reinterpret_cast<const float4*>(A + (size_t)gm * Kfull + k0g + kh);
            #pragma unroll
            for (int q = 0; q < 2; q++) {
                float4 v = (gm < M) ? p[q] : make_float4(0.f, 0.f, 0.f, 0.f);
                a_st[q * 4 + 0] = v.x; a_st[q * 4 + 1] = v.y;
                a_st[q * 4 + 2] = v.z; a_st[q * 4 + 3] = v.w;
            }
        }
        // ---- B ----
        if constexpr (MODE == 1) {
            const uint4* p = reinterpret_cast<const uint4*>(
                bh16 + (size_t)(k0g + kloc) * HW + n0 + nbb);
            b_raw[0] = p[0];
            b_raw[1] = p[1];
        } else if constexpr (MODE == 2) {
            constexpr int TAPS = TSM * TSM;
            constexpr int LDIM = 4096 + (TSM / 2) * 128;
            int gk  = k0g + kloc;
            int c   = gk / TAPS;
            int tap = gk - c * TAPS;
            int ti  = tap / TSM;
            int tjs = tap - ti * TSM;
            int Cch = Kfull / TAPS;
            const uint4* p = reinterpret_cast<const uint4*>(
                bh16 + (size_t)(tjs * Cch + c) * LDIM + ti * 64 + n0 + nbb);
            b_raw[0] = p[0];
            b_raw[1] = p[1];
        } else {  // MODE 3
            const float* src = srcF + (size_t)(k0g + kloc) * Nb;
            #pragma unroll
            for (int j = 0; j < 16; j++) {
                int n = n0 + nbb + j;
                b_st[j] = (n < Nb) ? __ldg(src + n) : 0.f;
            }
        }
    };

    // -------------------- tile store (regs -> smem) -------------------------
    auto STORE = [&](int buf) {
        // ---- A ----
        if constexpr (AHM == 1) {
            int m  = tid >> 1;
            int kh = (tid & 1) * 16;
            unsigned base = (unsigned)(m * A_STRIDE + kh) * 2;
            STS128A(sb + OFF_A(buf, 0) + base,
                    a_raw[0].x, a_raw[0].y, a_raw[0].z, a_raw[0].w);
            STS128A(sb + OFF_A(buf, 0) + base + 16,
                    a_raw[1].x, a_raw[1].y, a_raw[1].z, a_raw[1].w);
        } else if constexpr (AHM == 2 && BM == 64) {
            int m  = tid >> 2;
            int kh = (tid & 3) * 8;
            unsigned base = (unsigned)(m * A_STRIDE + kh) * 2;
            STS128A(sb + OFF_A(buf, 0) + base,
                    a_raw[0].x, a_raw[0].y, a_raw[0].z, a_raw[0].w);
            STS128A(sb + OFF_A(buf, 1) + base,
                    a_raw[1].x, a_raw[1].y, a_raw[1].z, a_raw[1].w);
        } else if constexpr (AHM == 2 && BM == 32) {
            int m  = tid >> 3;
            int kq = (tid & 7) * 4;
            unsigned base = (unsigned)(m * A_STRIDE + kq) * 2;
            STS64A(sb + OFF_A(buf, 0) + base, a_raw2[0].x, a_raw2[0].y);
            STS64A(sb + OFF_A(buf, 1) + base, a_raw2[1].x, a_raw2[1].y);
        } else if constexpr (BM == 64) {   // AHM 0: bf16 split in-kernel
            int m  = tid >> 2;
            int kh = (tid & 3) * 8;
            unsigned base = (unsigned)(m * A_STRIDE + kh) * 2;
            unsigned h[4], l[4];
            #pragma unroll
            for (int q = 0; q < 4; q++)
                split2(a_st[2 * q], a_st[2 * q + 1], h[q], l[q]);
            STS128A(sb + OFF_A(buf, 0) + base, h[0], h[1], h[2], h[3]);
            STS128A(sb + OFF_A(buf, 1) + base, l[0], l[1], l[2], l[3]);
        }
        // ---- B ----
        unsigned base = (unsigned)(kloc * B_STRIDE + nbb) * 2;
        if constexpr (MODE == 1 || MODE == 2) {
            STS128A(sb + OFF_B(buf, 0) + base,
                    b_raw[0].x, b_raw[0].y, b_raw[0].z, b_raw[0].w);
            STS128A(sb + OFF_B(buf, 0) + base + 16,
                    b_raw[1].x, b_raw[1].y, b_raw[1].z, b_raw[1].w);
        } else if constexpr (PREC == 0) {
            unsigned h[8], l[8];
            #pragma unroll
            for (int q = 0; q < 8; q++)
                split2(b_st[2 * q], b_st[2 * q + 1], h[q], l[q]);
            STS128A(sb + OFF_B(buf, 0) + base,      h[0], h[1], h[2], h[3]);
            STS128A(sb + OFF_B(buf, 0) + base + 16, h[4], h[5], h[6], h[7]);
            STS128A(sb + OFF_B(buf, 1) + base,      l[0], l[1], l[2], l[3]);
            STS128A(sb + OFF_B(buf, 1) + base + 16, l[4], l[5], l[6], l[7]);
        } else {
            unsigned h[8];
            #pragma unroll
            for (int q = 0; q < 8; q++)
                h[q] = packh2(b_st[2 * q], b_st[2 * q + 1]);
            STS128A(sb + OFF_B(buf, 0) + base,      h[0], h[1], h[2], h[3]);
            STS128A(sb + OFF_B(buf, 0) + base + 16, h[4], h[5], h[6], h[7]);
        }
    };

    // -------------------- compute -------------------------------------------
    const int wm  = wid % WARP_M;
    const int wn  = wid / WARP_M;
    const int mb  = wm * MFRAG * 16;
    const int nbw = wn * NFRAG * 8;

    auto COMPUTE = [&](int buf) {
        #pragma unroll
        for (int ks = 0; ks < BK; ks += 16) {
            unsigned ahf[MFRAG][4], alf[MFRAG][4];
            {
                int arow = mb + (lane & 15);
                int acol = ks + (lane >> 4) * 8;
                #pragma unroll
                for (int f = 0; f < MFRAG; f++) {
                    unsigned off = (unsigned)((arow + f * 16) * A_STRIDE + acol) * 2;
                    ldsm_x4(ahf[f], sb + OFF_A(buf, 0) + off);
                    if constexpr (NS_A == 2)
                        ldsm_x4(alf[f], sb + OFF_A(buf, 1) + off);
                }
            }
            #pragma unroll
            for (int g = 0; g < NFRAG / 2; g++) {
                unsigned bh[4], bl[4];
                int brow = ks + (lane & 15);
                int bcol = nbw + g * 16 + (lane >> 4) * 8;
                unsigned off = (unsigned)(brow * B_STRIDE + bcol) * 2;
                ldsm_x4_t(bh, sb + OFF_B(buf, 0) + off);
                if constexpr (NS_B == 2)
                    ldsm_x4_t(bl, sb + OFF_B(buf, 1) + off);
                #pragma unroll
                for (int f = 0; f < MFRAG; f++) {
                    #pragma unroll
                    for (int h2x = 0; h2x < 2; h2x++) {
                        float* c = acc[f][g * 2 + h2x];
                        if constexpr (PREC == 0) {
                            mma_bf16(c, ahf[f], bh + h2x * 2);
                            mma_bf16(c, ahf[f], bl + h2x * 2);
                            mma_bf16(c, alf[f], bh + h2x * 2);
                        } else if constexpr (PREC == 2) {
                            mma_f16(c, ahf[f], bh + h2x * 2);
                            mma_f16(c, alf[f], bh + h2x * 2);
                        } else {
                            mma_f16(c, ahf[f], bh + h2x * 2);
                        }
                    }
                }
            }
        }
    };

    // -------------------- main pipeline -------------------------------------
    LOAD(kb);
    STORE(0);
    __syncthreads();
    for (int i = 0; i < iters; i++) {
        if (i + 1 < iters) LOAD(kb + (i + 1) * BK);
        COMPUTE(i & 1);
        if (i + 1 < iters) {
            STORE((i + 1) & 1);
            __syncthreads();
        }
    }

    // -------------------- epilogue ------------------------------------------
    #pragma unroll
    for (int f = 0; f < MFRAG; f++) {
        #pragma unroll
        for (int j = 0; j < NFRAG; j++) {
            int r0  = m0 + mb + f * 16 + (lane >> 2);
            int col = n0 + nbw + j * 8 + (lane & 3) * 2;
            if (col >= Nb) continue;
            float2 v0 = make_float2(acc[f][j][0], acc[f][j][1]);
            float2 v1 = make_float2(acc[f][j][2], acc[f][j][3]);
            if (SPLITK) {
                if (r0 < M) {
                    atomicAdd(C + (size_t)r0 * ldc + col,     v0.x);
                    atomicAdd(C + (size_t)r0 * ldc + col + 1, v0.y);
                }
                if (r0 + 8 < M) {
                    atomicAdd(C + (size_t)(r0 + 8) * ldc + col,     v1.x);
                    atomicAdd(C + (size_t)(r0 + 8) * ldc + col + 1, v1.y);
                }
            } else {
                if (r0 < M)
                    *reinterpret_cast<float2*>(C + (size_t)r0 * ldc + col) = v0;
                if (r0 + 8 < M)
                    *reinterpret_cast<float2*>(C + (size_t)(r0 + 8) * ldc + col) = v1;
            }
        }
    }
}

// ============================================================================
// Small helper kernels for the conv3∘conv4 composition
// ============================================================================
__global__ __launch_bounds__(256)
void transpose_wo(const float* __restrict__ wo, float* __restrict__ woT)
{
    int id = blockIdx.x * 256 + threadIdx.x;
    if (id >= 162 * 1536) return;
    int row = id / 1536;        // o*9 + t1
    int m   = id - row * 1536;
    int o   = row / 9;
    int t1  = row - o * 9;
    woT[id] = wo[(size_t)o * 13824 + m * 9 + t1];
}

__global__ __launch_bounds__(256)
void build_wc(const float* __restrict__ G, float* __restrict__ Wc)
{
    int id = blockIdx.x * 256 + threadIdx.x;
    if (id >= 18 * 4800) return;
    int o   = id / 4800;
    int rem = id - o * 4800;
    int c   = rem / 25;
    int u   = rem - c * 25;
    int uy  = u / 5, ux = u - uy * 5;
    float s = 0.f;
    #pragma unroll
    for (int t1y = 0; t1y < 3; t1y++) {
        int t2y = uy - t1y;
        if ((unsigned)t2y >= 3u) continue;
        #pragma unroll
        for (int t1x = 0; t1x < 3; t1x++) {
            int t2x = ux - t1x;
            if ((unsigned)t2x >= 3u) continue;
            s += G[(size_t)(o * 9 + t1y * 3 + t1x) * 1728 + c * 9 + t2y * 3 + t2x];
        }
    }
    Wc[id] = s;
}

// Exact fp32 recomputation of the border ring (496 px). h2 is RAW -> relu here.
__global__ __launch_bounds__(192)
void border_fix(const float* __restrict__ h2, const float* __restrict__ G,
                float* __restrict__ off)
{
    int x = blockIdx.x, y = blockIdx.y;
    if (x >= 2 && x < 62 && y >= 2 && y < 62) return;
    int c = threadIdx.x;  // 0..191

    float acc[18];
    #pragma unroll
    for (int o = 0; o < 18; o++) acc[o] = 0.f;

    const float* h2c = h2 + (size_t)c * HW;
    for (int t1y = 0; t1y < 3; t1y++) {
        int qy = y + t1y - 1;
        if ((unsigned)qy >= 64u) continue;
        for (int t1x = 0; t1x < 3; t1x++) {
            int qx = x + t1x - 1;
            if ((unsigned)qx >= 64u) continue;
            int t1 = t1y * 3 + t1x;
            for (int t2y = 0; t2y < 3; t2y++) {
                int ry = qy + t2y - 1;
                if ((unsigned)ry >= 64u) continue;
                for (int t2x = 0; t2x < 3; t2x++) {
                    int rx = qx + t2x - 1;
                    if ((unsigned)rx >= 64u) continue;
                    float v = fmaxf(h2c[ry * 64 + rx], 0.f);
                    const float* g = G + (size_t)t1 * 1728 + c * 9 + t2y * 3 + t2x;
                    #pragma unroll
                    for (int o = 0; o < 18; o++)
                        acc[o] += g[(size_t)o * 9 * 1728] * v;
                }
            }
        }
    }

    __shared__ float red[18];
    if (threadIdx.x < 18) red[threadIdx.x] = 0.f;
    __syncthreads();
    #pragma unroll
    for (int o = 0; o < 18; o++) atomicAdd(&red[o], acc[o]);
    __syncthreads();
    if (threadIdx.x < 18)
        off[(size_t)threadIdx.x * HW + y * 64 + x] = red[threadIdx.x];
}

// ============================================================================
// Bilinear sampling with per-tap precompute.
// grid (16 n-tiles, 48 c-groups of 16), block 256, dyn smem 73728 B.
// Phase 1: per (tap, n) compute 4 clamped corner indices + 4 masked weights.
// Phase 2: loop (tap, c): 4 gathers + 4 FFMA + 1 fp16 store per sample.
// Bit-identical to the previous sampler (same fp32 ops & masking).
// ============================================================================
__global__ __launch_bounds__(256)
void sample_kernel(const float* __restrict__ ref,
                   const float* __restrict__ off,
                   __half* __restrict__ sh)
{
    extern __shared__ char sm[];
    int*   sidx = reinterpret_cast<int*>(sm);                    // [9][256][4]
    float* swt  = reinterpret_cast<float*>(sm + 9 * 256 * 16);   // [9][256][4]

    const int tid = threadIdx.x;
    const int n0  = blockIdx.x * 256;
    const int n   = n0 + tid;
    const int y   = n >> 6, x = n & 63;

    // ---- phase 1: per-tap corner indices & weights ----
    #pragma unroll
    for (int t = 0; t < 9; t++) {
        int ti = t / 3, tj = t - ti * 3;
        float dy = off[(2 * t)     * HW + n];
        float dx = off[(2 * t + 1) * HW + n];
        float py = (float)(y - 1 + ti) + dy;
        float px = (float)(x - 1 + tj) + dx;
        float y0f = floorf(py), x0f = floorf(px);
        float wy1 = py - y0f,  wx1 = px - x0f;
        float wy0 = 1.f - wy1, wx0 = 1.f - wx1;
        int y0 = (int)y0f, x0 = (int)x0f;

        bool vy0 = (unsigned)y0 < 64u,       vy1 = (unsigned)(y0 + 1) < 64u;
        bool vx0 = (unsigned)x0 < 64u,       vx1 = (unsigned)(x0 + 1) < 64u;
        int iy0 = min(max(y0, 0), 63),       iy1 = min(max(y0 + 1, 0), 63);
        int ix0 = min(max(x0, 0), 63),      ix1 = min(max(x0 + 1, 0), 63);

        int base = (t * 256 + tid) * 4;
        sidx[base + 0] = iy0 * 64 + ix0;
        sidx[base + 1] = iy0 * 64 + ix1;
        sidx[base + 2] = iy1 * 64 + ix0;
        sidx[base + 3] = iy1 * 64 + ix1;
        swt[base + 0] = (vy0 && vx0) ? wy0 * wx0 : 0.f;
        swt[base + 1] = (vy0 && vx1) ? wy0 * wx1 : 0.f;
        swt[base + 2] = (vy1 && vx0) ? wy1 * wx0 : 0.f;
        swt[base + 3] = (vy1 && vx1) ? wy1 * wx1 : 0.f;
    }
    __syncthreads();

    // ---- phase 2: gather for 16 channels ----
    const int c0 = blockIdx.y * 16;
    #pragma unroll
    for (int t = 0; t < 9; t++) {
        int4   id = *reinterpret_cast<const int4*>(&sidx[(t * 256 + tid) * 4]);
        float4 w  = *reinterpret_cast<const float4*>(&swt[(t * 256 + tid) * 4]);
        #pragma unroll 4
        for (int cc = 0; cc < 16; cc++) {
            const float* r = ref + (size_t)(c0 + cc) * HW;
            float v = w.x * __ldg(r + id.x) + w.y * __ldg(r + id.y)
                    + w.z * __ldg(r + id.z) + w.w * __ldg(r + id.w);
            sh[(size_t)((c0 + cc) * 9 + t) * HW + n] = __float2half(v);
        }
    }
}

// ============================================================================
extern "C" void kernel_launch(void* const* d_in, const int* in_sizes, int n_in,
                              void* d_out, int out_size)
{
    const float* x_in  = (const float*)d_in[0];
    const float* x_ref = (const float*)d_in[1];
    const float* w1    = (const float*)d_in[2];
    const float* w2    = (const float*)d_in[3];
    const float* w3    = (const float*)d_in[4];
    const float* wo    = (const float*)d_in[5];
    const float* wd    = (const float*)d_in[6];
    float* out = (float*)d_out;

    float *h1, *h2, *off, *woT, *G, *Wc;
    __half *sh, *x1, *x2, *x3, *wdh;
    __half *w1h, *w1l, *w2h, *w2l, *wch, *wcl;
    cudaGetSymbolAddress((void**)&h1,  g_h1);
    cudaGetSymbolAddress((void**)&h2,  g_h2);
    cudaGetSymbolAddress((void**)&off, g_off);
    cudaGetSymbolAddress((void**)&woT, g_woT);
    cudaGetSymbolAddress((void**)&G,   g_G);
    cudaGetSymbolAddress((void**)&Wc,  g_Wc);
    cudaGetSymbolAddress((void**)&sh,  g_sh);
    cudaGetSymbolAddress((void**)&x1,  g_x1);
    cudaGetSymbolAddress((void**)&x2,  g_x2);
    cudaGetSymbolAddress((void**)&x3,  g_x3);
    cudaGetSymbolAddress((void**)&wdh, g_wdh);
    cudaGetSymbolAddress((void**)&w1h, g_w1h);
    cudaGetSymbolAddress((void**)&w1l, g_w1l);
    cudaGetSymbolAddress((void**)&w2h, g_w2h);
    cudaGetSymbolAddress((void**)&w2l, g_w2l);
    cudaGetSymbolAddress((void**)&wch, g_wch);
    cudaGetSymbolAddress((void**)&wcl, g_wcl);

    constexpr int SM64_BF  = 2 * (2 * (64 * A_STRIDE * 2) + 2 * (32 * B_STRIDE * 2)); // 55296
    constexpr int SM64_P2  = 2 * (2 * (64 * A_STRIDE * 2) + 1 * (32 * B_STRIDE * 2)); // 37888
    constexpr int SM32_P2  = 2 * (2 * (32 * A_STRIDE * 2) + 1 * (32 * B_STRIDE * 2)); // 27648
    constexpr int SM128_FP = 2 * (1 * (128 * A_STRIDE * 2) + 1 * (32 * B_STRIDE * 2)); // 37888
    constexpr int SM_SAMPLE = 9 * 256 * 32;                                           // 73728

    cudaFuncSetAttribute(
        (const void*)gemm_mma<3, 0, 3, 0, 2, 4, 64, 2, false>,
        cudaFuncAttributeMaxDynamicSharedMemorySize, SM64_BF);
    cudaFuncSetAttribute(
        (const void*)gemm_mma<2, 2, 3, 2, 2, 4, 64, 2, true>,
        cudaFuncAttributeMaxDynamicSharedMemorySize, SM64_P2);
    cudaFuncSetAttribute(
        (const void*)gemm_mma<2, 2, 5, 2, 1, 8, 32, 2, true>,
        cudaFuncAttributeMaxDynamicSharedMemorySize, SM32_P2);
    cudaFuncSetAttribute(
        (const void*)gemm_mma<1, 1, 3, 1, 4, 2, 128, 2, true>,
        cudaFuncAttributeMaxDynamicSharedMemorySize, SM128_FP);
    cudaFuncSetAttribute((const void*)sample_kernel,
        cudaFuncAttributeMaxDynamicSharedMemorySize, SM_SAMPLE);

    // zero split-K accumulators (d_out is poisoned -> must zero for atomics)
    cudaMemsetAsync(h1,  0, (size_t)192 * HW * 4);
    cudaMemsetAsync(h2,  0, (size_t)192 * HW * 4);
    cudaMemsetAsync(off, 0, (size_t)18  * HW * 4);
    cudaMemsetAsync(out, 0, (size_t)768 * HW * 4);

    // --- weight prep: composition (conv3∘conv4) + fp16 conversions/splits ---
    transpose_wo<<<(162 * 1536 + 255) / 256, 256>>>(wo, woT);
    gemm_mma<3, 0, 3, 0, 2, 4, 64, 2, false><<<dim3(14, 3), 256, SM64_BF>>>(
        woT, w3, nullptr, nullptr, nullptr, G, 162, 1536, 1536, 1728, 1728);
    build_wc<<<(18 * 4800 + 255) / 256, 256>>>(G, Wc);
    conv_f2h<<<(768 * 6912) / 512, 256>>>(wd, wdh, 768 * 6912);
    presplit_h<<<(192 * 13824) / 512, 256>>>(w1, w1h, w1l, 192 * 13824);
    presplit_h<<<(192 * 1728)  / 512, 256>>>(w2, w2h, w2l, 192 * 1728);
    presplit_h<<<(18 * 4800 + 511) / 512, 256>>>(Wc, wch, wcl, 18 * 4800);

    // --- stage 1: shifted concat images + conv1 (SPLIT-K x3) ---
    shift_img<3, false, true><<<dim3(9, 3 * 1536), 256>>>(x_in, x_ref, x1, 1536);
    gemm_mma<2, 2, 3, 2, 2, 4, 64, 2, true><<<dim3(32, 3, 3), 256, SM64_P2>>>(
        nullptr, nullptr, w1h, w1l, x1, h1, 192, 13824, 4608, HW, HW);

    // --- stage 2: shifted relu(h1) images + conv2 (SPLIT-K x3) ---
    shift_img<3, true, false><<<dim3(9, 3 * 192), 256>>>(h1, nullptr, x2, 192);
    gemm_mma<2, 2, 3, 2, 2, 4, 64, 2, true><<<dim3(32, 3, 3), 256, SM64_P2>>>(
        nullptr, nullptr, w2h, w2l, x2, h2, 192, 1728, 576, HW, HW);

    // --- stage 3: shifted relu(h2) 5x5 images + composed offsets (x10) ---
    shift_img<5, true, false><<<dim3(9, 5 * 192), 256>>>(h2, nullptr, x3, 192);
    gemm_mma<2, 2, 5, 2, 1, 8, 32, 2, true><<<dim3(32, 1, 10), 256, SM32_P2>>>(
        nullptr, nullptr, wch, wcl, x3, off, 18, 4800, 480, HW, HW);
    // exact border ring (relu applied inside)
    border_fix<<<dim3(64, 64), 192>>>(h2, G, off);

    // bilinear sampling -> fp16 S (per-tap precompute)
    sample_kernel<<<dim3(16, 48), 256, SM_SAMPLE>>>(x_ref, off, sh);

    // deform GEMM: out = wdh @ S  (fp16 1-pass, BM=128, SPLIT-K x3, atomics)
    gemm_mma<1, 1, 3, 1, 4, 2, 128, 2, true><<<dim3(32, 6, 3), 256, SM128_FP>>>(
        nullptr, nullptr, wdh, nullptr, sh, out, 768, 6912, 2304, HW, HW);
}